// round 1
// baseline (speedup 1.0000x reference)
#include <cuda_runtime.h>
#include <math.h>

#define NN 20000
#define EE 320000
#define HH 4
#define QW 1536   // 6*C
#define AW 512    // 2*C (concat width)

// ---------------- scratch (static device globals; no allocation) ----------------
__device__ float g_qkv1[NN * QW];          // 122.9 MB
__device__ float g_qkv2[NN * QW];          // 122.9 MB
__device__ float g_att1[NN * AW];          // feat11 | feat12
__device__ float g_att2[NN * AW];          // feat22 | feat21
__device__ float g_s[4][EE * HH];          // per-edge per-head scores -> exp
__device__ float g_m[4][NN * HH];          // segment max
__device__ float g_z[4][NN * HH];          // segment sum
__device__ float g_rpe[16];                // [p*4+h] p<3, bias at [12+h]

// ---------------- helpers ----------------
__device__ __forceinline__ void atomicMaxFloat(float* addr, float value) {
    // standard signed/unsigned split: correct total order for all finite floats
    if (value >= 0.f)
        atomicMax((int*)addr, __float_as_int(value));
    else
        atomicMin((unsigned int*)addr, __float_as_uint(value));
}

// ---------------- init ----------------
__global__ void init_buffers() {
    int idx = blockIdx.x * blockDim.x + threadIdx.x;
    int stride = gridDim.x * blockDim.x;
    for (int i = idx; i < NN * AW; i += stride) { g_att1[i] = 0.f; g_att2[i] = 0.f; }
    float* zp = &g_z[0][0];
    float* mp = &g_m[0][0];
    const float ninf = __int_as_float(0xff800000);
    for (int i = idx; i < 4 * NN * HH; i += stride) { zp[i] = 0.f; mp[i] = ninf; }
}

// RPE collapses: sum_d rpe[e,h,d] = delta . colsum64(Wrpe)[:,h] + colsum64(brpe)[h]
__global__ void rpe_precompute(const float* __restrict__ Wrpe, const float* __restrict__ brpe) {
    int h = threadIdx.x;
    if (h >= HH) return;
    for (int p = 0; p < 3; p++) {
        float s = 0.f;
        for (int d = 0; d < 64; d++) s += Wrpe[p * 256 + h * 64 + d];
        g_rpe[p * HH + h] = s;
    }
    float b = 0.f;
    for (int d = 0; d < 64; d++) b += brpe[h * 64 + d];
    g_rpe[12 + h] = b;
}

// ---------------- fp32 tiled GEMM with bias: C[M,Nc] = A[M,K] @ B[K,Nc] + bias ----------------
// 64x64 tile, BK=16, 256 threads, 4x4 microtile per thread. Nc%64==0, K%16==0 assumed.
__global__ void sgemm_bias(const float* __restrict__ A, const float* __restrict__ B,
                           const float* __restrict__ bias, float* __restrict__ C,
                           int M, int K, int Nc) {
    __shared__ float sA[16][64];
    __shared__ float sB[16][64];
    const int t  = threadIdx.x;
    const int tx = t & 15, ty = t >> 4;
    const int m0 = blockIdx.y * 64, n0 = blockIdx.x * 64;
    const int ai = t >> 2, aj = (t & 3) << 2;   // A tile load: row ai (0..63), k sub aj
    const int bj = t >> 4, bi = (t & 15) << 2;  // B tile load: k row bj, col bi

    float acc[4][4] = {};

    for (int k0 = 0; k0 < K; k0 += 16) {
        float4 av = make_float4(0.f, 0.f, 0.f, 0.f);
        if (m0 + ai < M)
            av = *(const float4*)(A + (size_t)(m0 + ai) * K + k0 + aj);
        sA[aj + 0][ai] = av.x; sA[aj + 1][ai] = av.y;
        sA[aj + 2][ai] = av.z; sA[aj + 3][ai] = av.w;
        *(float4*)(&sB[bj][bi]) = *(const float4*)(B + (size_t)(k0 + bj) * Nc + n0 + bi);
        __syncthreads();
#pragma unroll
        for (int kk = 0; kk < 16; kk++) {
            float4 ra = *(const float4*)(&sA[kk][ty << 2]);
            float4 rb = *(const float4*)(&sB[kk][tx << 2]);
            acc[0][0] += ra.x * rb.x; acc[0][1] += ra.x * rb.y; acc[0][2] += ra.x * rb.z; acc[0][3] += ra.x * rb.w;
            acc[1][0] += ra.y * rb.x; acc[1][1] += ra.y * rb.y; acc[1][2] += ra.y * rb.z; acc[1][3] += ra.y * rb.w;
            acc[2][0] += ra.z * rb.x; acc[2][1] += ra.z * rb.y; acc[2][2] += ra.z * rb.z; acc[2][3] += ra.z * rb.w;
            acc[3][0] += ra.w * rb.x; acc[3][1] += ra.w * rb.y; acc[3][2] += ra.w * rb.z; acc[3][3] += ra.w * rb.w;
        }
        __syncthreads();
    }

    float4 bs = *(const float4*)(bias + n0 + (tx << 2));
#pragma unroll
    for (int r = 0; r < 4; r++) {
        int row = m0 + (ty << 2) + r;
        if (row < M) {
            float4 o = make_float4(acc[r][0] + bs.x, acc[r][1] + bs.y,
                                   acc[r][2] + bs.z, acc[r][3] + bs.w);
            *(float4*)(C + (size_t)row * Nc + n0 + (tx << 2)) = o;
        }
    }
}

// ---------------- attention pass A: per-edge per-head score + segment max ----------------
// warp per edge; lanes cover D=64 as lane and lane+32
__global__ void score_kernel(const float* __restrict__ qkvQ, int qoff,
                             const float* __restrict__ qkvK, int koff,
                             const int* __restrict__ g,
                             const float* __restrict__ coordD,
                             const float* __restrict__ coordS,
                             int useRpe, int aid) {
    int w = (blockIdx.x * blockDim.x + threadIdx.x) >> 5;
    int lane = threadIdx.x & 31;
    if (w >= EE) return;
    int dst = g[w];
    int src = g[EE + w];
    const float* qrow = qkvQ + (size_t)dst * QW + qoff;
    const float* krow = qkvK + (size_t)src * QW + koff;

    float rsc[4] = {0.f, 0.f, 0.f, 0.f};
    if (useRpe) {
        float d0 = coordD[dst * 3 + 0] - coordS[src * 3 + 0];
        float d1 = coordD[dst * 3 + 1] - coordS[src * 3 + 1];
        float d2 = coordD[dst * 3 + 2] - coordS[src * 3 + 2];
#pragma unroll
        for (int h = 0; h < 4; h++)
            rsc[h] = d0 * g_rpe[h] + d1 * g_rpe[4 + h] + d2 * g_rpe[8 + h] + g_rpe[12 + h];
    }

#pragma unroll
    for (int h = 0; h < 4; h++) {
        float p = qrow[h * 64 + lane] * krow[h * 64 + lane]
                + qrow[h * 64 + 32 + lane] * krow[h * 64 + 32 + lane];
#pragma unroll
        for (int o = 16; o; o >>= 1) p += __shfl_xor_sync(0xffffffffu, p, o);
        if (lane == 0) {
            float sc = p + rsc[h];
            g_s[aid][(size_t)w * 4 + h] = sc;
            atomicMaxFloat(&g_m[aid][dst * 4 + h], sc);
        }
    }
}

// ---------------- attention pass B: e = exp(s - m[dst]); z[dst] += e ----------------
__global__ void expz_kernel(const int* __restrict__ g, int aid) {
    int idx = blockIdx.x * blockDim.x + threadIdx.x;
    if (idx >= EE * HH) return;
    int e = idx >> 2, h = idx & 3;
    int dst = g[e];
    float ex = expf(g_s[aid][idx] - g_m[aid][dst * 4 + h]);
    g_s[aid][idx] = ex;
    atomicAdd(&g_z[aid][dst * 4 + h], ex);
}

// ---------------- attention pass C: out[dst] += (e/z) * v[src] ----------------
__global__ void aggregate_kernel(const float* __restrict__ qkvV, int voff,
                                 const int* __restrict__ g, float* __restrict__ out,
                                 int outoff, int aid) {
    int w = (blockIdx.x * blockDim.x + threadIdx.x) >> 5;
    int lane = threadIdx.x & 31;
    if (w >= EE) return;
    int dst = g[w];
    int src = g[EE + w];
    const float* vrow = qkvV + (size_t)src * QW + voff;
    float* orow = out + (size_t)dst * AW + outoff;
#pragma unroll
    for (int h = 0; h < 4; h++) {
        float coef = g_s[aid][(size_t)w * 4 + h] / g_z[aid][dst * 4 + h];
        atomicAdd(&orow[h * 64 + lane],      coef * vrow[h * 64 + lane]);
        atomicAdd(&orow[h * 64 + 32 + lane], coef * vrow[h * 64 + 32 + lane]);
    }
}

// ---------------- launch ----------------
extern "C" void kernel_launch(void* const* d_in, const int* in_sizes, int n_in,
                              void* d_out, int out_size) {
    const float* feat1  = (const float*)d_in[0];
    const float* coord1 = (const float*)d_in[1];
    const float* feat2  = (const float*)d_in[2];
    const float* coord2 = (const float*)d_in[3];
    const float* Wqkv1  = (const float*)d_in[4];
    const float* bqkv1  = (const float*)d_in[5];
    const float* Wqkv2  = (const float*)d_in[6];
    const float* bqkv2  = (const float*)d_in[7];
    const float* Wproj1 = (const float*)d_in[8];
    const float* bproj1 = (const float*)d_in[9];
    const float* Wproj2 = (const float*)d_in[10];
    const float* bproj2 = (const float*)d_in[11];
    const float* Wrpe   = (const float*)d_in[12];
    const float* brpe   = (const float*)d_in[13];
    const int* graph1   = (const int*)d_in[14];
    const int* graph2   = (const int*)d_in[15];
    const int* graph12  = (const int*)d_in[16];
    const int* graph21  = (const int*)d_in[17];
    float* out = (float*)d_out;

    float *qkv1, *qkv2, *att1, *att2;
    cudaGetSymbolAddress((void**)&qkv1, g_qkv1);
    cudaGetSymbolAddress((void**)&qkv2, g_qkv2);
    cudaGetSymbolAddress((void**)&att1, g_att1);
    cudaGetSymbolAddress((void**)&att2, g_att2);

    init_buffers<<<1024, 256>>>();
    rpe_precompute<<<1, 32>>>(Wrpe, brpe);

    // QKV GEMMs: [20000,256] @ [256,1536]
    dim3 gq(QW / 64, (NN + 63) / 64);
    sgemm_bias<<<gq, 256>>>(feat1, Wqkv1, bqkv1, qkv1, NN, 256, QW);
    sgemm_bias<<<gq, 256>>>(feat2, Wqkv2, bqkv2, qkv2, NN, 256, QW);

    // qkv row layout per set: [q_a(0) k_a(256) v_a(512) q_b(768) k_b(1024) v_b(1280)]
    // att0: feat11 = attn(k11,q11,v11, graph1, rpe(coord1))
    // att1: feat22 = attn(k22,q22,v22, graph2, rpe(coord2))
    // att2: feat12 = attn(k21,q12,v21, graph21)
    // att3: feat21 = attn(k12,q21,v12, graph12)
    const int SCORE_BLOCKS = EE / 8;  // warp per edge, 8 warps/block
    score_kernel<<<SCORE_BLOCKS, 256>>>(qkv1,    0, qkv1,  256, graph1,  coord1, coord1, 1, 0);
    score_kernel<<<SCORE_BLOCKS, 256>>>(qkv2,  768, qkv2, 1024, graph2,  coord2, coord2, 1, 1);
    score_kernel<<<SCORE_BLOCKS, 256>>>(qkv1,  768, qkv2,  256, graph21, nullptr, nullptr, 0, 2);
    score_kernel<<<SCORE_BLOCKS, 256>>>(qkv2,    0, qkv1, 1024, graph12, nullptr, nullptr, 0, 3);

    const int EB = (EE * HH + 255) / 256;
    expz_kernel<<<EB, 256>>>(graph1, 0);
    expz_kernel<<<EB, 256>>>(graph2, 1);
    expz_kernel<<<EB, 256>>>(graph21, 2);
    expz_kernel<<<EB, 256>>>(graph12, 3);

    aggregate_kernel<<<SCORE_BLOCKS, 256>>>(qkv1,  512, graph1,  att1,   0, 0);
    aggregate_kernel<<<SCORE_BLOCKS, 256>>>(qkv2, 1280, graph2,  att2,   0, 1);
    aggregate_kernel<<<SCORE_BLOCKS, 256>>>(qkv2,  512, graph21, att1, 256, 2);
    aggregate_kernel<<<SCORE_BLOCKS, 256>>>(qkv1, 1280, graph12, att2, 256, 3);

    // Output projections: [20000,512] @ [512,256]
    dim3 gp(256 / 64, (NN + 63) / 64);
    sgemm_bias<<<gp, 256>>>(att1, Wproj1, bproj1, out,                    NN, 512, 256);
    sgemm_bias<<<gp, 256>>>(att2, Wproj2, bproj2, out + (size_t)NN * 256, NN, 512, 256);
}

// round 2
// speedup vs baseline: 1.1161x; 1.1161x over previous
#include <cuda_runtime.h>
#include <math.h>

#define NN 20000
#define EE 320000
#define HH 4
#define QW 1536   // 6*C
#define AW 512    // 2*C (concat width)

// ---------------- scratch (static device globals; no allocation) ----------------
__device__ float g_qkv1[NN * QW];          // 122.9 MB
__device__ float g_qkv2[NN * QW];          // 122.9 MB
__device__ float g_att1[NN * AW];          // feat11 | feat12
__device__ float g_att2[NN * AW];          // feat22 | feat21
__device__ float g_s[4][EE * HH];          // per-edge per-head scores -> exp
__device__ float g_m[4][NN * HH];          // segment max
__device__ float g_z[4][NN * HH];          // segment sum
__device__ float g_rpe[16];                // [p*4+h] p<3, bias at [12+h]

// ---------------- helpers ----------------
__device__ __forceinline__ void atomicMaxFloat(float* addr, float value) {
    if (value >= 0.f)
        atomicMax((int*)addr, __float_as_int(value));
    else
        atomicMin((unsigned int*)addr, __float_as_uint(value));
}

// ---------------- init ----------------
__global__ void init_buffers() {
    int idx = blockIdx.x * blockDim.x + threadIdx.x;
    int stride = gridDim.x * blockDim.x;
    for (int i = idx; i < NN * AW; i += stride) { g_att1[i] = 0.f; g_att2[i] = 0.f; }
    float* zp = &g_z[0][0];
    float* mp = &g_m[0][0];
    const float ninf = __int_as_float(0xff800000);
    for (int i = idx; i < 4 * NN * HH; i += stride) { zp[i] = 0.f; mp[i] = ninf; }
}

// RPE collapses: sum_d rpe[e,h,d] = delta . colsum64(Wrpe)[:,h] + colsum64(brpe)[h]
__global__ void rpe_precompute(const float* __restrict__ Wrpe, const float* __restrict__ brpe) {
    int h = threadIdx.x;
    if (h >= HH) return;
    for (int p = 0; p < 3; p++) {
        float s = 0.f;
        for (int d = 0; d < 64; d++) s += Wrpe[p * 256 + h * 64 + d];
        g_rpe[p * HH + h] = s;
    }
    float b = 0.f;
    for (int d = 0; d < 64; d++) b += brpe[h * 64 + d];
    g_rpe[12 + h] = b;
}

// ---------------- fp32 GEMM + bias: 128x128x8 tile, 8x8 microtile, double-buffered ----------------
// C[M,Nc] = A[M,K] @ B[K,Nc] + bias.  Requires Nc % 128 == 0, K % 8 == 0.
#define BM 128
#define BN 128
#define BK 8

__global__ __launch_bounds__(256, 2)
void sgemm_bias(const float* __restrict__ A, const float* __restrict__ B,
                const float* __restrict__ bias, float* __restrict__ C,
                int M, int K, int Nc) {
    __shared__ float sA[2][BK][BM];
    __shared__ float sB[2][BK][BN];

    const int t  = threadIdx.x;
    const int tx = t & 15, ty = t >> 4;
    const int m0 = blockIdx.y * BM, n0 = blockIdx.x * BN;

    // A tile loaders: 128x8 = 1024 floats, 1 float4/thread
    const int arow = t >> 1;            // 0..127
    const int acol = (t & 1) << 2;      // 0 or 4
    // B tile loaders: 8x128 = 1024 floats, 1 float4/thread
    const int brow = t >> 5;            // 0..7
    const int bcol = (t & 31) << 2;     // 0..124

    const float* Aptr = A + (size_t)(m0 + arow) * K + acol;
    const bool   aok  = (m0 + arow) < M;
    const float* Bptr = B + (size_t)brow * Nc + n0 + bcol;

    float acc[8][8] = {};

    // prologue
    {
        float4 av = make_float4(0.f, 0.f, 0.f, 0.f);
        if (aok) av = *(const float4*)(Aptr);
        sA[0][acol + 0][arow] = av.x; sA[0][acol + 1][arow] = av.y;
        sA[0][acol + 2][arow] = av.z; sA[0][acol + 3][arow] = av.w;
        *(float4*)(&sB[0][brow][bcol]) = *(const float4*)(Bptr);
    }
    __syncthreads();

    int buf = 0;
    for (int k0 = 0; k0 < K; k0 += BK) {
        if (k0 + BK < K) {
            float4 av = make_float4(0.f, 0.f, 0.f, 0.f);
            if (aok) av = *(const float4*)(Aptr + k0 + BK);
            sA[buf ^ 1][acol + 0][arow] = av.x; sA[buf ^ 1][acol + 1][arow] = av.y;
            sA[buf ^ 1][acol + 2][arow] = av.z; sA[buf ^ 1][acol + 3][arow] = av.w;
            *(float4*)(&sB[buf ^ 1][brow][bcol]) = *(const float4*)(Bptr + (size_t)(k0 + BK) * Nc);
        }
#pragma unroll
        for (int kk = 0; kk < BK; kk++) {
            float4 a0 = *(const float4*)(&sA[buf][kk][ty << 2]);
            float4 a1 = *(const float4*)(&sA[buf][kk][64 + (ty << 2)]);
            float4 b0 = *(const float4*)(&sB[buf][kk][tx << 2]);
            float4 b1 = *(const float4*)(&sB[buf][kk][64 + (tx << 2)]);
            float ra[8] = {a0.x, a0.y, a0.z, a0.w, a1.x, a1.y, a1.z, a1.w};
            float rb[8] = {b0.x, b0.y, b0.z, b0.w, b1.x, b1.y, b1.z, b1.w};
#pragma unroll
            for (int i = 0; i < 8; i++)
#pragma unroll
                for (int j = 0; j < 8; j++)
                    acc[i][j] += ra[i] * rb[j];
        }
        __syncthreads();
        buf ^= 1;
    }

    // epilogue: rows {m0+ty*4+i, m0+64+ty*4+i}, cols {n0+tx*4, n0+64+tx*4}
    float4 bs0 = *(const float4*)(bias + n0 + (tx << 2));
    float4 bs1 = *(const float4*)(bias + n0 + 64 + (tx << 2));
#pragma unroll
    for (int ri = 0; ri < 2; ri++) {
#pragma unroll
        for (int i = 0; i < 4; i++) {
            int row = m0 + ri * 64 + (ty << 2) + i;
            if (row < M) {
                int ai = ri * 4 + i;
                float4 o0 = make_float4(acc[ai][0] + bs0.x, acc[ai][1] + bs0.y,
                                        acc[ai][2] + bs0.z, acc[ai][3] + bs0.w);
                float4 o1 = make_float4(acc[ai][4] + bs1.x, acc[ai][5] + bs1.y,
                                        acc[ai][6] + bs1.z, acc[ai][7] + bs1.w);
                *(float4*)(C + (size_t)row * Nc + n0 + (tx << 2))      = o0;
                *(float4*)(C + (size_t)row * Nc + n0 + 64 + (tx << 2)) = o1;
            }
        }
    }
}

// ---------------- attention pass A: per-edge per-head score + segment max ----------------
__global__ void score_kernel(const float* __restrict__ qkvQ, int qoff,
                             const float* __restrict__ qkvK, int koff,
                             const int* __restrict__ g,
                             const float* __restrict__ coordD,
                             const float* __restrict__ coordS,
                             int useRpe, int aid) {
    int w = (blockIdx.x * blockDim.x + threadIdx.x) >> 5;
    int lane = threadIdx.x & 31;
    if (w >= EE) return;
    int dst = g[w];
    int src = g[EE + w];
    const float* qrow = qkvQ + (size_t)dst * QW + qoff;
    const float* krow = qkvK + (size_t)src * QW + koff;

    float rsc[4] = {0.f, 0.f, 0.f, 0.f};
    if (useRpe) {
        float d0 = coordD[dst * 3 + 0] - coordS[src * 3 + 0];
        float d1 = coordD[dst * 3 + 1] - coordS[src * 3 + 1];
        float d2 = coordD[dst * 3 + 2] - coordS[src * 3 + 2];
#pragma unroll
        for (int h = 0; h < 4; h++)
            rsc[h] = d0 * g_rpe[h] + d1 * g_rpe[4 + h] + d2 * g_rpe[8 + h] + g_rpe[12 + h];
    }

#pragma unroll
    for (int h = 0; h < 4; h++) {
        float p = qrow[h * 64 + lane] * krow[h * 64 + lane]
                + qrow[h * 64 + 32 + lane] * krow[h * 64 + 32 + lane];
#pragma unroll
        for (int o = 16; o; o >>= 1) p += __shfl_xor_sync(0xffffffffu, p, o);
        if (lane == 0) {
            float sc = p + rsc[h];
            g_s[aid][(size_t)w * 4 + h] = sc;
            atomicMaxFloat(&g_m[aid][dst * 4 + h], sc);
        }
    }
}

// ---------------- attention pass B: e = exp(s - m[dst]); z[dst] += e ----------------
__global__ void expz_kernel(const int* __restrict__ g, int aid) {
    int idx = blockIdx.x * blockDim.x + threadIdx.x;
    if (idx >= EE * HH) return;
    int e = idx >> 2, h = idx & 3;
    int dst = g[e];
    float ex = expf(g_s[aid][idx] - g_m[aid][dst * 4 + h]);
    g_s[aid][idx] = ex;
    atomicAdd(&g_z[aid][dst * 4 + h], ex);
}

// ---------------- attention pass C: out[dst] += (e/z) * v[src] ----------------
__global__ void aggregate_kernel(const float* __restrict__ qkvV, int voff,
                                 const int* __restrict__ g, float* __restrict__ out,
                                 int outoff, int aid) {
    int w = (blockIdx.x * blockDim.x + threadIdx.x) >> 5;
    int lane = threadIdx.x & 31;
    if (w >= EE) return;
    int dst = g[w];
    int src = g[EE + w];
    const float* vrow = qkvV + (size_t)src * QW + voff;
    float* orow = out + (size_t)dst * AW + outoff;
#pragma unroll
    for (int h = 0; h < 4; h++) {
        float coef = g_s[aid][(size_t)w * 4 + h] / g_z[aid][dst * 4 + h];
        atomicAdd(&orow[h * 64 + lane],      coef * vrow[h * 64 + lane]);
        atomicAdd(&orow[h * 64 + 32 + lane], coef * vrow[h * 64 + 32 + lane]);
    }
}

// ---------------- launch ----------------
extern "C" void kernel_launch(void* const* d_in, const int* in_sizes, int n_in,
                              void* d_out, int out_size) {
    const float* feat1  = (const float*)d_in[0];
    const float* coord1 = (const float*)d_in[1];
    const float* feat2  = (const float*)d_in[2];
    const float* coord2 = (const float*)d_in[3];
    const float* Wqkv1  = (const float*)d_in[4];
    const float* bqkv1  = (const float*)d_in[5];
    const float* Wqkv2  = (const float*)d_in[6];
    const float* bqkv2  = (const float*)d_in[7];
    const float* Wproj1 = (const float*)d_in[8];
    const float* bproj1 = (const float*)d_in[9];
    const float* Wproj2 = (const float*)d_in[10];
    const float* bproj2 = (const float*)d_in[11];
    const float* Wrpe   = (const float*)d_in[12];
    const float* brpe   = (const float*)d_in[13];
    const int* graph1   = (const int*)d_in[14];
    const int* graph2   = (const int*)d_in[15];
    const int* graph12  = (const int*)d_in[16];
    const int* graph21  = (const int*)d_in[17];
    float* out = (float*)d_out;

    float *qkv1, *qkv2, *att1, *att2;
    cudaGetSymbolAddress((void**)&qkv1, g_qkv1);
    cudaGetSymbolAddress((void**)&qkv2, g_qkv2);
    cudaGetSymbolAddress((void**)&att1, g_att1);
    cudaGetSymbolAddress((void**)&att2, g_att2);

    init_buffers<<<1024, 256>>>();
    rpe_precompute<<<1, 32>>>(Wrpe, brpe);

    // QKV GEMMs: [20000,256] @ [256,1536]
    dim3 gq(QW / BN, (NN + BM - 1) / BM);
    sgemm_bias<<<gq, 256>>>(feat1, Wqkv1, bqkv1, qkv1, NN, 256, QW);
    sgemm_bias<<<gq, 256>>>(feat2, Wqkv2, bqkv2, qkv2, NN, 256, QW);

    // qkv row layout per set: [q_a(0) k_a(256) v_a(512) q_b(768) k_b(1024) v_b(1280)]
    const int SCORE_BLOCKS = EE / 8;  // warp per edge, 8 warps/block
    score_kernel<<<SCORE_BLOCKS, 256>>>(qkv1,    0, qkv1,  256, graph1,  coord1, coord1, 1, 0);
    score_kernel<<<SCORE_BLOCKS, 256>>>(qkv2,  768, qkv2, 1024, graph2,  coord2, coord2, 1, 1);
    score_kernel<<<SCORE_BLOCKS, 256>>>(qkv1,  768, qkv2,  256, graph21, nullptr, nullptr, 0, 2);
    score_kernel<<<SCORE_BLOCKS, 256>>>(qkv2,    0, qkv1, 1024, graph12, nullptr, nullptr, 0, 3);

    const int EB = (EE * HH + 255) / 256;
    expz_kernel<<<EB, 256>>>(graph1, 0);
    expz_kernel<<<EB, 256>>>(graph2, 1);
    expz_kernel<<<EB, 256>>>(graph21, 2);
    expz_kernel<<<EB, 256>>>(graph12, 3);

    aggregate_kernel<<<SCORE_BLOCKS, 256>>>(qkv1,  512, graph1,  att1,   0, 0);
    aggregate_kernel<<<SCORE_BLOCKS, 256>>>(qkv2, 1280, graph2,  att2,   0, 1);
    aggregate_kernel<<<SCORE_BLOCKS, 256>>>(qkv2,  512, graph21, att1, 256, 2);
    aggregate_kernel<<<SCORE_BLOCKS, 256>>>(qkv1, 1280, graph12, att2, 256, 3);

    // Output projections: [20000,512] @ [512,256]
    dim3 gp(256 / BN, (NN + BM - 1) / BM);
    sgemm_bias<<<gp, 256>>>(att1, Wproj1, bproj1, out,                    NN, 512, 256);
    sgemm_bias<<<gp, 256>>>(att2, Wproj2, bproj2, out + (size_t)NN * 256, NN, 512, 256);
}

// round 3
// speedup vs baseline: 1.1162x; 1.0001x over previous
#include <cuda_runtime.h>
#include <math.h>

#define NN 20000
#define EE 320000
#define HH 4
#define QW 1536   // 6*C
#define AW 512    // 2*C (concat width)

// ---------------- scratch (static device globals; no allocation) ----------------
__device__ float g_qkv1[NN * QW];          // 122.9 MB
__device__ float g_qkv2[NN * QW];          // 122.9 MB
__device__ float g_att1[NN * AW];          // feat11 | feat12
__device__ float g_att2[NN * AW];          // feat22 | feat21
__device__ float g_s[4][EE * HH];          // per-edge per-head scores -> exp
__device__ float g_m[4][NN * HH];          // segment max
__device__ float g_z[4][NN * HH];          // segment sum
__device__ float g_rpe[16];                // [p*4+h] p<3, bias at [12+h]

// ---------------- helpers ----------------
__device__ __forceinline__ void atomicMaxFloat(float* addr, float value) {
    if (value >= 0.f)
        atomicMax((int*)addr, __float_as_int(value));
    else
        atomicMin((unsigned int*)addr, __float_as_uint(value));
}

// ---------------- init ----------------
__global__ void init_buffers() {
    int idx = blockIdx.x * blockDim.x + threadIdx.x;
    int stride = gridDim.x * blockDim.x;
    for (int i = idx; i < NN * AW; i += stride) { g_att1[i] = 0.f; g_att2[i] = 0.f; }
    float* zp = &g_z[0][0];
    float* mp = &g_m[0][0];
    const float ninf = __int_as_float(0xff800000);
    for (int i = idx; i < 4 * NN * HH; i += stride) { zp[i] = 0.f; mp[i] = ninf; }
}

// RPE collapses: sum_d rpe[e,h,d] = delta . colsum64(Wrpe)[:,h] + colsum64(brpe)[h]
__global__ void rpe_precompute(const float* __restrict__ Wrpe, const float* __restrict__ brpe) {
    int h = threadIdx.x;
    if (h >= HH) return;
    for (int p = 0; p < 3; p++) {
        float s = 0.f;
        for (int d = 0; d < 64; d++) s += Wrpe[p * 256 + h * 64 + d];
        g_rpe[p * HH + h] = s;
    }
    float b = 0.f;
    for (int d = 0; d < 64; d++) b += brpe[h * 64 + d];
    g_rpe[12 + h] = b;
}

// ---------------- fp32 GEMM + bias: 128x128x8 tile, 8x8 microtile, double-buffered ----------------
// C[M,Nc] = A[M,K] @ B[K,Nc] + bias.  Requires Nc % 128 == 0, K % 8 == 0.
#define BM 128
#define BN 128
#define BK 8

__global__ __launch_bounds__(256, 2)
void sgemm_bias(const float* __restrict__ A, const float* __restrict__ B,
                const float* __restrict__ bias, float* __restrict__ C,
                int M, int K, int Nc) {
    __shared__ float sA[2][BK][BM];
    __shared__ float sB[2][BK][BN];

    const int t  = threadIdx.x;
    const int tx = t & 15, ty = t >> 4;
    const int m0 = blockIdx.y * BM, n0 = blockIdx.x * BN;

    // A tile loaders: 128x8 = 1024 floats, 1 float4/thread
    const int arow = t >> 1;            // 0..127
    const int acol = (t & 1) << 2;      // 0 or 4
    // B tile loaders: 8x128 = 1024 floats, 1 float4/thread
    const int brow = t >> 5;            // 0..7
    const int bcol = (t & 31) << 2;     // 0..124

    const float* Aptr = A + (size_t)(m0 + arow) * K + acol;
    const bool   aok  = (m0 + arow) < M;
    const float* Bptr = B + (size_t)brow * Nc + n0 + bcol;

    float acc[8][8] = {};

    // prologue
    {
        float4 av = make_float4(0.f, 0.f, 0.f, 0.f);
        if (aok) av = *(const float4*)(Aptr);
        sA[0][acol + 0][arow] = av.x; sA[0][acol + 1][arow] = av.y;
        sA[0][acol + 2][arow] = av.z; sA[0][acol + 3][arow] = av.w;
        *(float4*)(&sB[0][brow][bcol]) = *(const float4*)(Bptr);
    }
    __syncthreads();

    int buf = 0;
    for (int k0 = 0; k0 < K; k0 += BK) {
        if (k0 + BK < K) {
            float4 av = make_float4(0.f, 0.f, 0.f, 0.f);
            if (aok) av = *(const float4*)(Aptr + k0 + BK);
            sA[buf ^ 1][acol + 0][arow] = av.x; sA[buf ^ 1][acol + 1][arow] = av.y;
            sA[buf ^ 1][acol + 2][arow] = av.z; sA[buf ^ 1][acol + 3][arow] = av.w;
            *(float4*)(&sB[buf ^ 1][brow][bcol]) = *(const float4*)(Bptr + (size_t)(k0 + BK) * Nc);
        }
#pragma unroll
        for (int kk = 0; kk < BK; kk++) {
            float4 a0 = *(const float4*)(&sA[buf][kk][ty << 2]);
            float4 a1 = *(const float4*)(&sA[buf][kk][64 + (ty << 2)]);
            float4 b0 = *(const float4*)(&sB[buf][kk][tx << 2]);
            float4 b1 = *(const float4*)(&sB[buf][kk][64 + (tx << 2)]);
            float ra[8] = {a0.x, a0.y, a0.z, a0.w, a1.x, a1.y, a1.z, a1.w};
            float rb[8] = {b0.x, b0.y, b0.z, b0.w, b1.x, b1.y, b1.z, b1.w};
#pragma unroll
            for (int i = 0; i < 8; i++)
#pragma unroll
                for (int j = 0; j < 8; j++)
                    acc[i][j] += ra[i] * rb[j];
        }
        __syncthreads();
        buf ^= 1;
    }

    // epilogue: rows {m0+ty*4+i, m0+64+ty*4+i}, cols {n0+tx*4, n0+64+tx*4}
    float4 bs0 = *(const float4*)(bias + n0 + (tx << 2));
    float4 bs1 = *(const float4*)(bias + n0 + 64 + (tx << 2));
#pragma unroll
    for (int ri = 0; ri < 2; ri++) {
#pragma unroll
        for (int i = 0; i < 4; i++) {
            int row = m0 + ri * 64 + (ty << 2) + i;
            if (row < M) {
                int ai = ri * 4 + i;
                float4 o0 = make_float4(acc[ai][0] + bs0.x, acc[ai][1] + bs0.y,
                                        acc[ai][2] + bs0.z, acc[ai][3] + bs0.w);
                float4 o1 = make_float4(acc[ai][4] + bs1.x, acc[ai][5] + bs1.y,
                                        acc[ai][6] + bs1.z, acc[ai][7] + bs1.w);
                *(float4*)(C + (size_t)row * Nc + n0 + (tx << 2))      = o0;
                *(float4*)(C + (size_t)row * Nc + n0 + 64 + (tx << 2)) = o1;
            }
        }
    }
}

// ---------------- attention pass A: per-edge per-head score + segment max ----------------
__global__ void score_kernel(const float* __restrict__ qkvQ, int qoff,
                             const float* __restrict__ qkvK, int koff,
                             const int* __restrict__ g,
                             const float* __restrict__ coordD,
                             const float* __restrict__ coordS,
                             int useRpe, int aid) {
    int w = (blockIdx.x * blockDim.x + threadIdx.x) >> 5;
    int lane = threadIdx.x & 31;
    if (w >= EE) return;
    int dst = g[w];
    int src = g[EE + w];
    const float* qrow = qkvQ + (size_t)dst * QW + qoff;
    const float* krow = qkvK + (size_t)src * QW + koff;

    float rsc[4] = {0.f, 0.f, 0.f, 0.f};
    if (useRpe) {
        float d0 = coordD[dst * 3 + 0] - coordS[src * 3 + 0];
        float d1 = coordD[dst * 3 + 1] - coordS[src * 3 + 1];
        float d2 = coordD[dst * 3 + 2] - coordS[src * 3 + 2];
#pragma unroll
        for (int h = 0; h < 4; h++)
            rsc[h] = d0 * g_rpe[h] + d1 * g_rpe[4 + h] + d2 * g_rpe[8 + h] + g_rpe[12 + h];
    }

#pragma unroll
    for (int h = 0; h < 4; h++) {
        float p = qrow[h * 64 + lane] * krow[h * 64 + lane]
                + qrow[h * 64 + 32 + lane] * krow[h * 64 + 32 + lane];
#pragma unroll
        for (int o = 16; o; o >>= 1) p += __shfl_xor_sync(0xffffffffu, p, o);
        if (lane == 0) {
            float sc = p + rsc[h];
            g_s[aid][(size_t)w * 4 + h] = sc;
            atomicMaxFloat(&g_m[aid][dst * 4 + h], sc);
        }
    }
}

// ---------------- attention pass B: e = exp(s - m[dst]); z[dst] += e ----------------
__global__ void expz_kernel(const int* __restrict__ g, int aid) {
    int idx = blockIdx.x * blockDim.x + threadIdx.x;
    if (idx >= EE * HH) return;
    int e = idx >> 2, h = idx & 3;
    int dst = g[e];
    float ex = expf(g_s[aid][idx] - g_m[aid][dst * 4 + h]);
    g_s[aid][idx] = ex;
    atomicAdd(&g_z[aid][dst * 4 + h], ex);
}

// ---------------- attention pass C: out[dst] += (e/z) * v[src] ----------------
__global__ void aggregate_kernel(const float* __restrict__ qkvV, int voff,
                                 const int* __restrict__ g, float* __restrict__ out,
                                 int outoff, int aid) {
    int w = (blockIdx.x * blockDim.x + threadIdx.x) >> 5;
    int lane = threadIdx.x & 31;
    if (w >= EE) return;
    int dst = g[w];
    int src = g[EE + w];
    const float* vrow = qkvV + (size_t)src * QW + voff;
    float* orow = out + (size_t)dst * AW + outoff;
#pragma unroll
    for (int h = 0; h < 4; h++) {
        float coef = g_s[aid][(size_t)w * 4 + h] / g_z[aid][dst * 4 + h];
        atomicAdd(&orow[h * 64 + lane],      coef * vrow[h * 64 + lane]);
        atomicAdd(&orow[h * 64 + 32 + lane], coef * vrow[h * 64 + 32 + lane]);
    }
}

// ---------------- launch ----------------
extern "C" void kernel_launch(void* const* d_in, const int* in_sizes, int n_in,
                              void* d_out, int out_size) {
    const float* feat1  = (const float*)d_in[0];
    const float* coord1 = (const float*)d_in[1];
    const float* feat2  = (const float*)d_in[2];
    const float* coord2 = (const float*)d_in[3];
    const float* Wqkv1  = (const float*)d_in[4];
    const float* bqkv1  = (const float*)d_in[5];
    const float* Wqkv2  = (const float*)d_in[6];
    const float* bqkv2  = (const float*)d_in[7];
    const float* Wproj1 = (const float*)d_in[8];
    const float* bproj1 = (const float*)d_in[9];
    const float* Wproj2 = (const float*)d_in[10];
    const float* bproj2 = (const float*)d_in[11];
    const float* Wrpe   = (const float*)d_in[12];
    const float* brpe   = (const float*)d_in[13];
    const int* graph1   = (const int*)d_in[14];
    const int* graph2   = (const int*)d_in[15];
    const int* graph12  = (const int*)d_in[16];
    const int* graph21  = (const int*)d_in[17];
    float* out = (float*)d_out;

    float *qkv1, *qkv2, *att1, *att2;
    cudaGetSymbolAddress((void**)&qkv1, g_qkv1);
    cudaGetSymbolAddress((void**)&qkv2, g_qkv2);
    cudaGetSymbolAddress((void**)&att1, g_att1);
    cudaGetSymbolAddress((void**)&att2, g_att2);

    init_buffers<<<1024, 256>>>();
    rpe_precompute<<<1, 32>>>(Wrpe, brpe);

    // QKV GEMMs: [20000,256] @ [256,1536]
    dim3 gq(QW / BN, (NN + BM - 1) / BM);
    sgemm_bias<<<gq, 256>>>(feat1, Wqkv1, bqkv1, qkv1, NN, 256, QW);
    sgemm_bias<<<gq, 256>>>(feat2, Wqkv2, bqkv2, qkv2, NN, 256, QW);

    // qkv row layout per set: [q_a(0) k_a(256) v_a(512) q_b(768) k_b(1024) v_b(1280)]
    const int SCORE_BLOCKS = EE / 8;  // warp per edge, 8 warps/block
    score_kernel<<<SCORE_BLOCKS, 256>>>(qkv1,    0, qkv1,  256, graph1,  coord1, coord1, 1, 0);
    score_kernel<<<SCORE_BLOCKS, 256>>>(qkv2,  768, qkv2, 1024, graph2,  coord2, coord2, 1, 1);
    score_kernel<<<SCORE_BLOCKS, 256>>>(qkv1,  768, qkv2,  256, graph21, nullptr, nullptr, 0, 2);
    score_kernel<<<SCORE_BLOCKS, 256>>>(qkv2,    0, qkv1, 1024, graph12, nullptr, nullptr, 0, 3);

    const int EB = (EE * HH + 255) / 256;
    expz_kernel<<<EB, 256>>>(graph1, 0);
    expz_kernel<<<EB, 256>>>(graph2, 1);
    expz_kernel<<<EB, 256>>>(graph21, 2);
    expz_kernel<<<EB, 256>>>(graph12, 3);

    aggregate_kernel<<<SCORE_BLOCKS, 256>>>(qkv1,  512, graph1,  att1,   0, 0);
    aggregate_kernel<<<SCORE_BLOCKS, 256>>>(qkv2, 1280, graph2,  att2,   0, 1);
    aggregate_kernel<<<SCORE_BLOCKS, 256>>>(qkv2,  512, graph21, att1, 256, 2);
    aggregate_kernel<<<SCORE_BLOCKS, 256>>>(qkv1, 1280, graph12, att2, 256, 3);

    // Output projections: [20000,512] @ [512,256]
    dim3 gp(256 / BN, (NN + BM - 1) / BM);
    sgemm_bias<<<gp, 256>>>(att1, Wproj1, bproj1, out,                    NN, 512, 256);
    sgemm_bias<<<gp, 256>>>(att2, Wproj2, bproj2, out + (size_t)NN * 256, NN, 512, 256);
}

// round 6
// speedup vs baseline: 1.4177x; 1.2701x over previous
#include <cuda_runtime.h>
#include <cuda_bf16.h>
#include <math.h>
#include <stdint.h>

#define NN 20000
#define EE 320000
#define HH 4
#define QW 1536   // 6*C
#define AW 512    // 2*C
#define NP 20096  // 157 * 128 (padded M)

// ---------------- scratch (static device globals) ----------------
__device__ float g_qkv1[NN * QW];
__device__ float g_qkv2[NN * QW];
__device__ float g_att1[NN * AW];
__device__ float g_att2[NN * AW];
__device__ float g_s[4][EE * HH];
__device__ float g_m[4][NN * HH];
__device__ float g_z[4][NN * HH];
__device__ float g_rpe[16];

// interleaved 3-term-split bf16 operands:
//   A' rows: [hi(K) | hi(K) | lo(K)]   B' rows: [hi(K) | lo(K) | hi(K)]
__device__ __align__(16) __nv_bfloat16 g_f1p[NP * 768];     // feat1'  (K=256 -> 768)
__device__ __align__(16) __nv_bfloat16 g_f2p[NP * 768];
__device__ __align__(16) __nv_bfloat16 g_t1p[NP * 1536];    // att1'   (K=512 -> 1536)
__device__ __align__(16) __nv_bfloat16 g_t2p[NP * 1536];
__device__ __align__(16) __nv_bfloat16 g_w1p[1536 * 768];   // Wqkv1'^T
__device__ __align__(16) __nv_bfloat16 g_w2p[1536 * 768];
__device__ __align__(16) __nv_bfloat16 g_p1p[256 * 1536];   // Wproj1'^T
__device__ __align__(16) __nv_bfloat16 g_p2p[256 * 1536];

// ---------------- helpers ----------------
__device__ __forceinline__ uint32_t smem_u32(const void* p) {
    uint32_t a;
    asm("{ .reg .u64 t; cvta.to.shared.u64 t, %1; cvt.u32.u64 %0, t; }" : "=r"(a) : "l"(p));
    return a;
}
__device__ __forceinline__ void cp_async16(uint32_t dst, const void* src) {
    asm volatile("cp.async.cg.shared.global [%0], [%1], 16;" :: "r"(dst), "l"(src));
}
__device__ __forceinline__ void cp_commit() {
    asm volatile("cp.async.commit_group;" ::: "memory");
}
__device__ __forceinline__ void cp_wait0() {
    asm volatile("cp.async.wait_group 0;" ::: "memory");
}
__device__ __forceinline__ void ldmatrix4(uint32_t* r, uint32_t addr) {
    asm volatile("ldmatrix.sync.aligned.m8n8.x4.shared.b16 {%0,%1,%2,%3}, [%4];"
                 : "=r"(r[0]), "=r"(r[1]), "=r"(r[2]), "=r"(r[3]) : "r"(addr));
}
__device__ __forceinline__ void mma16816(float* c, const uint32_t* a, const uint32_t* b) {
    asm volatile("mma.sync.aligned.m16n8k16.row.col.f32.bf16.bf16.f32 "
                 "{%0,%1,%2,%3}, {%4,%5,%6,%7}, {%8,%9}, {%0,%1,%2,%3};"
                 : "+f"(c[0]), "+f"(c[1]), "+f"(c[2]), "+f"(c[3])
                 : "r"(a[0]), "r"(a[1]), "r"(a[2]), "r"(a[3]), "r"(b[0]), "r"(b[1]));
}
__device__ __forceinline__ void atomicMaxFloat(float* addr, float value) {
    if (value >= 0.f) atomicMax((int*)addr, __float_as_int(value));
    else              atomicMin((unsigned int*)addr, __float_as_uint(value));
}

// ---------------- init ----------------
__global__ void init_buffers() {
    int idx = blockIdx.x * blockDim.x + threadIdx.x;
    int stride = gridDim.x * blockDim.x;
    for (int i = idx; i < NN * AW; i += stride) { g_att1[i] = 0.f; g_att2[i] = 0.f; }
    float* zp = &g_z[0][0];
    float* mp = &g_m[0][0];
    const float ninf = __int_as_float(0xff800000);
    for (int i = idx; i < 4 * NN * HH; i += stride) { zp[i] = 0.f; mp[i] = ninf; }
}

__global__ void rpe_precompute(const float* __restrict__ Wrpe, const float* __restrict__ brpe) {
    int h = threadIdx.x;
    if (h >= HH) return;
    for (int p = 0; p < 3; p++) {
        float s = 0.f;
        for (int d = 0; d < 64; d++) s += Wrpe[p * 256 + h * 64 + d];
        g_rpe[p * HH + h] = s;
    }
    float b = 0.f;
    for (int d = 0; d < 64; d++) b += brpe[h * 64 + d];
    g_rpe[12 + h] = b;
}

// ---------------- split/interleave prep ----------------
// src [nrows_valid, K] f32 row-major -> dst [nrows_total, 3K]: [hi | hi | lo]
__global__ void split_pad3(const float* __restrict__ src, __nv_bfloat16* __restrict__ dst,
                           int nrows_valid, int nrows_total, int K) {
    int idx = blockIdx.x * blockDim.x + threadIdx.x;
    int stride = gridDim.x * blockDim.x;
    int total = nrows_total * K;
    for (int i = idx; i < total; i += stride) {
        int r = i / K, k = i - r * K;
        float x = (r < nrows_valid) ? src[i] : 0.f;
        __nv_bfloat16 h = __float2bfloat16(x);
        __nv_bfloat16 l = __float2bfloat16(x - __bfloat162float(h));
        size_t base = (size_t)r * (3 * K) + k;
        dst[base]         = h;
        dst[base + K]     = h;
        dst[base + 2 * K] = l;
    }
}
// W [K, Nc] f32 row-major -> dst [Nc, 3K]: [hi | lo | hi]
__global__ void transpose_split3(const float* __restrict__ W, __nv_bfloat16* __restrict__ dst,
                                 int K, int Nc) {
    int i = blockIdx.x * blockDim.x + threadIdx.x;
    if (i >= K * Nc) return;
    int k = i / Nc, n = i - k * Nc;
    float x = W[i];
    __nv_bfloat16 h = __float2bfloat16(x);
    __nv_bfloat16 l = __float2bfloat16(x - __bfloat162float(h));
    size_t base = (size_t)n * (3 * K) + k;
    dst[base]         = h;
    dst[base + K]     = l;
    dst[base + 2 * K] = h;
}

// ---------------- bf16 mma.sync GEMM ----------------
// C[M,Nc] = A'[Mpad,Kp] @ B'[Nc,Kp]^T + bias.  Kp % 64 == 0, Nc % 128 == 0,
// Mpad >= ceil(M/128)*128.  128x128 block, BK=64, 8 warps (2x4), 64x32/warp.
#define GSMEM 65536

__global__ __launch_bounds__(256)
void gemm_bf16_mma(const __nv_bfloat16* __restrict__ A, const __nv_bfloat16* __restrict__ B,
                   const float* __restrict__ bias, float* __restrict__ C,
                   int M, int Kp, int Nc) {
    extern __shared__ char smem[];
    const uint32_t sA_u = smem_u32(smem);            // [2][16384]
    const uint32_t sB_u = sA_u + 32768;              // [2][16384]

    const int t = threadIdx.x;
    const int wid = t >> 5, lane = t & 31;
    const int wm = wid & 1, wn = wid >> 1;           // 2 x 4 warp grid
    const int m0 = blockIdx.y * 128, n0 = blockIdx.x * 128;

    float acc[4][4][4];
#pragma unroll
    for (int i = 0; i < 4; i++)
#pragma unroll
        for (int j = 0; j < 4; j++)
#pragma unroll
            for (int v = 0; v < 4; v++) acc[i][j][v] = 0.f;

    // tile loader: 128 rows x 64 bf16 (= 8 x 16B per row), 1024 chunks / 256 thr
    auto load_tiles = [&](int buf, int k0) {
#pragma unroll
        for (int i = 0; i < 4; i++) {
            int lin = i * 256 + t;
            int row = lin >> 3, ku = lin & 7;
            uint32_t b = (uint32_t)(row * 128 + ku * 16);
            b ^= (b >> 3) & 0x70;
            cp_async16(sA_u + buf * 16384 + b, A + (size_t)(m0 + row) * Kp + k0 + ku * 8);
            cp_async16(sB_u + buf * 16384 + b, B + (size_t)(n0 + row) * Kp + k0 + ku * 8);
        }
    };

    const int nk = Kp >> 6;
    load_tiles(0, 0);
    cp_commit();

    for (int kt = 0; kt < nk; kt++) {
        cp_wait0();
        __syncthreads();
        if (kt + 1 < nk) { load_tiles((kt + 1) & 1, (kt + 1) << 6); cp_commit(); }

        const uint32_t bufA = sA_u + (kt & 1) * 16384;
        const uint32_t bufB = sB_u + (kt & 1) * 16384;
#pragma unroll
        for (int kk = 0; kk < 4; kk++) {
            uint32_t afrag[4][4], bfrag[4][2];
            const int kseg = kk * 2 + (lane >> 4);
#pragma unroll
            for (int mt = 0; mt < 4; mt++) {
                int row = wm * 64 + mt * 16 + (lane & 15);
                uint32_t b = (uint32_t)(row * 128 + kseg * 16);
                b ^= (b >> 3) & 0x70;
                ldmatrix4(afrag[mt], bufA + b);
            }
#pragma unroll
            for (int nt2 = 0; nt2 < 2; nt2++) {
                int row = wn * 32 + nt2 * 16 + (lane & 7) + ((lane >> 3) & 1) * 8;
                uint32_t b = (uint32_t)(row * 128 + kseg * 16);
                b ^= (b >> 3) & 0x70;
                uint32_t r[4];
                ldmatrix4(r, bufB + b);
                bfrag[nt2 * 2][0]     = r[0]; bfrag[nt2 * 2][1]     = r[2];
                bfrag[nt2 * 2 + 1][0] = r[1]; bfrag[nt2 * 2 + 1][1] = r[3];
            }
#pragma unroll
            for (int mt = 0; mt < 4; mt++)
#pragma unroll
                for (int nt = 0; nt < 4; nt++)
                    mma16816(acc[mt][nt], afrag[mt], bfrag[nt]);
        }
        __syncthreads();
    }

    // epilogue: d-frag c0,c1 -> row lane/4, cols (lane%4)*2+{0,1}; c2,c3 -> row+8
#pragma unroll
    for (int mt = 0; mt < 4; mt++) {
        int rbase = m0 + wm * 64 + mt * 16 + (lane >> 2);
#pragma unroll
        for (int nt = 0; nt < 4; nt++) {
            int c = n0 + wn * 32 + nt * 8 + (lane & 3) * 2;
            float bx = bias[c], by = bias[c + 1];
            if (rbase < M) {
                float2 o = make_float2(acc[mt][nt][0] + bx, acc[mt][nt][1] + by);
                *(float2*)(C + (size_t)rbase * Nc + c) = o;
            }
            if (rbase + 8 < M) {
                float2 o = make_float2(acc[mt][nt][2] + bx, acc[mt][nt][3] + by);
                *(float2*)(C + (size_t)(rbase + 8) * Nc + c) = o;
            }
        }
    }
}

// ---------------- attention pass A ----------------
__global__ void score_kernel(const float* __restrict__ qkvQ, int qoff,
                             const float* __restrict__ qkvK, int koff,
                             const int* __restrict__ g,
                             const float* __restrict__ coordD,
                             const float* __restrict__ coordS,
                             int useRpe, int aid) {
    int w = (blockIdx.x * blockDim.x + threadIdx.x) >> 5;
    int lane = threadIdx.x & 31;
    if (w >= EE) return;
    int dst = g[w];
    int src = g[EE + w];
    const float* qrow = qkvQ + (size_t)dst * QW + qoff;
    const float* krow = qkvK + (size_t)src * QW + koff;

    float rsc[4] = {0.f, 0.f, 0.f, 0.f};
    if (useRpe) {
        float d0 = coordD[dst * 3 + 0] - coordS[src * 3 + 0];
        float d1 = coordD[dst * 3 + 1] - coordS[src * 3 + 1];
        float d2 = coordD[dst * 3 + 2] - coordS[src * 3 + 2];
#pragma unroll
        for (int h = 0; h < 4; h++)
            rsc[h] = d0 * g_rpe[h] + d1 * g_rpe[4 + h] + d2 * g_rpe[8 + h] + g_rpe[12 + h];
    }
#pragma unroll
    for (int h = 0; h < 4; h++) {
        float p = qrow[h * 64 + lane] * krow[h * 64 + lane]
                + qrow[h * 64 + 32 + lane] * krow[h * 64 + 32 + lane];
#pragma unroll
        for (int o = 16; o; o >>= 1) p += __shfl_xor_sync(0xffffffffu, p, o);
        if (lane == 0) {
            float sc = p + rsc[h];
            g_s[aid][(size_t)w * 4 + h] = sc;
            atomicMaxFloat(&g_m[aid][dst * 4 + h], sc);
        }
    }
}

// ---------------- attention pass B ----------------
__global__ void expz_kernel(const int* __restrict__ g, int aid) {
    int idx = blockIdx.x * blockDim.x + threadIdx.x;
    if (idx >= EE * HH) return;
    int e = idx >> 2, h = idx & 3;
    int dst = g[e];
    float ex = expf(g_s[aid][idx] - g_m[aid][dst * 4 + h]);
    g_s[aid][idx] = ex;
    atomicAdd(&g_z[aid][dst * 4 + h], ex);
}

// ---------------- attention pass C ----------------
__global__ void aggregate_kernel(const float* __restrict__ qkvV, int voff,
                                 const int* __restrict__ g, float* __restrict__ out,
                                 int outoff, int aid) {
    int w = (blockIdx.x * blockDim.x + threadIdx.x) >> 5;
    int lane = threadIdx.x & 31;
    if (w >= EE) return;
    int dst = g[w];
    int src = g[EE + w];
    const float* vrow = qkvV + (size_t)src * QW + voff;
    float* orow = out + (size_t)dst * AW + outoff;
#pragma unroll
    for (int h = 0; h < 4; h++) {
        float coef = g_s[aid][(size_t)w * 4 + h] / g_z[aid][dst * 4 + h];
        atomicAdd(&orow[h * 64 + lane],      coef * vrow[h * 64 + lane]);
        atomicAdd(&orow[h * 64 + 32 + lane], coef * vrow[h * 64 + 32 + lane]);
    }
}

// ---------------- launch ----------------
extern "C" void kernel_launch(void* const* d_in, const int* in_sizes, int n_in,
                              void* d_out, int out_size) {
    const float* feat1  = (const float*)d_in[0];
    const float* coord1 = (const float*)d_in[1];
    const float* feat2  = (const float*)d_in[2];
    const float* coord2 = (const float*)d_in[3];
    const float* Wqkv1  = (const float*)d_in[4];
    const float* bqkv1  = (const float*)d_in[5];
    const float* Wqkv2  = (const float*)d_in[6];
    const float* bqkv2  = (const float*)d_in[7];
    const float* Wproj1 = (const float*)d_in[8];
    const float* bproj1 = (const float*)d_in[9];
    const float* Wproj2 = (const float*)d_in[10];
    const float* bproj2 = (const float*)d_in[11];
    const float* Wrpe   = (const float*)d_in[12];
    const float* brpe   = (const float*)d_in[13];
    const int* graph1   = (const int*)d_in[14];
    const int* graph2   = (const int*)d_in[15];
    const int* graph12  = (const int*)d_in[16];
    const int* graph21  = (const int*)d_in[17];
    float* out = (float*)d_out;

    float *qkv1, *qkv2, *att1, *att2;
    cudaGetSymbolAddress((void**)&qkv1, g_qkv1);
    cudaGetSymbolAddress((void**)&qkv2, g_qkv2);
    cudaGetSymbolAddress((void**)&att1, g_att1);
    cudaGetSymbolAddress((void**)&att2, g_att2);
    __nv_bfloat16 *f1p, *f2p, *t1p, *t2p, *w1p, *w2p, *p1p, *p2p;
    cudaGetSymbolAddress((void**)&f1p, g_f1p);
    cudaGetSymbolAddress((void**)&f2p, g_f2p);
    cudaGetSymbolAddress((void**)&t1p, g_t1p);
    cudaGetSymbolAddress((void**)&t2p, g_t2p);
    cudaGetSymbolAddress((void**)&w1p, g_w1p);
    cudaGetSymbolAddress((void**)&w2p, g_w2p);
    cudaGetSymbolAddress((void**)&p1p, g_p1p);
    cudaGetSymbolAddress((void**)&p2p, g_p2p);

    cudaFuncSetAttribute(gemm_bf16_mma, cudaFuncAttributeMaxDynamicSharedMemorySize, GSMEM);

    init_buffers<<<1024, 256>>>();
    rpe_precompute<<<1, 32>>>(Wrpe, brpe);

    // operand prep (3-term split interleave)
    split_pad3<<<2048, 256>>>(feat1, f1p, NN, NP, 256);
    split_pad3<<<2048, 256>>>(feat2, f2p, NN, NP, 256);
    transpose_split3<<<(256 * 1536 + 255) / 256, 256>>>(Wqkv1, w1p, 256, 1536);
    transpose_split3<<<(256 * 1536 + 255) / 256, 256>>>(Wqkv2, w2p, 256, 1536);
    transpose_split3<<<(512 * 256 + 255) / 256, 256>>>(Wproj1, p1p, 512, 256);
    transpose_split3<<<(512 * 256 + 255) / 256, 256>>>(Wproj2, p2p, 512, 256);

    // QKV GEMMs: [20000,256] @ [256,1536]  (Kp = 768)
    dim3 gq(QW / 128, NP / 128);
    gemm_bf16_mma<<<gq, 256, GSMEM>>>(f1p, w1p, bqkv1, qkv1, NN, 768, QW);
    gemm_bf16_mma<<<gq, 256, GSMEM>>>(f2p, w2p, bqkv2, qkv2, NN, 768, QW);

    // attention: qkv row layout [q_a(0) k_a(256) v_a(512) q_b(768) k_b(1024) v_b(1280)]
    const int SCORE_BLOCKS = EE / 8;
    score_kernel<<<SCORE_BLOCKS, 256>>>(qkv1,    0, qkv1,  256, graph1,  coord1, coord1, 1, 0);
    score_kernel<<<SCORE_BLOCKS, 256>>>(qkv2,  768, qkv2, 1024, graph2,  coord2, coord2, 1, 1);
    score_kernel<<<SCORE_BLOCKS, 256>>>(qkv1,  768, qkv2,  256, graph21, nullptr, nullptr, 0, 2);
    score_kernel<<<SCORE_BLOCKS, 256>>>(qkv2,    0, qkv1, 1024, graph12, nullptr, nullptr, 0, 3);

    const int EB = (EE * HH + 255) / 256;
    expz_kernel<<<EB, 256>>>(graph1, 0);
    expz_kernel<<<EB, 256>>>(graph2, 1);
    expz_kernel<<<EB, 256>>>(graph21, 2);
    expz_kernel<<<EB, 256>>>(graph12, 3);

    aggregate_kernel<<<SCORE_BLOCKS, 256>>>(qkv1,  512, graph1,  att1,   0, 0);
    aggregate_kernel<<<SCORE_BLOCKS, 256>>>(qkv2, 1280, graph2,  att2,   0, 1);
    aggregate_kernel<<<SCORE_BLOCKS, 256>>>(qkv2,  512, graph21, att1, 256, 2);
    aggregate_kernel<<<SCORE_BLOCKS, 256>>>(qkv1, 1280, graph12, att2, 256, 3);

    // split attention outputs for proj GEMMs (Kp = 1536)
    split_pad3<<<2048, 256>>>(att1, t1p, NN, NP, 512);
    split_pad3<<<2048, 256>>>(att2, t2p, NN, NP, 512);

    // Output projections: [20000,512] @ [512,256]
    dim3 gp(256 / 128, NP / 128);
    gemm_bf16_mma<<<gp, 256, GSMEM>>>(t1p, p1p, bproj1, out,                    NN, 1536, 256);
    gemm_bf16_mma<<<gp, 256, GSMEM>>>(t2p, p2p, bproj2, out + (size_t)NN * 256, NN, 1536, 256);
}

// round 7
// speedup vs baseline: 2.0112x; 1.4186x over previous
#include <cuda_runtime.h>
#include <cuda_bf16.h>
#include <math.h>
#include <stdint.h>

#define NN 20000
#define EE 320000
#define HH 4
#define QW 1536   // 6*C
#define AW 512    // 2*C
#define NP 20096  // 157 * 128 (padded M)

// ---------------- scratch (static device globals) ----------------
__device__ __align__(16) float g_qkv1[NN * QW];
__device__ __align__(16) float g_qkv2[NN * QW];
__device__ __align__(16) float g_att1[NN * AW];
__device__ __align__(16) float g_att2[NN * AW];
__device__ float g_rpe[16];

// CSR per graph
__device__ int g_deg[4][NN];
__device__ int g_off[4][NN + 1];
__device__ int g_pos[4][NN];
__device__ int g_srcs[4][EE];    // src node ids, grouped by dst

// interleaved 3-term-split bf16 operands:
//   A' rows: [hi(K) | hi(K) | lo(K)]   B' rows: [hi(K) | lo(K) | hi(K)]
__device__ __align__(16) __nv_bfloat16 g_f1p[NP * 768];
__device__ __align__(16) __nv_bfloat16 g_f2p[NP * 768];
__device__ __align__(16) __nv_bfloat16 g_t1p[NP * 1536];
__device__ __align__(16) __nv_bfloat16 g_t2p[NP * 1536];
__device__ __align__(16) __nv_bfloat16 g_w1p[1536 * 768];
__device__ __align__(16) __nv_bfloat16 g_w2p[1536 * 768];
__device__ __align__(16) __nv_bfloat16 g_p1p[256 * 1536];
__device__ __align__(16) __nv_bfloat16 g_p2p[256 * 1536];

// ---------------- helpers ----------------
__device__ __forceinline__ uint32_t smem_u32(const void* p) {
    uint32_t a;
    asm("{ .reg .u64 t; cvta.to.shared.u64 t, %1; cvt.u32.u64 %0, t; }" : "=r"(a) : "l"(p));
    return a;
}
__device__ __forceinline__ void cp_async16(uint32_t dst, const void* src) {
    asm volatile("cp.async.cg.shared.global [%0], [%1], 16;" :: "r"(dst), "l"(src));
}
__device__ __forceinline__ void cp_commit() {
    asm volatile("cp.async.commit_group;" ::: "memory");
}
__device__ __forceinline__ void cp_wait0() {
    asm volatile("cp.async.wait_group 0;" ::: "memory");
}
__device__ __forceinline__ void ldmatrix4(uint32_t* r, uint32_t addr) {
    asm volatile("ldmatrix.sync.aligned.m8n8.x4.shared.b16 {%0,%1,%2,%3}, [%4];"
                 : "=r"(r[0]), "=r"(r[1]), "=r"(r[2]), "=r"(r[3]) : "r"(addr));
}
__device__ __forceinline__ void mma16816(float* c, const uint32_t* a, const uint32_t* b) {
    asm volatile("mma.sync.aligned.m16n8k16.row.col.f32.bf16.bf16.f32 "
                 "{%0,%1,%2,%3}, {%4,%5,%6,%7}, {%8,%9}, {%0,%1,%2,%3};"
                 : "+f"(c[0]), "+f"(c[1]), "+f"(c[2]), "+f"(c[3])
                 : "r"(a[0]), "r"(a[1]), "r"(a[2]), "r"(a[3]), "r"(b[0]), "r"(b[1]));
}

// ---------------- RPE collapse ----------------
__global__ void rpe_precompute(const float* __restrict__ Wrpe, const float* __restrict__ brpe) {
    int h = threadIdx.x;
    if (h >= HH) return;
    for (int p = 0; p < 3; p++) {
        float s = 0.f;
        for (int d = 0; d < 64; d++) s += Wrpe[p * 256 + h * 64 + d];
        g_rpe[p * HH + h] = s;
    }
    float b = 0.f;
    for (int d = 0; d < 64; d++) b += brpe[h * 64 + d];
    g_rpe[12 + h] = b;
}

// ---------------- CSR build ----------------
__global__ void zero_counts() {
    int i = blockIdx.x * blockDim.x + threadIdx.x;
    int stride = gridDim.x * blockDim.x;
    int* d = &g_deg[0][0];
    int* p = &g_pos[0][0];
    for (; i < 4 * NN; i += stride) { d[i] = 0; p[i] = 0; }
}
__global__ void count_kernel(const int* __restrict__ g, int aid) {
    int i = blockIdx.x * blockDim.x + threadIdx.x;
    if (i < EE) atomicAdd(&g_deg[aid][g[i]], 1);
}
// one block (1024 thr) per graph; exclusive prefix sum of degrees
__global__ void scan_kernel() {
    __shared__ int ssum[1024];
    int aid = blockIdx.x;
    int t = threadIdx.x;
    const int CH = 20;  // 1024*20 >= NN
    int base = t * CH;
    int loc[CH];
    int s = 0;
#pragma unroll
    for (int i = 0; i < CH; i++) {
        int idx = base + i;
        int v = (idx < NN) ? g_deg[aid][idx] : 0;
        loc[i] = s; s += v;
    }
    ssum[t] = s;
    __syncthreads();
    for (int o = 1; o < 1024; o <<= 1) {
        int v = (t >= o) ? ssum[t - o] : 0;
        __syncthreads();
        ssum[t] += v;
        __syncthreads();
    }
    int offs = (t > 0) ? ssum[t - 1] : 0;
#pragma unroll
    for (int i = 0; i < CH; i++) {
        int idx = base + i;
        if (idx < NN) g_off[aid][idx] = offs + loc[i];
    }
    if (t == 1023) g_off[aid][NN] = ssum[1023];
}
__global__ void permute_kernel(const int* __restrict__ g, int aid) {
    int i = blockIdx.x * blockDim.x + threadIdx.x;
    if (i >= EE) return;
    int d = g[i];
    int p = g_off[aid][d] + atomicAdd(&g_pos[aid][d], 1);
    g_srcs[aid][p] = g[EE + i];
}

// ---------------- fused per-node attention ----------------
// warp per dst node; 8-lane group per head; lane owns 8 dims.
// out[n, outoff + h*64 + (lane%8)*8 .. +8] = sum_e exp(q.k + rpe) * v / sum_e exp
__global__ __launch_bounds__(256)
void fused_attn(const float* __restrict__ qkvQ, int qoff,
                const float* __restrict__ qkvK, int koff,
                const float* __restrict__ qkvV, int voff,
                const float* __restrict__ coordD,
                const float* __restrict__ coordS,
                int useRpe, int aid,
                float* __restrict__ out, int outoff) {
    int w = (blockIdx.x * blockDim.x + threadIdx.x) >> 5;
    if (w >= NN) return;
    int lane = threadIdx.x & 31;
    int h = lane >> 3;            // head 0..3
    int dsub = (lane & 7) << 3;   // 8-dim slice start

    const float* qrow = qkvQ + (size_t)w * QW + qoff + h * 64 + dsub;
    float4 q0 = *(const float4*)(qrow);
    float4 q1 = *(const float4*)(qrow + 4);

    float r0 = 0.f, r1 = 0.f, r2 = 0.f, rb = 0.f, c0 = 0.f, c1 = 0.f, c2 = 0.f;
    if (useRpe) {
        r0 = g_rpe[h]; r1 = g_rpe[4 + h]; r2 = g_rpe[8 + h]; rb = g_rpe[12 + h];
        c0 = coordD[w * 3 + 0]; c1 = coordD[w * 3 + 1]; c2 = coordD[w * 3 + 2];
    }

    int s0 = g_off[aid][w], s1 = g_off[aid][w + 1];
    float a0 = 0.f, a1 = 0.f, a2 = 0.f, a3 = 0.f, a4 = 0.f, a5 = 0.f, a6 = 0.f, a7 = 0.f;
    float den = 0.f;

    for (int p = s0; p < s1; p++) {
        int src = g_srcs[aid][p];
        const float* krow = qkvK + (size_t)src * QW + koff + h * 64 + dsub;
        float4 k0 = *(const float4*)(krow);
        float4 k1 = *(const float4*)(krow + 4);
        float dot = q0.x * k0.x + q0.y * k0.y + q0.z * k0.z + q0.w * k0.w
                  + q1.x * k1.x + q1.y * k1.y + q1.z * k1.z + q1.w * k1.w;
        dot += __shfl_xor_sync(0xffffffffu, dot, 1);
        dot += __shfl_xor_sync(0xffffffffu, dot, 2);
        dot += __shfl_xor_sync(0xffffffffu, dot, 4);
        if (useRpe) {
            float d0 = c0 - coordS[src * 3 + 0];
            float d1 = c1 - coordS[src * 3 + 1];
            float d2 = c2 - coordS[src * 3 + 2];
            dot += d0 * r0 + d1 * r1 + d2 * r2 + rb;
        }
        float esc = __expf(dot);
        den += esc;
        const float* vrow = qkvV + (size_t)src * QW + voff + h * 64 + dsub;
        float4 v0 = *(const float4*)(vrow);
        float4 v1 = *(const float4*)(vrow + 4);
        a0 += esc * v0.x; a1 += esc * v0.y; a2 += esc * v0.z; a3 += esc * v0.w;
        a4 += esc * v1.x; a5 += esc * v1.y; a6 += esc * v1.z; a7 += esc * v1.w;
    }

    float inv = (den > 0.f) ? (1.f / den) : 0.f;
    float* orow = out + (size_t)w * AW + outoff + h * 64 + dsub;
    *(float4*)(orow)     = make_float4(a0 * inv, a1 * inv, a2 * inv, a3 * inv);
    *(float4*)(orow + 4) = make_float4(a4 * inv, a5 * inv, a6 * inv, a7 * inv);
}

// ---------------- split/interleave prep ----------------
__global__ void split_pad3(const float* __restrict__ src, __nv_bfloat16* __restrict__ dst,
                           int nrows_valid, int nrows_total, int K) {
    int idx = blockIdx.x * blockDim.x + threadIdx.x;
    int stride = gridDim.x * blockDim.x;
    int total = nrows_total * K;
    for (int i = idx; i < total; i += stride) {
        int r = i / K, k = i - r * K;
        float x = (r < nrows_valid) ? src[i] : 0.f;
        __nv_bfloat16 h = __float2bfloat16(x);
        __nv_bfloat16 l = __float2bfloat16(x - __bfloat162float(h));
        size_t base = (size_t)r * (3 * K) + k;
        dst[base]         = h;
        dst[base + K]     = h;
        dst[base + 2 * K] = l;
    }
}
__global__ void transpose_split3(const float* __restrict__ W, __nv_bfloat16* __restrict__ dst,
                                 int K, int Nc) {
    int i = blockIdx.x * blockDim.x + threadIdx.x;
    if (i >= K * Nc) return;
    int k = i / Nc, n = i - k * Nc;
    float x = W[i];
    __nv_bfloat16 h = __float2bfloat16(x);
    __nv_bfloat16 l = __float2bfloat16(x - __bfloat162float(h));
    size_t base = (size_t)n * (3 * K) + k;
    dst[base]         = h;
    dst[base + K]     = l;
    dst[base + 2 * K] = h;
}

// ---------------- bf16 mma.sync GEMM ----------------
#define GSMEM 65536

__global__ __launch_bounds__(256)
void gemm_bf16_mma(const __nv_bfloat16* __restrict__ A, const __nv_bfloat16* __restrict__ B,
                   const float* __restrict__ bias, float* __restrict__ C,
                   int M, int Kp, int Nc) {
    extern __shared__ char smem[];
    const uint32_t sA_u = smem_u32(smem);
    const uint32_t sB_u = sA_u + 32768;

    const int t = threadIdx.x;
    const int wid = t >> 5, lane = t & 31;
    const int wm = wid & 1, wn = wid >> 1;
    const int m0 = blockIdx.y * 128, n0 = blockIdx.x * 128;

    float acc[4][4][4];
#pragma unroll
    for (int i = 0; i < 4; i++)
#pragma unroll
        for (int j = 0; j < 4; j++)
#pragma unroll
            for (int v = 0; v < 4; v++) acc[i][j][v] = 0.f;

    auto load_tiles = [&](int buf, int k0) {
#pragma unroll
        for (int i = 0; i < 4; i++) {
            int lin = i * 256 + t;
            int row = lin >> 3, ku = lin & 7;
            uint32_t b = (uint32_t)(row * 128 + ku * 16);
            b ^= (b >> 3) & 0x70;
            cp_async16(sA_u + buf * 16384 + b, A + (size_t)(m0 + row) * Kp + k0 + ku * 8);
            cp_async16(sB_u + buf * 16384 + b, B + (size_t)(n0 + row) * Kp + k0 + ku * 8);
        }
    };

    const int nk = Kp >> 6;
    load_tiles(0, 0);
    cp_commit();

    for (int kt = 0; kt < nk; kt++) {
        cp_wait0();
        __syncthreads();
        if (kt + 1 < nk) { load_tiles((kt + 1) & 1, (kt + 1) << 6); cp_commit(); }

        const uint32_t bufA = sA_u + (kt & 1) * 16384;
        const uint32_t bufB = sB_u + (kt & 1) * 16384;
#pragma unroll
        for (int kk = 0; kk < 4; kk++) {
            uint32_t afrag[4][4], bfrag[4][2];
            const int kseg = kk * 2 + (lane >> 4);
#pragma unroll
            for (int mt = 0; mt < 4; mt++) {
                int row = wm * 64 + mt * 16 + (lane & 15);
                uint32_t b = (uint32_t)(row * 128 + kseg * 16);
                b ^= (b >> 3) & 0x70;
                ldmatrix4(afrag[mt], bufA + b);
            }
#pragma unroll
            for (int nt2 = 0; nt2 < 2; nt2++) {
                int row = wn * 32 + nt2 * 16 + (lane & 7) + ((lane >> 3) & 1) * 8;
                uint32_t b = (uint32_t)(row * 128 + kseg * 16);
                b ^= (b >> 3) & 0x70;
                uint32_t r[4];
                ldmatrix4(r, bufB + b);
                bfrag[nt2 * 2][0]     = r[0]; bfrag[nt2 * 2][1]     = r[2];
                bfrag[nt2 * 2 + 1][0] = r[1]; bfrag[nt2 * 2 + 1][1] = r[3];
            }
#pragma unroll
            for (int mt = 0; mt < 4; mt++)
#pragma unroll
                for (int nt = 0; nt < 4; nt++)
                    mma16816(acc[mt][nt], afrag[mt], bfrag[nt]);
        }
        __syncthreads();
    }

#pragma unroll
    for (int mt = 0; mt < 4; mt++) {
        int rbase = m0 + wm * 64 + mt * 16 + (lane >> 2);
#pragma unroll
        for (int nt = 0; nt < 4; nt++) {
            int c = n0 + wn * 32 + nt * 8 + (lane & 3) * 2;
            float bx = bias[c], by = bias[c + 1];
            if (rbase < M) {
                float2 o = make_float2(acc[mt][nt][0] + bx, acc[mt][nt][1] + by);
                *(float2*)(C + (size_t)rbase * Nc + c) = o;
            }
            if (rbase + 8 < M) {
                float2 o = make_float2(acc[mt][nt][2] + bx, acc[mt][nt][3] + by);
                *(float2*)(C + (size_t)(rbase + 8) * Nc + c) = o;
            }
        }
    }
}

// ---------------- launch ----------------
extern "C" void kernel_launch(void* const* d_in, const int* in_sizes, int n_in,
                              void* d_out, int out_size) {
    const float* feat1  = (const float*)d_in[0];
    const float* coord1 = (const float*)d_in[1];
    const float* feat2  = (const float*)d_in[2];
    const float* coord2 = (const float*)d_in[3];
    const float* Wqkv1  = (const float*)d_in[4];
    const float* bqkv1  = (const float*)d_in[5];
    const float* Wqkv2  = (const float*)d_in[6];
    const float* bqkv2  = (const float*)d_in[7];
    const float* Wproj1 = (const float*)d_in[8];
    const float* bproj1 = (const float*)d_in[9];
    const float* Wproj2 = (const float*)d_in[10];
    const float* bproj2 = (const float*)d_in[11];
    const float* Wrpe   = (const float*)d_in[12];
    const float* brpe   = (const float*)d_in[13];
    const int* graph1   = (const int*)d_in[14];
    const int* graph2   = (const int*)d_in[15];
    const int* graph12  = (const int*)d_in[16];
    const int* graph21  = (const int*)d_in[17];
    float* out = (float*)d_out;

    float *qkv1, *qkv2, *att1, *att2;
    cudaGetSymbolAddress((void**)&qkv1, g_qkv1);
    cudaGetSymbolAddress((void**)&qkv2, g_qkv2);
    cudaGetSymbolAddress((void**)&att1, g_att1);
    cudaGetSymbolAddress((void**)&att2, g_att2);
    __nv_bfloat16 *f1p, *f2p, *t1p, *t2p, *w1p, *w2p, *p1p, *p2p;
    cudaGetSymbolAddress((void**)&f1p, g_f1p);
    cudaGetSymbolAddress((void**)&f2p, g_f2p);
    cudaGetSymbolAddress((void**)&t1p, g_t1p);
    cudaGetSymbolAddress((void**)&t2p, g_t2p);
    cudaGetSymbolAddress((void**)&w1p, g_w1p);
    cudaGetSymbolAddress((void**)&w2p, g_w2p);
    cudaGetSymbolAddress((void**)&p1p, g_p1p);
    cudaGetSymbolAddress((void**)&p2p, g_p2p);

    cudaFuncSetAttribute(gemm_bf16_mma, cudaFuncAttributeMaxDynamicSharedMemorySize, GSMEM);

    rpe_precompute<<<1, 32>>>(Wrpe, brpe);

    // CSR build (4 graphs)
    zero_counts<<<(4 * NN + 255) / 256, 256>>>();
    const int EBLK = (EE + 255) / 256;
    count_kernel<<<EBLK, 256>>>(graph1, 0);
    count_kernel<<<EBLK, 256>>>(graph2, 1);
    count_kernel<<<EBLK, 256>>>(graph21, 2);
    count_kernel<<<EBLK, 256>>>(graph12, 3);
    scan_kernel<<<4, 1024>>>();
    permute_kernel<<<EBLK, 256>>>(graph1, 0);
    permute_kernel<<<EBLK, 256>>>(graph2, 1);
    permute_kernel<<<EBLK, 256>>>(graph21, 2);
    permute_kernel<<<EBLK, 256>>>(graph12, 3);

    // operand prep (3-term split interleave)
    split_pad3<<<2048, 256>>>(feat1, f1p, NN, NP, 256);
    split_pad3<<<2048, 256>>>(feat2, f2p, NN, NP, 256);
    transpose_split3<<<(256 * 1536 + 255) / 256, 256>>>(Wqkv1, w1p, 256, 1536);
    transpose_split3<<<(256 * 1536 + 255) / 256, 256>>>(Wqkv2, w2p, 256, 1536);
    transpose_split3<<<(512 * 256 + 255) / 256, 256>>>(Wproj1, p1p, 512, 256);
    transpose_split3<<<(512 * 256 + 255) / 256, 256>>>(Wproj2, p2p, 512, 256);

    // QKV GEMMs: [20000,256] @ [256,1536]  (Kp = 768)
    dim3 gq(QW / 128, NP / 128);
    gemm_bf16_mma<<<gq, 256, GSMEM>>>(f1p, w1p, bqkv1, qkv1, NN, 768, QW);
    gemm_bf16_mma<<<gq, 256, GSMEM>>>(f2p, w2p, bqkv2, qkv2, NN, 768, QW);

    // fused attention; qkv row layout [q_a(0) k_a(256) v_a(512) q_b(768) k_b(1024) v_b(1280)]
    const int ABLK = (NN * 32 + 255) / 256;
    fused_attn<<<ABLK, 256>>>(qkv1,    0, qkv1,  256, qkv1,  512, coord1, coord1, 1, 0, att1,   0);
    fused_attn<<<ABLK, 256>>>(qkv2,  768, qkv2, 1024, qkv2, 1280, coord2, coord2, 1, 1, att2,   0);
    fused_attn<<<ABLK, 256>>>(qkv1,  768, qkv2,  256, qkv2,  512, nullptr, nullptr, 0, 2, att1, 256);
    fused_attn<<<ABLK, 256>>>(qkv2,    0, qkv1, 1024, qkv1, 1280, nullptr, nullptr, 0, 3, att2, 256);

    // split attention outputs for proj GEMMs (Kp = 1536)
    split_pad3<<<2048, 256>>>(att1, t1p, NN, NP, 512);
    split_pad3<<<2048, 256>>>(att2, t2p, NN, NP, 512);

    // Output projections: [20000,512] @ [512,256]
    dim3 gp(256 / 128, NP / 128);
    gemm_bf16_mma<<<gp, 256, GSMEM>>>(t1p, p1p, bproj1, out,                    NN, 1536, 256);
    gemm_bf16_mma<<<gp, 256, GSMEM>>>(t2p, p2p, bproj2, out + (size_t)NN * 256, NN, 1536, 256);
}

// round 8
// speedup vs baseline: 2.2100x; 1.0988x over previous
#include <cuda_runtime.h>
#include <cuda_bf16.h>
#include <math.h>
#include <stdint.h>

#define NN 20000
#define EE 320000
#define HH 4
#define QW 1536   // 6*C
#define AW 512    // 2*C
#define NP 20096  // 157 * 128 (padded M)

// ---------------- scratch (static device globals) ----------------
__device__ __align__(16) float g_qkv1[NN * QW];
__device__ __align__(16) float g_qkv2[NN * QW];
__device__ float g_rpe[16];

// CSR per graph
__device__ int g_deg[4][NN];
__device__ int g_off[4][NN + 1];
__device__ int g_pos[4][NN];
__device__ int g_srcs[4][EE];    // src node ids, grouped by dst

// interleaved 3-term-split bf16 operands:
//   A' rows: [hi(K) | hi(K) | lo(K)]   B' rows: [hi(K) | lo(K) | hi(K)]
__device__ __align__(16) __nv_bfloat16 g_f1p[NP * 768];
__device__ __align__(16) __nv_bfloat16 g_f2p[NP * 768];
__device__ __align__(16) __nv_bfloat16 g_t1p[NP * 1536];   // attention out (set1), split
__device__ __align__(16) __nv_bfloat16 g_t2p[NP * 1536];   // attention out (set2), split
__device__ __align__(16) __nv_bfloat16 g_w1p[1536 * 768];
__device__ __align__(16) __nv_bfloat16 g_w2p[1536 * 768];
__device__ __align__(16) __nv_bfloat16 g_p1p[256 * 1536];
__device__ __align__(16) __nv_bfloat16 g_p2p[256 * 1536];

// ---------------- helpers ----------------
__device__ __forceinline__ uint32_t smem_u32(const void* p) {
    uint32_t a;
    asm("{ .reg .u64 t; cvta.to.shared.u64 t, %1; cvt.u32.u64 %0, t; }" : "=r"(a) : "l"(p));
    return a;
}
__device__ __forceinline__ void cp_async16(uint32_t dst, const void* src) {
    asm volatile("cp.async.cg.shared.global [%0], [%1], 16;" :: "r"(dst), "l"(src));
}
__device__ __forceinline__ void cp_commit() {
    asm volatile("cp.async.commit_group;" ::: "memory");
}
__device__ __forceinline__ void cp_wait0() {
    asm volatile("cp.async.wait_group 0;" ::: "memory");
}
__device__ __forceinline__ void ldmatrix4(uint32_t* r, uint32_t addr) {
    asm volatile("ldmatrix.sync.aligned.m8n8.x4.shared.b16 {%0,%1,%2,%3}, [%4];"
                 : "=r"(r[0]), "=r"(r[1]), "=r"(r[2]), "=r"(r[3]) : "r"(addr));
}
__device__ __forceinline__ void mma16816(float* c, const uint32_t* a, const uint32_t* b) {
    asm volatile("mma.sync.aligned.m16n8k16.row.col.f32.bf16.bf16.f32 "
                 "{%0,%1,%2,%3}, {%4,%5,%6,%7}, {%8,%9}, {%0,%1,%2,%3};"
                 : "+f"(c[0]), "+f"(c[1]), "+f"(c[2]), "+f"(c[3])
                 : "r"(a[0]), "r"(a[1]), "r"(a[2]), "r"(a[3]), "r"(b[0]), "r"(b[1]));
}

// ---------------- RPE collapse ----------------
__global__ void rpe_precompute(const float* __restrict__ Wrpe, const float* __restrict__ brpe) {
    int h = threadIdx.x;
    if (h >= HH) return;
    for (int p = 0; p < 3; p++) {
        float s = 0.f;
        for (int d = 0; d < 64; d++) s += Wrpe[p * 256 + h * 64 + d];
        g_rpe[p * HH + h] = s;
    }
    float b = 0.f;
    for (int d = 0; d < 64; d++) b += brpe[h * 64 + d];
    g_rpe[12 + h] = b;
}

// ---------------- init: zero CSR counters + pad rows of t buffers ----------------
#define TPAD ((NP - NN) * 1536)
__global__ void init_all() {
    int i = blockIdx.x * blockDim.x + threadIdx.x;
    int stride = gridDim.x * blockDim.x;
    int* d = &g_deg[0][0];
    int* p = &g_pos[0][0];
    for (int j = i; j < 4 * NN; j += stride) { d[j] = 0; p[j] = 0; }
    __nv_bfloat16 z = __float2bfloat16(0.f);
    for (int j = i; j < TPAD; j += stride) {
        g_t1p[(size_t)NN * 1536 + j] = z;
        g_t2p[(size_t)NN * 1536 + j] = z;
    }
}

// ---------------- CSR build (batched over 4 graphs via blockIdx.y) ----------------
__global__ void count4(const int* __restrict__ g0, const int* __restrict__ g1,
                       const int* __restrict__ g2, const int* __restrict__ g3) {
    int aid = blockIdx.y;
    const int* g = (aid == 0) ? g0 : (aid == 1) ? g1 : (aid == 2) ? g2 : g3;
    int i = blockIdx.x * blockDim.x + threadIdx.x;
    if (i < EE) atomicAdd(&g_deg[aid][g[i]], 1);
}
__global__ void scan_kernel() {
    __shared__ int ssum[1024];
    int aid = blockIdx.x;
    int t = threadIdx.x;
    const int CH = 20;
    int base = t * CH;
    int loc[CH];
    int s = 0;
#pragma unroll
    for (int i = 0; i < CH; i++) {
        int idx = base + i;
        int v = (idx < NN) ? g_deg[aid][idx] : 0;
        loc[i] = s; s += v;
    }
    ssum[t] = s;
    __syncthreads();
    for (int o = 1; o < 1024; o <<= 1) {
        int v = (t >= o) ? ssum[t - o] : 0;
        __syncthreads();
        ssum[t] += v;
        __syncthreads();
    }
    int offs = (t > 0) ? ssum[t - 1] : 0;
#pragma unroll
    for (int i = 0; i < CH; i++) {
        int idx = base + i;
        if (idx < NN) g_off[aid][idx] = offs + loc[i];
    }
    if (t == 1023) g_off[aid][NN] = ssum[1023];
}
__global__ void permute4(const int* __restrict__ g0, const int* __restrict__ g1,
                         const int* __restrict__ g2, const int* __restrict__ g3) {
    int aid = blockIdx.y;
    const int* g = (aid == 0) ? g0 : (aid == 1) ? g1 : (aid == 2) ? g2 : g3;
    int i = blockIdx.x * blockDim.x + threadIdx.x;
    if (i >= EE) return;
    int d = g[i];
    int p = g_off[aid][d] + atomicAdd(&g_pos[aid][d], 1);
    g_srcs[aid][p] = g[EE + i];
}

// ---------------- fused per-node attention -> direct 3-term bf16 split output ----------------
// warp per dst node; 8-lane group per head; lane owns 8 dims.
// Writes row w of outp [NP,1536]: hi at ch, hi at ch+512, lo at ch+1024.
__global__ __launch_bounds__(256)
void fused_attn(const float* __restrict__ qkvQ, int qoff,
                const float* __restrict__ qkvK, int koff,
                const float* __restrict__ qkvV, int voff,
                const float* __restrict__ coordD,
                const float* __restrict__ coordS,
                int useRpe, int aid,
                __nv_bfloat16* __restrict__ outp, int outoff) {
    int w = (blockIdx.x * blockDim.x + threadIdx.x) >> 5;
    if (w >= NN) return;
    int lane = threadIdx.x & 31;
    int h = lane >> 3;            // head 0..3
    int dsub = (lane & 7) << 3;   // 8-dim slice start

    const float* qrow = qkvQ + (size_t)w * QW + qoff + h * 64 + dsub;
    float4 q0 = *(const float4*)(qrow);
    float4 q1 = *(const float4*)(qrow + 4);

    float r0 = 0.f, r1 = 0.f, r2 = 0.f, rb = 0.f, c0 = 0.f, c1 = 0.f, c2 = 0.f;
    if (useRpe) {
        r0 = g_rpe[h]; r1 = g_rpe[4 + h]; r2 = g_rpe[8 + h]; rb = g_rpe[12 + h];
        c0 = coordD[w * 3 + 0]; c1 = coordD[w * 3 + 1]; c2 = coordD[w * 3 + 2];
    }

    int s0 = g_off[aid][w], s1 = g_off[aid][w + 1];
    float a0 = 0.f, a1 = 0.f, a2 = 0.f, a3 = 0.f, a4 = 0.f, a5 = 0.f, a6 = 0.f, a7 = 0.f;
    float den = 0.f;

#pragma unroll 2
    for (int p = s0; p < s1; p++) {
        int src = g_srcs[aid][p];
        const float* krow = qkvK + (size_t)src * QW + koff + h * 64 + dsub;
        float4 k0 = *(const float4*)(krow);
        float4 k1 = *(const float4*)(krow + 4);
        const float* vrow = qkvV + (size_t)src * QW + voff + h * 64 + dsub;
        float4 v0 = *(const float4*)(vrow);
        float4 v1 = *(const float4*)(vrow + 4);
        float dot = q0.x * k0.x + q0.y * k0.y + q0.z * k0.z + q0.w * k0.w
                  + q1.x * k1.x + q1.y * k1.y + q1.z * k1.z + q1.w * k1.w;
        dot += __shfl_xor_sync(0xffffffffu, dot, 1);
        dot += __shfl_xor_sync(0xffffffffu, dot, 2);
        dot += __shfl_xor_sync(0xffffffffu, dot, 4);
        if (useRpe) {
            float d0 = c0 - coordS[src * 3 + 0];
            float d1 = c1 - coordS[src * 3 + 1];
            float d2 = c2 - coordS[src * 3 + 2];
            dot += d0 * r0 + d1 * r1 + d2 * r2 + rb;
        }
        float esc = __expf(dot);
        den += esc;
        a0 += esc * v0.x; a1 += esc * v0.y; a2 += esc * v0.z; a3 += esc * v0.w;
        a4 += esc * v1.x; a5 += esc * v1.y; a6 += esc * v1.z; a7 += esc * v1.w;
    }

    float inv = (den > 0.f) ? (1.f / den) : 0.f;
    float vals[8] = {a0 * inv, a1 * inv, a2 * inv, a3 * inv,
                     a4 * inv, a5 * inv, a6 * inv, a7 * inv};
    __align__(16) __nv_bfloat16 h8[8];
    __align__(16) __nv_bfloat16 l8[8];
#pragma unroll
    for (int j = 0; j < 8; j++) {
        h8[j] = __float2bfloat16(vals[j]);
        l8[j] = __float2bfloat16(vals[j] - __bfloat162float(h8[j]));
    }
    size_t rb_off = (size_t)w * 1536 + outoff + h * 64 + dsub;
    uint4 uh = *(const uint4*)h8;
    uint4 ul = *(const uint4*)l8;
    *(uint4*)(outp + rb_off)        = uh;
    *(uint4*)(outp + rb_off + 512)  = uh;
    *(uint4*)(outp + rb_off + 1024) = ul;
}

// ---------------- split/interleave prep ----------------
__global__ void split_pad3(const float* __restrict__ src, __nv_bfloat16* __restrict__ dst,
                           int nrows_valid, int nrows_total, int K) {
    int idx = blockIdx.x * blockDim.x + threadIdx.x;
    int stride = gridDim.x * blockDim.x;
    int total = nrows_total * K;
    for (int i = idx; i < total; i += stride) {
        int r = i / K, k = i - r * K;
        float x = (r < nrows_valid) ? src[i] : 0.f;
        __nv_bfloat16 h = __float2bfloat16(x);
        __nv_bfloat16 l = __float2bfloat16(x - __bfloat162float(h));
        size_t base = (size_t)r * (3 * K) + k;
        dst[base]         = h;
        dst[base + K]     = h;
        dst[base + 2 * K] = l;
    }
}
__global__ void transpose_split3(const float* __restrict__ W, __nv_bfloat16* __restrict__ dst,
                                 int K, int Nc) {
    int i = blockIdx.x * blockDim.x + threadIdx.x;
    if (i >= K * Nc) return;
    int k = i / Nc, n = i - k * Nc;
    float x = W[i];
    __nv_bfloat16 h = __float2bfloat16(x);
    __nv_bfloat16 l = __float2bfloat16(x - __bfloat162float(h));
    size_t base = (size_t)n * (3 * K) + k;
    dst[base]         = h;
    dst[base + K]     = l;
    dst[base + 2 * K] = h;
}

// ---------------- bf16 mma.sync GEMM ----------------
#define GSMEM 65536

__global__ __launch_bounds__(256)
void gemm_bf16_mma(const __nv_bfloat16* __restrict__ A, const __nv_bfloat16* __restrict__ B,
                   const float* __restrict__ bias, float* __restrict__ C,
                   int M, int Kp, int Nc) {
    extern __shared__ char smem[];
    const uint32_t sA_u = smem_u32(smem);
    const uint32_t sB_u = sA_u + 32768;

    const int t = threadIdx.x;
    const int wid = t >> 5, lane = t & 31;
    const int wm = wid & 1, wn = wid >> 1;
    const int m0 = blockIdx.y * 128, n0 = blockIdx.x * 128;

    float acc[4][4][4];
#pragma unroll
    for (int i = 0; i < 4; i++)
#pragma unroll
        for (int j = 0; j < 4; j++)
#pragma unroll
            for (int v = 0; v < 4; v++) acc[i][j][v] = 0.f;

    auto load_tiles = [&](int buf, int k0) {
#pragma unroll
        for (int i = 0; i < 4; i++) {
            int lin = i * 256 + t;
            int row = lin >> 3, ku = lin & 7;
            uint32_t b = (uint32_t)(row * 128 + ku * 16);
            b ^= (b >> 3) & 0x70;
            cp_async16(sA_u + buf * 16384 + b, A + (size_t)(m0 + row) * Kp + k0 + ku * 8);
            cp_async16(sB_u + buf * 16384 + b, B + (size_t)(n0 + row) * Kp + k0 + ku * 8);
        }
    };

    const int nk = Kp >> 6;
    load_tiles(0, 0);
    cp_commit();

    for (int kt = 0; kt < nk; kt++) {
        cp_wait0();
        __syncthreads();
        if (kt + 1 < nk) { load_tiles((kt + 1) & 1, (kt + 1) << 6); cp_commit(); }

        const uint32_t bufA = sA_u + (kt & 1) * 16384;
        const uint32_t bufB = sB_u + (kt & 1) * 16384;
#pragma unroll
        for (int kk = 0; kk < 4; kk++) {
            uint32_t afrag[4][4], bfrag[4][2];
            const int kseg = kk * 2 + (lane >> 4);
#pragma unroll
            for (int mt = 0; mt < 4; mt++) {
                int row = wm * 64 + mt * 16 + (lane & 15);
                uint32_t b = (uint32_t)(row * 128 + kseg * 16);
                b ^= (b >> 3) & 0x70;
                ldmatrix4(afrag[mt], bufA + b);
            }
#pragma unroll
            for (int nt2 = 0; nt2 < 2; nt2++) {
                int row = wn * 32 + nt2 * 16 + (lane & 7) + ((lane >> 3) & 1) * 8;
                uint32_t b = (uint32_t)(row * 128 + kseg * 16);
                b ^= (b >> 3) & 0x70;
                uint32_t r[4];
                ldmatrix4(r, bufB + b);
                bfrag[nt2 * 2][0]     = r[0]; bfrag[nt2 * 2][1]     = r[2];
                bfrag[nt2 * 2 + 1][0] = r[1]; bfrag[nt2 * 2 + 1][1] = r[3];
            }
#pragma unroll
            for (int mt = 0; mt < 4; mt++)
#pragma unroll
                for (int nt = 0; nt < 4; nt++)
                    mma16816(acc[mt][nt], afrag[mt], bfrag[nt]);
        }
        __syncthreads();
    }

#pragma unroll
    for (int mt = 0; mt < 4; mt++) {
        int rbase = m0 + wm * 64 + mt * 16 + (lane >> 2);
#pragma unroll
        for (int nt = 0; nt < 4; nt++) {
            int c = n0 + wn * 32 + nt * 8 + (lane & 3) * 2;
            float bx = bias[c], by = bias[c + 1];
            if (rbase < M) {
                float2 o = make_float2(acc[mt][nt][0] + bx, acc[mt][nt][1] + by);
                *(float2*)(C + (size_t)rbase * Nc + c) = o;
            }
            if (rbase + 8 < M) {
                float2 o = make_float2(acc[mt][nt][2] + bx, acc[mt][nt][3] + by);
                *(float2*)(C + (size_t)(rbase + 8) * Nc + c) = o;
            }
        }
    }
}

// ---------------- launch ----------------
extern "C" void kernel_launch(void* const* d_in, const int* in_sizes, int n_in,
                              void* d_out, int out_size) {
    const float* feat1  = (const float*)d_in[0];
    const float* coord1 = (const float*)d_in[1];
    const float* feat2  = (const float*)d_in[2];
    const float* coord2 = (const float*)d_in[3];
    const float* Wqkv1  = (const float*)d_in[4];
    const float* bqkv1  = (const float*)d_in[5];
    const float* Wqkv2  = (const float*)d_in[6];
    const float* bqkv2  = (const float*)d_in[7];
    const float* Wproj1 = (const float*)d_in[8];
    const float* bproj1 = (const float*)d_in[9];
    const float* Wproj2 = (const float*)d_in[10];
    const float* bproj2 = (const float*)d_in[11];
    const float* Wrpe   = (const float*)d_in[12];
    const float* brpe   = (const float*)d_in[13];
    const int* graph1   = (const int*)d_in[14];
    const int* graph2   = (const int*)d_in[15];
    const int* graph12  = (const int*)d_in[16];
    const int* graph21  = (const int*)d_in[17];
    float* out = (float*)d_out;

    float *qkv1, *qkv2;
    cudaGetSymbolAddress((void**)&qkv1, g_qkv1);
    cudaGetSymbolAddress((void**)&qkv2, g_qkv2);
    __nv_bfloat16 *f1p, *f2p, *t1p, *t2p, *w1p, *w2p, *p1p, *p2p;
    cudaGetSymbolAddress((void**)&f1p, g_f1p);
    cudaGetSymbolAddress((void**)&f2p, g_f2p);
    cudaGetSymbolAddress((void**)&t1p, g_t1p);
    cudaGetSymbolAddress((void**)&t2p, g_t2p);
    cudaGetSymbolAddress((void**)&w1p, g_w1p);
    cudaGetSymbolAddress((void**)&w2p, g_w2p);
    cudaGetSymbolAddress((void**)&p1p, g_p1p);
    cudaGetSymbolAddress((void**)&p2p, g_p2p);

    cudaFuncSetAttribute(gemm_bf16_mma, cudaFuncAttributeMaxDynamicSharedMemorySize, GSMEM);

    rpe_precompute<<<1, 32>>>(Wrpe, brpe);
    init_all<<<(TPAD + 255) / 256, 256>>>();

    // CSR build (batched)
    const int EBLK = (EE + 255) / 256;
    dim3 gcnt(EBLK, 4);
    count4<<<gcnt, 256>>>(graph1, graph2, graph21, graph12);
    scan_kernel<<<4, 1024>>>();
    permute4<<<gcnt, 256>>>(graph1, graph2, graph21, graph12);

    // operand prep (3-term split interleave)
    split_pad3<<<2048, 256>>>(feat1, f1p, NN, NP, 256);
    split_pad3<<<2048, 256>>>(feat2, f2p, NN, NP, 256);
    transpose_split3<<<(256 * 1536 + 255) / 256, 256>>>(Wqkv1, w1p, 256, 1536);
    transpose_split3<<<(256 * 1536 + 255) / 256, 256>>>(Wqkv2, w2p, 256, 1536);
    transpose_split3<<<(512 * 256 + 255) / 256, 256>>>(Wproj1, p1p, 512, 256);
    transpose_split3<<<(512 * 256 + 255) / 256, 256>>>(Wproj2, p2p, 512, 256);

    // QKV GEMMs: [20000,256] @ [256,1536]  (Kp = 768)
    dim3 gq(QW / 128, NP / 128);
    gemm_bf16_mma<<<gq, 256, GSMEM>>>(f1p, w1p, bqkv1, qkv1, NN, 768, QW);
    gemm_bf16_mma<<<gq, 256, GSMEM>>>(f2p, w2p, bqkv2, qkv2, NN, 768, QW);

    // fused attention writes split bf16 directly into t1p/t2p
    // qkv row layout [q_a(0) k_a(256) v_a(512) q_b(768) k_b(1024) v_b(1280)]
    const int ABLK = (NN * 32 + 255) / 256;
    fused_attn<<<ABLK, 256>>>(qkv1,    0, qkv1,  256, qkv1,  512, coord1, coord1, 1, 0, t1p,   0);
    fused_attn<<<ABLK, 256>>>(qkv2,  768, qkv2, 1024, qkv2, 1280, coord2, coord2, 1, 1, t2p,   0);
    fused_attn<<<ABLK, 256>>>(qkv1,  768, qkv2,  256, qkv2,  512, nullptr, nullptr, 0, 2, t1p, 256);
    fused_attn<<<ABLK, 256>>>(qkv2,    0, qkv1, 1024, qkv1, 1280, nullptr, nullptr, 0, 3, t2p, 256);

    // Output projections: [20000,512] @ [512,256]  (Kp = 1536)
    dim3 gp(256 / 128, NP / 128);
    gemm_bf16_mma<<<gp, 256, GSMEM>>>(t1p, p1p, bproj1, out,                    NN, 1536, 256);
    gemm_bf16_mma<<<gp, 256, GSMEM>>>(t2p, p2p, bproj2, out + (size_t)NN * 256, NN, 1536, 256);
}

// round 9
// speedup vs baseline: 2.4734x; 1.1192x over previous
#include <cuda_runtime.h>
#include <cuda_bf16.h>
#include <math.h>
#include <stdint.h>

#define NN 20000
#define EE 320000
#define HH 4
#define QW 1536   // 6*C
#define AW 512    // 2*C
#define NP 20096  // 157 * 128 (padded M)

// ---------------- scratch (static device globals) ----------------
__device__ __align__(16) float g_qkv1[NN * QW];
__device__ __align__(16) float g_qkv2[NN * QW];
__device__ float g_rpe[16];

// CSR per graph
__device__ int g_deg[4][NN];
__device__ int g_off[4][NN + 1];
__device__ int g_pos[4][NN];
__device__ int g_srcs[4][EE];

// interleaved 3-term-split bf16 operands:
//   A' rows: [hi(K) | hi(K) | lo(K)]   B' rows: [hi(K) | lo(K) | hi(K)]
__device__ __align__(16) __nv_bfloat16 g_f1p[NP * 768];
__device__ __align__(16) __nv_bfloat16 g_f2p[NP * 768];
__device__ __align__(16) __nv_bfloat16 g_t1p[NP * 1536];
__device__ __align__(16) __nv_bfloat16 g_t2p[NP * 1536];
__device__ __align__(16) __nv_bfloat16 g_w1p[1536 * 768];
__device__ __align__(16) __nv_bfloat16 g_w2p[1536 * 768];
__device__ __align__(16) __nv_bfloat16 g_p1p[256 * 1536];
__device__ __align__(16) __nv_bfloat16 g_p2p[256 * 1536];

// ---------------- helpers ----------------
__device__ __forceinline__ uint32_t smem_u32(const void* p) {
    uint32_t a;
    asm("{ .reg .u64 t; cvta.to.shared.u64 t, %1; cvt.u32.u64 %0, t; }" : "=r"(a) : "l"(p));
    return a;
}
__device__ __forceinline__ void cp_async16(uint32_t dst, const void* src) {
    asm volatile("cp.async.cg.shared.global [%0], [%1], 16;" :: "r"(dst), "l"(src));
}
__device__ __forceinline__ void cp_commit() {
    asm volatile("cp.async.commit_group;" ::: "memory");
}
__device__ __forceinline__ void cp_wait0() {
    asm volatile("cp.async.wait_group 0;" ::: "memory");
}
__device__ __forceinline__ void ldmatrix4(uint32_t* r, uint32_t addr) {
    asm volatile("ldmatrix.sync.aligned.m8n8.x4.shared.b16 {%0,%1,%2,%3}, [%4];"
                 : "=r"(r[0]), "=r"(r[1]), "=r"(r[2]), "=r"(r[3]) : "r"(addr));
}
__device__ __forceinline__ void mma16816(float* c, const uint32_t* a, const uint32_t* b) {
    asm volatile("mma.sync.aligned.m16n8k16.row.col.f32.bf16.bf16.f32 "
                 "{%0,%1,%2,%3}, {%4,%5,%6,%7}, {%8,%9}, {%0,%1,%2,%3};"
                 : "+f"(c[0]), "+f"(c[1]), "+f"(c[2]), "+f"(c[3])
                 : "r"(a[0]), "r"(a[1]), "r"(a[2]), "r"(a[3]), "r"(b[0]), "r"(b[1]));
}

// ---------------- prep: rpe + zero CSR counters + zero t-buffer pad rows ----------------
#define TPAD ((NP - NN) * 1536)          // bf16 elems of pad per t buffer
#define TPADV (TPAD / 8)                 // uint4 chunks
__global__ void prep_all(const float* __restrict__ Wrpe, const float* __restrict__ brpe) {
    int gid = blockIdx.x * blockDim.x + threadIdx.x;
    int stride = gridDim.x * blockDim.x;

    if (blockIdx.x == 0 && threadIdx.x < HH) {
        int h = threadIdx.x;
        for (int p = 0; p < 3; p++) {
            float s = 0.f;
            for (int d = 0; d < 64; d++) s += Wrpe[p * 256 + h * 64 + d];
            g_rpe[p * HH + h] = s;
        }
        float b = 0.f;
        for (int d = 0; d < 64; d++) b += brpe[h * 64 + d];
        g_rpe[12 + h] = b;
    }

    int* d = &g_deg[0][0];
    int* p = &g_pos[0][0];
    for (int j = gid; j < 4 * NN; j += stride) { d[j] = 0; p[j] = 0; }

    uint4 zz = make_uint4(0, 0, 0, 0);
    uint4* t1 = (uint4*)(&g_t1p[(size_t)NN * 1536]);
    uint4* t2 = (uint4*)(&g_t2p[(size_t)NN * 1536]);
    for (int j = gid; j < TPADV; j += stride) { t1[j] = zz; t2[j] = zz; }
}

// ---------------- CSR build ----------------
__global__ void count4(const int* __restrict__ g0, const int* __restrict__ g1,
                       const int* __restrict__ g2, const int* __restrict__ g3) {
    int aid = blockIdx.y;
    const int* g = (aid == 0) ? g0 : (aid == 1) ? g1 : (aid == 2) ? g2 : g3;
    int i = blockIdx.x * blockDim.x + threadIdx.x;
    if (i < EE) atomicAdd(&g_deg[aid][g[i]], 1);
}
// one block (1024 thr) per graph; smem-staged exclusive prefix sum
#define SCAN_SMEM (NN * 4)
__global__ void scan_kernel() {
    extern __shared__ int sd[];          // [NN]
    __shared__ int ssum[1024];
    int aid = blockIdx.x;
    int t = threadIdx.x;

    for (int i = t; i < NN; i += 1024) sd[i] = g_deg[aid][i];
    __syncthreads();

    const int CH = 20;                   // 1024*20 >= NN
    int base = t * CH;
    int loc[CH];
    int s = 0;
#pragma unroll
    for (int i = 0; i < CH; i++) {
        int idx = base + i;
        int v = (idx < NN) ? sd[idx] : 0;
        loc[i] = s; s += v;
    }
    ssum[t] = s;
    __syncthreads();
    for (int o = 1; o < 1024; o <<= 1) {
        int v = (t >= o) ? ssum[t - o] : 0;
        __syncthreads();
        ssum[t] += v;
        __syncthreads();
    }
    int offs = (t > 0) ? ssum[t - 1] : 0;
#pragma unroll
    for (int i = 0; i < CH; i++) {
        int idx = base + i;
        if (idx < NN) sd[idx] = offs + loc[i];
    }
    __syncthreads();
    for (int i = t; i < NN; i += 1024) g_off[aid][i] = sd[i];
    if (t == 1023) g_off[aid][NN] = ssum[1023];
}
__global__ void permute4(const int* __restrict__ g0, const int* __restrict__ g1,
                         const int* __restrict__ g2, const int* __restrict__ g3) {
    int aid = blockIdx.y;
    const int* g = (aid == 0) ? g0 : (aid == 1) ? g1 : (aid == 2) ? g2 : g3;
    int i = blockIdx.x * blockDim.x + threadIdx.x;
    if (i >= EE) return;
    int d = g[i];
    int p = g_off[aid][d] + atomicAdd(&g_pos[aid][d], 1);
    g_srcs[aid][p] = g[EE + i];
}

// ---------------- feat split (vectorized, both sets) ----------------
// src [NN,256] f32 -> dst [NP,768] bf16: [hi | hi | lo]; pad rows zero.
#define FSV (NP * 256 / 8)   // 8-elem groups per set
__global__ void split_feats(const float* __restrict__ feat1, const float* __restrict__ feat2,
                            __nv_bfloat16* __restrict__ d1, __nv_bfloat16* __restrict__ d2) {
    const float* src = blockIdx.y ? feat2 : feat1;
    __nv_bfloat16* dst = blockIdx.y ? d2 : d1;
    int i8 = blockIdx.x * blockDim.x + threadIdx.x;
    if (i8 >= FSV) return;
    int r = i8 >> 5;             // row (256/8 = 32 groups per row)
    int kk = (i8 & 31) << 3;     // elem offset within row
    float v[8];
    if (r < NN) {
        float4 x0 = *(const float4*)(src + (size_t)r * 256 + kk);
        float4 x1 = *(const float4*)(src + (size_t)r * 256 + kk + 4);
        v[0] = x0.x; v[1] = x0.y; v[2] = x0.z; v[3] = x0.w;
        v[4] = x1.x; v[5] = x1.y; v[6] = x1.z; v[7] = x1.w;
    } else {
#pragma unroll
        for (int j = 0; j < 8; j++) v[j] = 0.f;
    }
    __align__(16) __nv_bfloat16 h8[8], l8[8];
#pragma unroll
    for (int j = 0; j < 8; j++) {
        h8[j] = __float2bfloat16(v[j]);
        l8[j] = __float2bfloat16(v[j] - __bfloat162float(h8[j]));
    }
    uint4 uh = *(const uint4*)h8;
    uint4 ul = *(const uint4*)l8;
    size_t base = (size_t)r * 768 + kk;
    *(uint4*)(dst + base)       = uh;
    *(uint4*)(dst + base + 256) = uh;
    *(uint4*)(dst + base + 512) = ul;
}

// ---------------- weight transpose+split (all 4 weights, blockIdx.y) ----------------
// W [K,Nc] -> dst [Nc,3K]: [hi | lo | hi]
__global__ void transposeW4(const float* __restrict__ Wq1, const float* __restrict__ Wq2,
                            const float* __restrict__ Wp1, const float* __restrict__ Wp2,
                            __nv_bfloat16* __restrict__ o1, __nv_bfloat16* __restrict__ o2,
                            __nv_bfloat16* __restrict__ o3, __nv_bfloat16* __restrict__ o4) {
    int sel = blockIdx.y;
    const float* W = (sel == 0) ? Wq1 : (sel == 1) ? Wq2 : (sel == 2) ? Wp1 : Wp2;
    __nv_bfloat16* dst = (sel == 0) ? o1 : (sel == 1) ? o2 : (sel == 2) ? o3 : o4;
    int K  = (sel < 2) ? 256 : 512;
    int Nc = (sel < 2) ? 1536 : 256;
    int i = blockIdx.x * blockDim.x + threadIdx.x;
    if (i >= K * Nc) return;
    int k = i / Nc, n = i - k * Nc;
    float x = W[i];
    __nv_bfloat16 h = __float2bfloat16(x);
    __nv_bfloat16 l = __float2bfloat16(x - __bfloat162float(h));
    size_t base = (size_t)n * (3 * K) + k;
    dst[base]         = h;
    dst[base + K]     = l;
    dst[base + 2 * K] = h;
}

// ---------------- fused per-node attention (all 4 graphs, blockIdx.y) ----------------
__global__ __launch_bounds__(256)
void attn4(const float* __restrict__ qkv1, const float* __restrict__ qkv2,
           const float* __restrict__ coord1, const float* __restrict__ coord2,
           __nv_bfloat16* __restrict__ t1p, __nv_bfloat16* __restrict__ t2p) {
    int aid = blockIdx.y;
    const float *qkvQ, *qkvK, *qkvV, *coordD, *coordS;
    __nv_bfloat16* outp;
    int qoff, koff, voff, outoff, useRpe;
    switch (aid) {
        case 0: qkvQ = qkv1; qoff = 0;    qkvK = qkv1; koff = 256;  qkvV = qkv1; voff = 512;
                coordD = coord1; coordS = coord1; useRpe = 1; outp = t1p; outoff = 0;   break;
        case 1: qkvQ = qkv2; qoff = 768;  qkvK = qkv2; koff = 1024; qkvV = qkv2; voff = 1280;
                coordD = coord2; coordS = coord2; useRpe = 1; outp = t2p; outoff = 0;   break;
        case 2: qkvQ = qkv1; qoff = 768;  qkvK = qkv2; koff = 256;  qkvV = qkv2; voff = 512;
                coordD = nullptr; coordS = nullptr; useRpe = 0; outp = t1p; outoff = 256; break;
        default:qkvQ = qkv2; qoff = 0;    qkvK = qkv1; koff = 1024; qkvV = qkv1; voff = 1280;
                coordD = nullptr; coordS = nullptr; useRpe = 0; outp = t2p; outoff = 256; break;
    }

    int w = (blockIdx.x * blockDim.x + threadIdx.x) >> 5;
    if (w >= NN) return;
    int lane = threadIdx.x & 31;
    int h = lane >> 3;
    int dsub = (lane & 7) << 3;

    const float* qrow = qkvQ + (size_t)w * QW + qoff + h * 64 + dsub;
    float4 q0 = *(const float4*)(qrow);
    float4 q1 = *(const float4*)(qrow + 4);

    float r0 = 0.f, r1 = 0.f, r2 = 0.f, rb = 0.f, c0 = 0.f, c1 = 0.f, c2 = 0.f;
    if (useRpe) {
        r0 = g_rpe[h]; r1 = g_rpe[4 + h]; r2 = g_rpe[8 + h]; rb = g_rpe[12 + h];
        c0 = coordD[w * 3 + 0]; c1 = coordD[w * 3 + 1]; c2 = coordD[w * 3 + 2];
    }

    int s0 = g_off[aid][w], s1 = g_off[aid][w + 1];
    float a0 = 0.f, a1 = 0.f, a2 = 0.f, a3 = 0.f, a4 = 0.f, a5 = 0.f, a6 = 0.f, a7 = 0.f;
    float den = 0.f;

#pragma unroll 2
    for (int p = s0; p < s1; p++) {
        int src = g_srcs[aid][p];
        const float* krow = qkvK + (size_t)src * QW + koff + h * 64 + dsub;
        float4 k0 = *(const float4*)(krow);
        float4 k1 = *(const float4*)(krow + 4);
        const float* vrow = qkvV + (size_t)src * QW + voff + h * 64 + dsub;
        float4 v0 = *(const float4*)(vrow);
        float4 v1 = *(const float4*)(vrow + 4);
        float dot = q0.x * k0.x + q0.y * k0.y + q0.z * k0.z + q0.w * k0.w
                  + q1.x * k1.x + q1.y * k1.y + q1.z * k1.z + q1.w * k1.w;
        dot += __shfl_xor_sync(0xffffffffu, dot, 1);
        dot += __shfl_xor_sync(0xffffffffu, dot, 2);
        dot += __shfl_xor_sync(0xffffffffu, dot, 4);
        if (useRpe) {
            float d0 = c0 - coordS[src * 3 + 0];
            float d1 = c1 - coordS[src * 3 + 1];
            float d2 = c2 - coordS[src * 3 + 2];
            dot += d0 * r0 + d1 * r1 + d2 * r2 + rb;
        }
        float esc = __expf(dot);
        den += esc;
        a0 += esc * v0.x; a1 += esc * v0.y; a2 += esc * v0.z; a3 += esc * v0.w;
        a4 += esc * v1.x; a5 += esc * v1.y; a6 += esc * v1.z; a7 += esc * v1.w;
    }

    float inv = (den > 0.f) ? (1.f / den) : 0.f;
    float vals[8] = {a0 * inv, a1 * inv, a2 * inv, a3 * inv,
                     a4 * inv, a5 * inv, a6 * inv, a7 * inv};
    __align__(16) __nv_bfloat16 h8[8], l8[8];
#pragma unroll
    for (int j = 0; j < 8; j++) {
        h8[j] = __float2bfloat16(vals[j]);
        l8[j] = __float2bfloat16(vals[j] - __bfloat162float(h8[j]));
    }
    size_t rb_off = (size_t)w * 1536 + outoff + h * 64 + dsub;
    uint4 uh = *(const uint4*)h8;
    uint4 ul = *(const uint4*)l8;
    *(uint4*)(outp + rb_off)        = uh;
    *(uint4*)(outp + rb_off + 512)  = uh;
    *(uint4*)(outp + rb_off + 1024) = ul;
}

// ---------------- bf16 mma.sync GEMM (both sets via blockIdx.z) ----------------
#define GSMEM 65536

__global__ __launch_bounds__(256)
void gemm_bf16_mma2(const __nv_bfloat16* __restrict__ A0, const __nv_bfloat16* __restrict__ A1,
                    const __nv_bfloat16* __restrict__ B0, const __nv_bfloat16* __restrict__ B1,
                    const float* __restrict__ bias0, const float* __restrict__ bias1,
                    float* __restrict__ C0, float* __restrict__ C1,
                    int M, int Kp, int Nc) {
    const int z = blockIdx.z;
    const __nv_bfloat16* A = z ? A1 : A0;
    const __nv_bfloat16* B = z ? B1 : B0;
    const float* bias = z ? bias1 : bias0;
    float* C = z ? C1 : C0;

    extern __shared__ char smem[];
    const uint32_t sA_u = smem_u32(smem);
    const uint32_t sB_u = sA_u + 32768;

    const int t = threadIdx.x;
    const int wid = t >> 5, lane = t & 31;
    const int wm = wid & 1, wn = wid >> 1;
    const int m0 = blockIdx.y * 128, n0 = blockIdx.x * 128;

    float acc[4][4][4];
#pragma unroll
    for (int i = 0; i < 4; i++)
#pragma unroll
        for (int j = 0; j < 4; j++)
#pragma unroll
            for (int v = 0; v < 4; v++) acc[i][j][v] = 0.f;

    auto load_tiles = [&](int buf, int k0) {
#pragma unroll
        for (int i = 0; i < 4; i++) {
            int lin = i * 256 + t;
            int row = lin >> 3, ku = lin & 7;
            uint32_t b = (uint32_t)(row * 128 + ku * 16);
            b ^= (b >> 3) & 0x70;
            cp_async16(sA_u + buf * 16384 + b, A + (size_t)(m0 + row) * Kp + k0 + ku * 8);
            cp_async16(sB_u + buf * 16384 + b, B + (size_t)(n0 + row) * Kp + k0 + ku * 8);
        }
    };

    const int nk = Kp >> 6;
    load_tiles(0, 0);
    cp_commit();

    for (int kt = 0; kt < nk; kt++) {
        cp_wait0();
        __syncthreads();
        if (kt + 1 < nk) { load_tiles((kt + 1) & 1, (kt + 1) << 6); cp_commit(); }

        const uint32_t bufA = sA_u + (kt & 1) * 16384;
        const uint32_t bufB = sB_u + (kt & 1) * 16384;
#pragma unroll
        for (int kk = 0; kk < 4; kk++) {
            uint32_t afrag[4][4], bfrag[4][2];
            const int kseg = kk * 2 + (lane >> 4);
#pragma unroll
            for (int mt = 0; mt < 4; mt++) {
                int row = wm * 64 + mt * 16 + (lane & 15);
                uint32_t b = (uint32_t)(row * 128 + kseg * 16);
                b ^= (b >> 3) & 0x70;
                ldmatrix4(afrag[mt], bufA + b);
            }
#pragma unroll
            for (int nt2 = 0; nt2 < 2; nt2++) {
                int row = wn * 32 + nt2 * 16 + (lane & 7) + ((lane >> 3) & 1) * 8;
                uint32_t b = (uint32_t)(row * 128 + kseg * 16);
                b ^= (b >> 3) & 0x70;
                uint32_t r[4];
                ldmatrix4(r, bufB + b);
                bfrag[nt2 * 2][0]     = r[0]; bfrag[nt2 * 2][1]     = r[2];
                bfrag[nt2 * 2 + 1][0] = r[1]; bfrag[nt2 * 2 + 1][1] = r[3];
            }
#pragma unroll
            for (int mt = 0; mt < 4; mt++)
#pragma unroll
                for (int nt = 0; nt < 4; nt++)
                    mma16816(acc[mt][nt], afrag[mt], bfrag[nt]);
        }
        __syncthreads();
    }

#pragma unroll
    for (int mt = 0; mt < 4; mt++) {
        int rbase = m0 + wm * 64 + mt * 16 + (lane >> 2);
#pragma unroll
        for (int nt = 0; nt < 4; nt++) {
            int c = n0 + wn * 32 + nt * 8 + (lane & 3) * 2;
            float bx = bias[c], by = bias[c + 1];
            if (rbase < M) {
                float2 o = make_float2(acc[mt][nt][0] + bx, acc[mt][nt][1] + by);
                *(float2*)(C + (size_t)rbase * Nc + c) = o;
            }
            if (rbase + 8 < M) {
                float2 o = make_float2(acc[mt][nt][2] + bx, acc[mt][nt][3] + by);
                *(float2*)(C + (size_t)(rbase + 8) * Nc + c) = o;
            }
        }
    }
}

// ---------------- launch ----------------
extern "C" void kernel_launch(void* const* d_in, const int* in_sizes, int n_in,
                              void* d_out, int out_size) {
    const float* feat1  = (const float*)d_in[0];
    const float* coord1 = (const float*)d_in[1];
    const float* feat2  = (const float*)d_in[2];
    const float* coord2 = (const float*)d_in[3];
    const float* Wqkv1  = (const float*)d_in[4];
    const float* bqkv1  = (const float*)d_in[5];
    const float* Wqkv2  = (const float*)d_in[6];
    const float* bqkv2  = (const float*)d_in[7];
    const float* Wproj1 = (const float*)d_in[8];
    const float* bproj1 = (const float*)d_in[9];
    const float* Wproj2 = (const float*)d_in[10];
    const float* bproj2 = (const float*)d_in[11];
    const float* Wrpe   = (const float*)d_in[12];
    const float* brpe   = (const float*)d_in[13];
    const int* graph1   = (const int*)d_in[14];
    const int* graph2   = (const int*)d_in[15];
    const int* graph12  = (const int*)d_in[16];
    const int* graph21  = (const int*)d_in[17];
    float* out = (float*)d_out;

    float *qkv1, *qkv2;
    cudaGetSymbolAddress((void**)&qkv1, g_qkv1);
    cudaGetSymbolAddress((void**)&qkv2, g_qkv2);
    __nv_bfloat16 *f1p, *f2p, *t1p, *t2p, *w1p, *w2p, *p1p, *p2p;
    cudaGetSymbolAddress((void**)&f1p, g_f1p);
    cudaGetSymbolAddress((void**)&f2p, g_f2p);
    cudaGetSymbolAddress((void**)&t1p, g_t1p);
    cudaGetSymbolAddress((void**)&t2p, g_t2p);
    cudaGetSymbolAddress((void**)&w1p, g_w1p);
    cudaGetSymbolAddress((void**)&w2p, g_w2p);
    cudaGetSymbolAddress((void**)&p1p, g_p1p);
    cudaGetSymbolAddress((void**)&p2p, g_p2p);

    cudaFuncSetAttribute(gemm_bf16_mma2, cudaFuncAttributeMaxDynamicSharedMemorySize, GSMEM);
    cudaFuncSetAttribute(scan_kernel, cudaFuncAttributeMaxDynamicSharedMemorySize, SCAN_SMEM);

    // 1. prep: rpe + zero counters + zero t-buffer pads
    prep_all<<<128, 256>>>(Wrpe, brpe);

    // 2-4. CSR build
    const int EBLK = (EE + 255) / 256;
    dim3 gcnt(EBLK, 4);
    count4<<<gcnt, 256>>>(graph1, graph2, graph21, graph12);
    scan_kernel<<<4, 1024, SCAN_SMEM>>>();
    permute4<<<gcnt, 256>>>(graph1, graph2, graph21, graph12);

    // 5. feat split (both sets)
    dim3 gfs((FSV + 255) / 256, 2);
    split_feats<<<gfs, 256>>>(feat1, feat2, f1p, f2p);

    // 6. weight transposes (all 4)
    dim3 gtw((256 * 1536 + 255) / 256, 4);
    transposeW4<<<gtw, 256>>>(Wqkv1, Wqkv2, Wproj1, Wproj2, w1p, w2p, p1p, p2p);

    // 7. QKV GEMMs (both sets): [20096,768] @ [1536,768]^T
    dim3 gq(QW / 128, NP / 128, 2);
    gemm_bf16_mma2<<<gq, 256, GSMEM>>>(f1p, f2p, w1p, w2p, bqkv1, bqkv2, qkv1, qkv2,
                                       NN, 768, QW);

    // 8. all 4 attentions -> split bf16 into t1p/t2p
    dim3 ga((NN * 32 + 255) / 256, 4);
    attn4<<<ga, 256>>>(qkv1, qkv2, coord1, coord2, t1p, t2p);

    // 9. output projections (both sets): [20096,1536] @ [256,1536]^T
    dim3 gp(256 / 128, NP / 128, 2);
    gemm_bf16_mma2<<<gp, 256, GSMEM>>>(t1p, t2p, p1p, p2p, bproj1, bproj2,
                                       out, out + (size_t)NN * 256, NN, 1536, 256);
}

// round 10
// speedup vs baseline: 2.5422x; 1.0278x over previous
#include <cuda_runtime.h>
#include <cuda_bf16.h>
#include <math.h>
#include <stdint.h>

#define NN 20000
#define EE 320000
#define HH 4
#define QW 1536   // 6*C
#define AW 512    // 2*C
#define NP 20096  // 157 * 128 (padded M)

// ---------------- scratch (static device globals) ----------------
__device__ __align__(16) float g_qkv1[NN * QW];
__device__ __align__(16) float g_qkv2[NN * QW];
__device__ float g_rpe[16];

// CSR per graph
__device__ int g_deg[4][NN];
__device__ int g_off[4][NN + 1];
__device__ int g_eidx[4][EE];    // per-edge insertion index (from count pass)
__device__ int g_srcs[4][EE];

// interleaved 3-term-split bf16 operands:
//   A' rows: [hi(K) | hi(K) | lo(K)]   B' rows: [hi(K) | lo(K) | hi(K)]
__device__ __align__(16) __nv_bfloat16 g_f1p[NP * 768];
__device__ __align__(16) __nv_bfloat16 g_f2p[NP * 768];
__device__ __align__(16) __nv_bfloat16 g_t1p[NP * 1536];
__device__ __align__(16) __nv_bfloat16 g_t2p[NP * 1536];
__device__ __align__(16) __nv_bfloat16 g_w1p[1536 * 768];
__device__ __align__(16) __nv_bfloat16 g_w2p[1536 * 768];
__device__ __align__(16) __nv_bfloat16 g_p1p[256 * 1536];
__device__ __align__(16) __nv_bfloat16 g_p2p[256 * 1536];

// ---------------- helpers ----------------
__device__ __forceinline__ uint32_t smem_u32(const void* p) {
    uint32_t a;
    asm("{ .reg .u64 t; cvta.to.shared.u64 t, %1; cvt.u32.u64 %0, t; }" : "=r"(a) : "l"(p));
    return a;
}
__device__ __forceinline__ void cp_async16(uint32_t dst, const void* src) {
    asm volatile("cp.async.cg.shared.global [%0], [%1], 16;" :: "r"(dst), "l"(src));
}
__device__ __forceinline__ void cp_commit() {
    asm volatile("cp.async.commit_group;" ::: "memory");
}
__device__ __forceinline__ void cp_wait0() {
    asm volatile("cp.async.wait_group 0;" ::: "memory");
}
__device__ __forceinline__ void ldmatrix4(uint32_t* r, uint32_t addr) {
    asm volatile("ldmatrix.sync.aligned.m8n8.x4.shared.b16 {%0,%1,%2,%3}, [%4];"
                 : "=r"(r[0]), "=r"(r[1]), "=r"(r[2]), "=r"(r[3]) : "r"(addr));
}
__device__ __forceinline__ void mma16816(float* c, const uint32_t* a, const uint32_t* b) {
    asm volatile("mma.sync.aligned.m16n8k16.row.col.f32.bf16.bf16.f32 "
                 "{%0,%1,%2,%3}, {%4,%5,%6,%7}, {%8,%9}, {%0,%1,%2,%3};"
                 : "+f"(c[0]), "+f"(c[1]), "+f"(c[2]), "+f"(c[3])
                 : "r"(a[0]), "r"(a[1]), "r"(a[2]), "r"(a[3]), "r"(b[0]), "r"(b[1]));
}

// ---------------- prep: rpe + zero CSR counters + zero t-buffer pad rows ----------------
#define TPAD ((NP - NN) * 1536)
#define TPADV (TPAD / 8)
__global__ void prep_all(const float* __restrict__ Wrpe, const float* __restrict__ brpe) {
    int gid = blockIdx.x * blockDim.x + threadIdx.x;
    int stride = gridDim.x * blockDim.x;

    if (blockIdx.x == 0 && threadIdx.x < HH) {
        int h = threadIdx.x;
        for (int p = 0; p < 3; p++) {
            float s = 0.f;
            for (int d = 0; d < 64; d++) s += Wrpe[p * 256 + h * 64 + d];
            g_rpe[p * HH + h] = s;
        }
        float b = 0.f;
        for (int d = 0; d < 64; d++) b += brpe[h * 64 + d];
        g_rpe[12 + h] = b;
    }

    int* d = &g_deg[0][0];
    for (int j = gid; j < 4 * NN; j += stride) d[j] = 0;

    uint4 zz = make_uint4(0, 0, 0, 0);
    uint4* t1 = (uint4*)(&g_t1p[(size_t)NN * 1536]);
    uint4* t2 = (uint4*)(&g_t2p[(size_t)NN * 1536]);
    for (int j = gid; j < TPADV; j += stride) { t1[j] = zz; t2[j] = zz; }
}

// ---------------- CSR build ----------------
__global__ void count4(const int* __restrict__ g0, const int* __restrict__ g1,
                       const int* __restrict__ g2, const int* __restrict__ g3) {
    int aid = blockIdx.y;
    const int* g = (aid == 0) ? g0 : (aid == 1) ? g1 : (aid == 2) ? g2 : g3;
    int i = blockIdx.x * blockDim.x + threadIdx.x;
    if (i < EE) g_eidx[aid][i] = atomicAdd(&g_deg[aid][g[i]], 1);
}
// one block (1024 thr) per graph; smem-staged exclusive prefix sum
#define SCAN_SMEM (NN * 4)
__global__ void scan_kernel() {
    extern __shared__ int sd[];
    __shared__ int ssum[1024];
    int aid = blockIdx.x;
    int t = threadIdx.x;

    for (int i = t; i < NN; i += 1024) sd[i] = g_deg[aid][i];
    __syncthreads();

    const int CH = 20;
    int base = t * CH;
    int loc[CH];
    int s = 0;
#pragma unroll
    for (int i = 0; i < CH; i++) {
        int idx = base + i;
        int v = (idx < NN) ? sd[idx] : 0;
        loc[i] = s; s += v;
    }
    ssum[t] = s;
    __syncthreads();
    for (int o = 1; o < 1024; o <<= 1) {
        int v = (t >= o) ? ssum[t - o] : 0;
        __syncthreads();
        ssum[t] += v;
        __syncthreads();
    }
    int offs = (t > 0) ? ssum[t - 1] : 0;
#pragma unroll
    for (int i = 0; i < CH; i++) {
        int idx = base + i;
        if (idx < NN) sd[idx] = offs + loc[i];
    }
    __syncthreads();
    for (int i = t; i < NN; i += 1024) g_off[aid][i] = sd[i];
    if (t == 1023) g_off[aid][NN] = ssum[1023];
}
__global__ void permute4(const int* __restrict__ g0, const int* __restrict__ g1,
                         const int* __restrict__ g2, const int* __restrict__ g3) {
    int aid = blockIdx.y;
    const int* g = (aid == 0) ? g0 : (aid == 1) ? g1 : (aid == 2) ? g2 : g3;
    int i = blockIdx.x * blockDim.x + threadIdx.x;
    if (i >= EE) return;
    int d = g[i];
    int p = g_off[aid][d] + g_eidx[aid][i];
    g_srcs[aid][p] = g[EE + i];
}

// ---------------- feat split (vectorized, both sets) ----------------
#define FSV (NP * 256 / 8)
__global__ void split_feats(const float* __restrict__ feat1, const float* __restrict__ feat2,
                            __nv_bfloat16* __restrict__ d1, __nv_bfloat16* __restrict__ d2) {
    const float* src = blockIdx.y ? feat2 : feat1;
    __nv_bfloat16* dst = blockIdx.y ? d2 : d1;
    int i8 = blockIdx.x * blockDim.x + threadIdx.x;
    if (i8 >= FSV) return;
    int r = i8 >> 5;
    int kk = (i8 & 31) << 3;
    float v[8];
    if (r < NN) {
        float4 x0 = *(const float4*)(src + (size_t)r * 256 + kk);
        float4 x1 = *(const float4*)(src + (size_t)r * 256 + kk + 4);
        v[0] = x0.x; v[1] = x0.y; v[2] = x0.z; v[3] = x0.w;
        v[4] = x1.x; v[5] = x1.y; v[6] = x1.z; v[7] = x1.w;
    } else {
#pragma unroll
        for (int j = 0; j < 8; j++) v[j] = 0.f;
    }
    __align__(16) __nv_bfloat16 h8[8], l8[8];
#pragma unroll
    for (int j = 0; j < 8; j++) {
        h8[j] = __float2bfloat16(v[j]);
        l8[j] = __float2bfloat16(v[j] - __bfloat162float(h8[j]));
    }
    uint4 uh = *(const uint4*)h8;
    uint4 ul = *(const uint4*)l8;
    size_t base = (size_t)r * 768 + kk;
    *(uint4*)(dst + base)       = uh;
    *(uint4*)(dst + base + 256) = uh;
    *(uint4*)(dst + base + 512) = ul;
}

// ---------------- weight transpose+split: W [K,Nc] -> dst [Nc,3K] [hi|lo|hi] ----------------
__global__ void transposeW2(const float* __restrict__ Wa, const float* __restrict__ Wb,
                            __nv_bfloat16* __restrict__ oa, __nv_bfloat16* __restrict__ ob,
                            int K, int Nc) {
    const float* W = blockIdx.y ? Wb : Wa;
    __nv_bfloat16* dst = blockIdx.y ? ob : oa;
    int i = blockIdx.x * blockDim.x + threadIdx.x;
    if (i >= K * Nc) return;
    int k = i / Nc, n = i - k * Nc;
    float x = W[i];
    __nv_bfloat16 h = __float2bfloat16(x);
    __nv_bfloat16 l = __float2bfloat16(x - __bfloat162float(h));
    size_t base = (size_t)n * (3 * K) + k;
    dst[base]         = h;
    dst[base + K]     = l;
    dst[base + 2 * K] = h;
}

// ---------------- fused per-node attention (all 4 graphs, blockIdx.y) ----------------
__global__ __launch_bounds__(256)
void attn4(const float* __restrict__ qkv1, const float* __restrict__ qkv2,
           const float* __restrict__ coord1, const float* __restrict__ coord2,
           __nv_bfloat16* __restrict__ t1p, __nv_bfloat16* __restrict__ t2p) {
    int aid = blockIdx.y;
    const float *qkvQ, *qkvK, *qkvV, *coordD, *coordS;
    __nv_bfloat16* outp;
    int qoff, koff, voff, outoff, useRpe;
    switch (aid) {
        case 0: qkvQ = qkv1; qoff = 0;    qkvK = qkv1; koff = 256;  qkvV = qkv1; voff = 512;
                coordD = coord1; coordS = coord1; useRpe = 1; outp = t1p; outoff = 0;   break;
        case 1: qkvQ = qkv2; qoff = 768;  qkvK = qkv2; koff = 1024; qkvV = qkv2; voff = 1280;
                coordD = coord2; coordS = coord2; useRpe = 1; outp = t2p; outoff = 0;   break;
        case 2: qkvQ = qkv1; qoff = 768;  qkvK = qkv2; koff = 256;  qkvV = qkv2; voff = 512;
                coordD = nullptr; coordS = nullptr; useRpe = 0; outp = t1p; outoff = 256; break;
        default:qkvQ = qkv2; qoff = 0;    qkvK = qkv1; koff = 1024; qkvV = qkv1; voff = 1280;
                coordD = nullptr; coordS = nullptr; useRpe = 0; outp = t2p; outoff = 256; break;
    }

    int w = (blockIdx.x * blockDim.x + threadIdx.x) >> 5;
    if (w >= NN) return;
    int lane = threadIdx.x & 31;
    int h = lane >> 3;
    int dsub = (lane & 7) << 3;

    const float* qrow = qkvQ + (size_t)w * QW + qoff + h * 64 + dsub;
    float4 q0 = *(const float4*)(qrow);
    float4 q1 = *(const float4*)(qrow + 4);

    float r0 = 0.f, r1 = 0.f, r2 = 0.f, rb = 0.f, c0 = 0.f, c1 = 0.f, c2 = 0.f;
    if (useRpe) {
        r0 = g_rpe[h]; r1 = g_rpe[4 + h]; r2 = g_rpe[8 + h]; rb = g_rpe[12 + h];
        c0 = coordD[w * 3 + 0]; c1 = coordD[w * 3 + 1]; c2 = coordD[w * 3 + 2];
    }

    int s0 = g_off[aid][w], s1 = g_off[aid][w + 1];
    float a0 = 0.f, a1 = 0.f, a2 = 0.f, a3 = 0.f, a4 = 0.f, a5 = 0.f, a6 = 0.f, a7 = 0.f;
    float den = 0.f;

#pragma unroll 2
    for (int p = s0; p < s1; p++) {
        int src = g_srcs[aid][p];
        const float* krow = qkvK + (size_t)src * QW + koff + h * 64 + dsub;
        float4 k0 = *(const float4*)(krow);
        float4 k1 = *(const float4*)(krow + 4);
        const float* vrow = qkvV + (size_t)src * QW + voff + h * 64 + dsub;
        float4 v0 = *(const float4*)(vrow);
        float4 v1 = *(const float4*)(vrow + 4);
        float dot = q0.x * k0.x + q0.y * k0.y + q0.z * k0.z + q0.w * k0.w
                  + q1.x * k1.x + q1.y * k1.y + q1.z * k1.z + q1.w * k1.w;
        dot += __shfl_xor_sync(0xffffffffu, dot, 1);
        dot += __shfl_xor_sync(0xffffffffu, dot, 2);
        dot += __shfl_xor_sync(0xffffffffu, dot, 4);
        if (useRpe) {
            float d0 = c0 - coordS[src * 3 + 0];
            float d1 = c1 - coordS[src * 3 + 1];
            float d2 = c2 - coordS[src * 3 + 2];
            dot += d0 * r0 + d1 * r1 + d2 * r2 + rb;
        }
        float esc = __expf(dot);
        den += esc;
        a0 += esc * v0.x; a1 += esc * v0.y; a2 += esc * v0.z; a3 += esc * v0.w;
        a4 += esc * v1.x; a5 += esc * v1.y; a6 += esc * v1.z; a7 += esc * v1.w;
    }

    float inv = (den > 0.f) ? (1.f / den) : 0.f;
    float vals[8] = {a0 * inv, a1 * inv, a2 * inv, a3 * inv,
                     a4 * inv, a5 * inv, a6 * inv, a7 * inv};
    __align__(16) __nv_bfloat16 h8[8], l8[8];
#pragma unroll
    for (int j = 0; j < 8; j++) {
        h8[j] = __float2bfloat16(vals[j]);
        l8[j] = __float2bfloat16(vals[j] - __bfloat162float(h8[j]));
    }
    size_t rb_off = (size_t)w * 1536 + outoff + h * 64 + dsub;
    uint4 uh = *(const uint4*)h8;
    uint4 ul = *(const uint4*)l8;
    *(uint4*)(outp + rb_off)        = uh;
    *(uint4*)(outp + rb_off + 512)  = uh;
    *(uint4*)(outp + rb_off + 1024) = ul;
}

// ---------------- bf16 mma.sync GEMM (both sets via blockIdx.z) ----------------
#define GSMEM 65536

__global__ __launch_bounds__(256)
void gemm_bf16_mma2(const __nv_bfloat16* __restrict__ A0, const __nv_bfloat16* __restrict__ A1,
                    const __nv_bfloat16* __restrict__ B0, const __nv_bfloat16* __restrict__ B1,
                    const float* __restrict__ bias0, const float* __restrict__ bias1,
                    float* __restrict__ C0, float* __restrict__ C1,
                    int M, int Kp, int Nc) {
    const int z = blockIdx.z;
    const __nv_bfloat16* A = z ? A1 : A0;
    const __nv_bfloat16* B = z ? B1 : B0;
    const float* bias = z ? bias1 : bias0;
    float* C = z ? C1 : C0;

    extern __shared__ char smem[];
    const uint32_t sA_u = smem_u32(smem);
    const uint32_t sB_u = sA_u + 32768;

    const int t = threadIdx.x;
    const int wid = t >> 5, lane = t & 31;
    const int wm = wid & 1, wn = wid >> 1;
    const int m0 = blockIdx.y * 128, n0 = blockIdx.x * 128;

    float acc[4][4][4];
#pragma unroll
    for (int i = 0; i < 4; i++)
#pragma unroll
        for (int j = 0; j < 4; j++)
#pragma unroll
            for (int v = 0; v < 4; v++) acc[i][j][v] = 0.f;

    auto load_tiles = [&](int buf, int k0) {
#pragma unroll
        for (int i = 0; i < 4; i++) {
            int lin = i * 256 + t;
            int row = lin >> 3, ku = lin & 7;
            uint32_t b = (uint32_t)(row * 128 + ku * 16);
            b ^= (b >> 3) & 0x70;
            cp_async16(sA_u + buf * 16384 + b, A + (size_t)(m0 + row) * Kp + k0 + ku * 8);
            cp_async16(sB_u + buf * 16384 + b, B + (size_t)(n0 + row) * Kp + k0 + ku * 8);
        }
    };

    const int nk = Kp >> 6;
    load_tiles(0, 0);
    cp_commit();

    for (int kt = 0; kt < nk; kt++) {
        cp_wait0();
        __syncthreads();
        if (kt + 1 < nk) { load_tiles((kt + 1) & 1, (kt + 1) << 6); cp_commit(); }

        const uint32_t bufA = sA_u + (kt & 1) * 16384;
        const uint32_t bufB = sB_u + (kt & 1) * 16384;
#pragma unroll
        for (int kk = 0; kk < 4; kk++) {
            uint32_t afrag[4][4], bfrag[4][2];
            const int kseg = kk * 2 + (lane >> 4);
#pragma unroll
            for (int mt = 0; mt < 4; mt++) {
                int row = wm * 64 + mt * 16 + (lane & 15);
                uint32_t b = (uint32_t)(row * 128 + kseg * 16);
                b ^= (b >> 3) & 0x70;
                ldmatrix4(afrag[mt], bufA + b);
            }
#pragma unroll
            for (int nt2 = 0; nt2 < 2; nt2++) {
                int row = wn * 32 + nt2 * 16 + (lane & 7) + ((lane >> 3) & 1) * 8;
                uint32_t b = (uint32_t)(row * 128 + kseg * 16);
                b ^= (b >> 3) & 0x70;
                uint32_t r[4];
                ldmatrix4(r, bufB + b);
                bfrag[nt2 * 2][0]     = r[0]; bfrag[nt2 * 2][1]     = r[2];
                bfrag[nt2 * 2 + 1][0] = r[1]; bfrag[nt2 * 2 + 1][1] = r[3];
            }
#pragma unroll
            for (int mt = 0; mt < 4; mt++)
#pragma unroll
                for (int nt = 0; nt < 4; nt++)
                    mma16816(acc[mt][nt], afrag[mt], bfrag[nt]);
        }
        __syncthreads();
    }

#pragma unroll
    for (int mt = 0; mt < 4; mt++) {
        int rbase = m0 + wm * 64 + mt * 16 + (lane >> 2);
#pragma unroll
        for (int nt = 0; nt < 4; nt++) {
            int c = n0 + wn * 32 + nt * 8 + (lane & 3) * 2;
            float bx = bias[c], by = bias[c + 1];
            if (rbase < M) {
                float2 o = make_float2(acc[mt][nt][0] + bx, acc[mt][nt][1] + by);
                *(float2*)(C + (size_t)rbase * Nc + c) = o;
            }
            if (rbase + 8 < M) {
                float2 o = make_float2(acc[mt][nt][2] + bx, acc[mt][nt][3] + by);
                *(float2*)(C + (size_t)(rbase + 8) * Nc + c) = o;
            }
        }
    }
}

// ---------------- launch ----------------
extern "C" void kernel_launch(void* const* d_in, const int* in_sizes, int n_in,
                              void* d_out, int out_size) {
    const float* feat1  = (const float*)d_in[0];
    const float* coord1 = (const float*)d_in[1];
    const float* feat2  = (const float*)d_in[2];
    const float* coord2 = (const float*)d_in[3];
    const float* Wqkv1  = (const float*)d_in[4];
    const float* bqkv1  = (const float*)d_in[5];
    const float* Wqkv2  = (const float*)d_in[6];
    const float* bqkv2  = (const float*)d_in[7];
    const float* Wproj1 = (const float*)d_in[8];
    const float* bproj1 = (const float*)d_in[9];
    const float* Wproj2 = (const float*)d_in[10];
    const float* bproj2 = (const float*)d_in[11];
    const float* Wrpe   = (const float*)d_in[12];
    const float* brpe   = (const float*)d_in[13];
    const int* graph1   = (const int*)d_in[14];
    const int* graph2   = (const int*)d_in[15];
    const int* graph12  = (const int*)d_in[16];
    const int* graph21  = (const int*)d_in[17];
    float* out = (float*)d_out;

    float *qkv1, *qkv2;
    cudaGetSymbolAddress((void**)&qkv1, g_qkv1);
    cudaGetSymbolAddress((void**)&qkv2, g_qkv2);
    __nv_bfloat16 *f1p, *f2p, *t1p, *t2p, *w1p, *w2p, *p1p, *p2p;
    cudaGetSymbolAddress((void**)&f1p, g_f1p);
    cudaGetSymbolAddress((void**)&f2p, g_f2p);
    cudaGetSymbolAddress((void**)&t1p, g_t1p);
    cudaGetSymbolAddress((void**)&t2p, g_t2p);
    cudaGetSymbolAddress((void**)&w1p, g_w1p);
    cudaGetSymbolAddress((void**)&w2p, g_w2p);
    cudaGetSymbolAddress((void**)&p1p, g_p1p);
    cudaGetSymbolAddress((void**)&p2p, g_p2p);

    // lazily created host objects (first call = uncaptured correctness run)
    static cudaStream_t s1 = nullptr;
    static cudaEvent_t evFork = nullptr, evJoin = nullptr;
    static bool inited = false;
    if (!inited) {
        cudaStreamCreateWithFlags(&s1, cudaStreamNonBlocking);
        cudaEventCreateWithFlags(&evFork, cudaEventDisableTiming);
        cudaEventCreateWithFlags(&evJoin, cudaEventDisableTiming);
        cudaFuncSetAttribute(gemm_bf16_mma2, cudaFuncAttributeMaxDynamicSharedMemorySize, GSMEM);
        cudaFuncSetAttribute(scan_kernel, cudaFuncAttributeMaxDynamicSharedMemorySize, SCAN_SMEM);
        inited = true;
    }

    // s0 (default stream): prep (zeroes counters used by s1)
    prep_all<<<128, 256>>>(Wrpe, brpe);

    // fork s1: CSR build + proj-weight transpose, concurrent with GEMM path
    cudaEventRecord(evFork, 0);
    cudaStreamWaitEvent(s1, evFork, 0);

    const int EBLK = (EE + 255) / 256;
    dim3 gcnt(EBLK, 4);
    count4<<<gcnt, 256, 0, s1>>>(graph1, graph2, graph21, graph12);
    scan_kernel<<<4, 1024, SCAN_SMEM, s1>>>();
    permute4<<<gcnt, 256, 0, s1>>>(graph1, graph2, graph21, graph12);
    dim3 gtp((512 * 256 + 255) / 256, 2);
    transposeW2<<<gtp, 256, 0, s1>>>(Wproj1, Wproj2, p1p, p2p, 512, 256);
    cudaEventRecord(evJoin, s1);

    // s0: feat split + qkv weight transpose + QKV GEMMs
    dim3 gfs((FSV + 255) / 256, 2);
    split_feats<<<gfs, 256>>>(feat1, feat2, f1p, f2p);
    dim3 gtw((256 * 1536 + 255) / 256, 2);
    transposeW2<<<gtw, 256>>>(Wqkv1, Wqkv2, w1p, w2p, 256, 1536);

    dim3 gq(QW / 128, NP / 128, 2);
    gemm_bf16_mma2<<<gq, 256, GSMEM>>>(f1p, f2p, w1p, w2p, bqkv1, bqkv2, qkv1, qkv2,
                                       NN, 768, QW);

    // join: attn needs CSR + QKV
    cudaStreamWaitEvent(0, evJoin, 0);

    dim3 ga((NN * 32 + 255) / 256, 4);
    attn4<<<ga, 256>>>(qkv1, qkv2, coord1, coord2, t1p, t2p);

    dim3 gp(256 / 128, NP / 128, 2);
    gemm_bf16_mma2<<<gp, 256, GSMEM>>>(t1p, t2p, p1p, p2p, bproj1, bproj2,
                                       out, out + (size_t)NN * 256, NN, 1536, 256);
}

// round 11
// speedup vs baseline: 2.7434x; 1.0792x over previous
#include <cuda_runtime.h>
#include <cuda_bf16.h>
#include <cuda_fp16.h>
#include <math.h>
#include <stdint.h>

#define NN 20000
#define EE 320000
#define HH 4
#define QW 1536   // 6*C
#define NP 20096  // 157 * 128 (padded M)

// ---------------- scratch (static device globals) ----------------
__device__ __align__(16) float g_qkv1[NN * QW];   // only q_a / q_b sections written
__device__ __align__(16) float g_qkv2[NN * QW];
// fp16 attention operands, row = [k_a(0) | v_a(256) | k_b(512) | v_b(768)]
__device__ __align__(16) __half g_kv1[NN * 1024];
__device__ __align__(16) __half g_kv2[NN * 1024];
__device__ float g_rpe[16];

// CSR per graph
__device__ int g_deg[4][NN];
__device__ int g_off[4][NN + 1];
__device__ int g_eidx[4][EE];
__device__ int g_srcs[4][EE];

// interleaved 3-term-split bf16 operands
__device__ __align__(16) __nv_bfloat16 g_f1p[NP * 768];
__device__ __align__(16) __nv_bfloat16 g_f2p[NP * 768];
__device__ __align__(16) __nv_bfloat16 g_t1p[NP * 1536];
__device__ __align__(16) __nv_bfloat16 g_t2p[NP * 1536];
__device__ __align__(16) __nv_bfloat16 g_w1p[1536 * 768];
__device__ __align__(16) __nv_bfloat16 g_w2p[1536 * 768];
__device__ __align__(16) __nv_bfloat16 g_p1p[256 * 1536];
__device__ __align__(16) __nv_bfloat16 g_p2p[256 * 1536];

// ---------------- helpers ----------------
__device__ __forceinline__ uint32_t smem_u32(const void* p) {
    uint32_t a;
    asm("{ .reg .u64 t; cvta.to.shared.u64 t, %1; cvt.u32.u64 %0, t; }" : "=r"(a) : "l"(p));
    return a;
}
__device__ __forceinline__ void cp_async16(uint32_t dst, const void* src) {
    asm volatile("cp.async.cg.shared.global [%0], [%1], 16;" :: "r"(dst), "l"(src));
}
__device__ __forceinline__ void cp_commit() {
    asm volatile("cp.async.commit_group;" ::: "memory");
}
__device__ __forceinline__ void cp_wait0() {
    asm volatile("cp.async.wait_group 0;" ::: "memory");
}
__device__ __forceinline__ void ldmatrix4(uint32_t* r, uint32_t addr) {
    asm volatile("ldmatrix.sync.aligned.m8n8.x4.shared.b16 {%0,%1,%2,%3}, [%4];"
                 : "=r"(r[0]), "=r"(r[1]), "=r"(r[2]), "=r"(r[3]) : "r"(addr));
}
__device__ __forceinline__ void mma16816(float* c, const uint32_t* a, const uint32_t* b) {
    asm volatile("mma.sync.aligned.m16n8k16.row.col.f32.bf16.bf16.f32 "
                 "{%0,%1,%2,%3}, {%4,%5,%6,%7}, {%8,%9}, {%0,%1,%2,%3};"
                 : "+f"(c[0]), "+f"(c[1]), "+f"(c[2]), "+f"(c[3])
                 : "r"(a[0]), "r"(a[1]), "r"(a[2]), "r"(a[3]), "r"(b[0]), "r"(b[1]));
}

// ---------------- prep: rpe + zero CSR counters + zero t-buffer pad rows ----------------
#define TPAD ((NP - NN) * 1536)
#define TPADV (TPAD / 8)
__global__ void prep_all(const float* __restrict__ Wrpe, const float* __restrict__ brpe) {
    int gid = blockIdx.x * blockDim.x + threadIdx.x;
    int stride = gridDim.x * blockDim.x;

    if (blockIdx.x == 0 && threadIdx.x < HH) {
        int h = threadIdx.x;
        for (int p = 0; p < 3; p++) {
            float s = 0.f;
            for (int d = 0; d < 64; d++) s += Wrpe[p * 256 + h * 64 + d];
            g_rpe[p * HH + h] = s;
        }
        float b = 0.f;
        for (int d = 0; d < 64; d++) b += brpe[h * 64 + d];
        g_rpe[12 + h] = b;
    }

    int* d = &g_deg[0][0];
    for (int j = gid; j < 4 * NN; j += stride) d[j] = 0;

    uint4 zz = make_uint4(0, 0, 0, 0);
    uint4* t1 = (uint4*)(&g_t1p[(size_t)NN * 1536]);
    uint4* t2 = (uint4*)(&g_t2p[(size_t)NN * 1536]);
    for (int j = gid; j < TPADV; j += stride) { t1[j] = zz; t2[j] = zz; }
}

// ---------------- CSR build ----------------
__global__ void count4(const int* __restrict__ g0, const int* __restrict__ g1,
                       const int* __restrict__ g2, const int* __restrict__ g3) {
    int aid = blockIdx.y;
    const int* g = (aid == 0) ? g0 : (aid == 1) ? g1 : (aid == 2) ? g2 : g3;
    int i = blockIdx.x * blockDim.x + threadIdx.x;
    if (i < EE) g_eidx[aid][i] = atomicAdd(&g_deg[aid][g[i]], 1);
}
#define SCAN_SMEM (NN * 4)
__global__ void scan_kernel() {
    extern __shared__ int sd[];
    __shared__ int ssum[1024];
    int aid = blockIdx.x;
    int t = threadIdx.x;

    for (int i = t; i < NN; i += 1024) sd[i] = g_deg[aid][i];
    __syncthreads();

    const int CH = 20;
    int base = t * CH;
    int loc[CH];
    int s = 0;
#pragma unroll
    for (int i = 0; i < CH; i++) {
        int idx = base + i;
        int v = (idx < NN) ? sd[idx] : 0;
        loc[i] = s; s += v;
    }
    ssum[t] = s;
    __syncthreads();
    for (int o = 1; o < 1024; o <<= 1) {
        int v = (t >= o) ? ssum[t - o] : 0;
        __syncthreads();
        ssum[t] += v;
        __syncthreads();
    }
    int offs = (t > 0) ? ssum[t - 1] : 0;
#pragma unroll
    for (int i = 0; i < CH; i++) {
        int idx = base + i;
        if (idx < NN) sd[idx] = offs + loc[i];
    }
    __syncthreads();
    for (int i = t; i < NN; i += 1024) g_off[aid][i] = sd[i];
    if (t == 1023) g_off[aid][NN] = ssum[1023];
}
__global__ void permute4(const int* __restrict__ g0, const int* __restrict__ g1,
                         const int* __restrict__ g2, const int* __restrict__ g3) {
    int aid = blockIdx.y;
    const int* g = (aid == 0) ? g0 : (aid == 1) ? g1 : (aid == 2) ? g2 : g3;
    int i = blockIdx.x * blockDim.x + threadIdx.x;
    if (i >= EE) return;
    int d = g[i];
    int p = g_off[aid][d] + g_eidx[aid][i];
    g_srcs[aid][p] = g[EE + i];
}

// ---------------- feat split (vectorized, both sets) ----------------
#define FSV (NP * 256 / 8)
__global__ void split_feats(const float* __restrict__ feat1, const float* __restrict__ feat2,
                            __nv_bfloat16* __restrict__ d1, __nv_bfloat16* __restrict__ d2) {
    const float* src = blockIdx.y ? feat2 : feat1;
    __nv_bfloat16* dst = blockIdx.y ? d2 : d1;
    int i8 = blockIdx.x * blockDim.x + threadIdx.x;
    if (i8 >= FSV) return;
    int r = i8 >> 5;
    int kk = (i8 & 31) << 3;
    float v[8];
    if (r < NN) {
        float4 x0 = *(const float4*)(src + (size_t)r * 256 + kk);
        float4 x1 = *(const float4*)(src + (size_t)r * 256 + kk + 4);
        v[0] = x0.x; v[1] = x0.y; v[2] = x0.z; v[3] = x0.w;
        v[4] = x1.x; v[5] = x1.y; v[6] = x1.z; v[7] = x1.w;
    } else {
#pragma unroll
        for (int j = 0; j < 8; j++) v[j] = 0.f;
    }
    __align__(16) __nv_bfloat16 h8[8], l8[8];
#pragma unroll
    for (int j = 0; j < 8; j++) {
        h8[j] = __float2bfloat16(v[j]);
        l8[j] = __float2bfloat16(v[j] - __bfloat162float(h8[j]));
    }
    uint4 uh = *(const uint4*)h8;
    uint4 ul = *(const uint4*)l8;
    size_t base = (size_t)r * 768 + kk;
    *(uint4*)(dst + base)       = uh;
    *(uint4*)(dst + base + 256) = uh;
    *(uint4*)(dst + base + 512) = ul;
}

// ---------------- weight transpose+split ----------------
__global__ void transposeW2(const float* __restrict__ Wa, const float* __restrict__ Wb,
                            __nv_bfloat16* __restrict__ oa, __nv_bfloat16* __restrict__ ob,
                            int K, int Nc) {
    const float* W = blockIdx.y ? Wb : Wa;
    __nv_bfloat16* dst = blockIdx.y ? ob : oa;
    int i = blockIdx.x * blockDim.x + threadIdx.x;
    if (i >= K * Nc) return;
    int k = i / Nc, n = i - k * Nc;
    float x = W[i];
    __nv_bfloat16 h = __float2bfloat16(x);
    __nv_bfloat16 l = __float2bfloat16(x - __bfloat162float(h));
    size_t base = (size_t)n * (3 * K) + k;
    dst[base]         = h;
    dst[base + K]     = l;
    dst[base + 2 * K] = h;
}

// ---------------- fused per-node attention (fp16 k/v operands) ----------------
__global__ __launch_bounds__(256)
void attn4(const float* __restrict__ qkv1, const float* __restrict__ qkv2,
           const __half* __restrict__ kv1, const __half* __restrict__ kv2,
           const float* __restrict__ coord1, const float* __restrict__ coord2,
           __nv_bfloat16* __restrict__ t1p, __nv_bfloat16* __restrict__ t2p) {
    int aid = blockIdx.y;
    const float* qkvQ;
    const __half* kvSrc;
    const float *coordD, *coordS;
    __nv_bfloat16* outp;
    int qoff, koff, voff, outoff, useRpe;
    switch (aid) {
        case 0: qkvQ = qkv1; qoff = 0;   kvSrc = kv1; koff = 0;   voff = 256;
                coordD = coord1; coordS = coord1; useRpe = 1; outp = t1p; outoff = 0;   break;
        case 1: qkvQ = qkv2; qoff = 768; kvSrc = kv2; koff = 512; voff = 768;
                coordD = coord2; coordS = coord2; useRpe = 1; outp = t2p; outoff = 0;   break;
        case 2: qkvQ = qkv1; qoff = 768; kvSrc = kv2; koff = 0;   voff = 256;
                coordD = nullptr; coordS = nullptr; useRpe = 0; outp = t1p; outoff = 256; break;
        default:qkvQ = qkv2; qoff = 0;   kvSrc = kv1; koff = 512; voff = 768;
                coordD = nullptr; coordS = nullptr; useRpe = 0; outp = t2p; outoff = 256; break;
    }

    int w = (blockIdx.x * blockDim.x + threadIdx.x) >> 5;
    if (w >= NN) return;
    int lane = threadIdx.x & 31;
    int h = lane >> 3;
    int dsub = (lane & 7) << 3;

    const float* qrow = qkvQ + (size_t)w * QW + qoff + h * 64 + dsub;
    float4 q0 = *(const float4*)(qrow);
    float4 q1 = *(const float4*)(qrow + 4);

    float r0 = 0.f, r1 = 0.f, r2 = 0.f, rb = 0.f, c0 = 0.f, c1 = 0.f, c2 = 0.f;
    if (useRpe) {
        r0 = g_rpe[h]; r1 = g_rpe[4 + h]; r2 = g_rpe[8 + h]; rb = g_rpe[12 + h];
        c0 = coordD[w * 3 + 0]; c1 = coordD[w * 3 + 1]; c2 = coordD[w * 3 + 2];
    }

    int s0 = g_off[aid][w], s1 = g_off[aid][w + 1];
    float a0 = 0.f, a1 = 0.f, a2 = 0.f, a3 = 0.f, a4 = 0.f, a5 = 0.f, a6 = 0.f, a7 = 0.f;
    float den = 0.f;

#pragma unroll 2
    for (int p = s0; p < s1; p++) {
        int src = g_srcs[aid][p];
        const __half2* k2 = (const __half2*)(kvSrc + (size_t)src * 1024 + koff + h * 64 + dsub);
        const __half2* v2 = (const __half2*)(kvSrc + (size_t)src * 1024 + voff + h * 64 + dsub);
        uint4 kraw = *(const uint4*)k2;
        uint4 vraw = *(const uint4*)v2;
        float2 kf0 = __half22float2(*(const __half2*)&kraw.x);
        float2 kf1 = __half22float2(*(const __half2*)&kraw.y);
        float2 kf2 = __half22float2(*(const __half2*)&kraw.z);
        float2 kf3 = __half22float2(*(const __half2*)&kraw.w);
        float dot = q0.x * kf0.x + q0.y * kf0.y + q0.z * kf1.x + q0.w * kf1.y
                  + q1.x * kf2.x + q1.y * kf2.y + q1.z * kf3.x + q1.w * kf3.y;
        dot += __shfl_xor_sync(0xffffffffu, dot, 1);
        dot += __shfl_xor_sync(0xffffffffu, dot, 2);
        dot += __shfl_xor_sync(0xffffffffu, dot, 4);
        if (useRpe) {
            float d0 = c0 - coordS[src * 3 + 0];
            float d1 = c1 - coordS[src * 3 + 1];
            float d2 = c2 - coordS[src * 3 + 2];
            dot += d0 * r0 + d1 * r1 + d2 * r2 + rb;
        }
        float esc = __expf(dot);
        den += esc;
        float2 vf0 = __half22float2(*(const __half2*)&vraw.x);
        float2 vf1 = __half22float2(*(const __half2*)&vraw.y);
        float2 vf2 = __half22float2(*(const __half2*)&vraw.z);
        float2 vf3 = __half22float2(*(const __half2*)&vraw.w);
        a0 += esc * vf0.x; a1 += esc * vf0.y; a2 += esc * vf1.x; a3 += esc * vf1.y;
        a4 += esc * vf2.x; a5 += esc * vf2.y; a6 += esc * vf3.x; a7 += esc * vf3.y;
    }

    float inv = (den > 0.f) ? (1.f / den) : 0.f;
    float vals[8] = {a0 * inv, a1 * inv, a2 * inv, a3 * inv,
                     a4 * inv, a5 * inv, a6 * inv, a7 * inv};
    __align__(16) __nv_bfloat16 h8[8], l8[8];
#pragma unroll
    for (int j = 0; j < 8; j++) {
        h8[j] = __float2bfloat16(vals[j]);
        l8[j] = __float2bfloat16(vals[j] - __bfloat162float(h8[j]));
    }
    size_t rb_off = (size_t)w * 1536 + outoff + h * 64 + dsub;
    uint4 uh = *(const uint4*)h8;
    uint4 ul = *(const uint4*)l8;
    *(uint4*)(outp + rb_off)        = uh;
    *(uint4*)(outp + rb_off + 512)  = uh;
    *(uint4*)(outp + rb_off + 1024) = ul;
}

// ---------------- bf16 mma.sync GEMM (both sets via blockIdx.z) ----------------
// If KV0/KV1 non-null (QKV pass): k/v column sections [256,768) and [1024,1536)
// are written as fp16 to KV (compact cols: k_a->0, v_a->256, k_b->512, v_b->768)
// and NOT written to C; q sections go to C as fp32.
#define GSMEM 65536

__global__ __launch_bounds__(256)
void gemm_bf16_mma2(const __nv_bfloat16* __restrict__ A0, const __nv_bfloat16* __restrict__ A1,
                    const __nv_bfloat16* __restrict__ B0, const __nv_bfloat16* __restrict__ B1,
                    const float* __restrict__ bias0, const float* __restrict__ bias1,
                    float* __restrict__ C0, float* __restrict__ C1,
                    __half* __restrict__ KV0, __half* __restrict__ KV1,
                    int M, int Kp, int Nc) {
    const int z = blockIdx.z;
    const __nv_bfloat16* A = z ? A1 : A0;
    const __nv_bfloat16* B = z ? B1 : B0;
    const float* bias = z ? bias1 : bias0;
    float* C = z ? C1 : C0;
    __half* KV = z ? KV1 : KV0;

    extern __shared__ char smem[];
    const uint32_t sA_u = smem_u32(smem);
    const uint32_t sB_u = sA_u + 32768;

    const int t = threadIdx.x;
    const int wid = t >> 5, lane = t & 31;
    const int wm = wid & 1, wn = wid >> 1;
    const int m0 = blockIdx.y * 128, n0 = blockIdx.x * 128;

    float acc[4][4][4];
#pragma unroll
    for (int i = 0; i < 4; i++)
#pragma unroll
        for (int j = 0; j < 4; j++)
#pragma unroll
            for (int v = 0; v < 4; v++) acc[i][j][v] = 0.f;

    auto load_tiles = [&](int buf, int k0) {
#pragma unroll
        for (int i = 0; i < 4; i++) {
            int lin = i * 256 + t;
            int row = lin >> 3, ku = lin & 7;
            uint32_t b = (uint32_t)(row * 128 + ku * 16);
            b ^= (b >> 3) & 0x70;
            cp_async16(sA_u + buf * 16384 + b, A + (size_t)(m0 + row) * Kp + k0 + ku * 8);
            cp_async16(sB_u + buf * 16384 + b, B + (size_t)(n0 + row) * Kp + k0 + ku * 8);
        }
    };

    const int nk = Kp >> 6;
    load_tiles(0, 0);
    cp_commit();

    for (int kt = 0; kt < nk; kt++) {
        cp_wait0();
        __syncthreads();
        if (kt + 1 < nk) { load_tiles((kt + 1) & 1, (kt + 1) << 6); cp_commit(); }

        const uint32_t bufA = sA_u + (kt & 1) * 16384;
        const uint32_t bufB = sB_u + (kt & 1) * 16384;
#pragma unroll
        for (int kk = 0; kk < 4; kk++) {
            uint32_t afrag[4][4], bfrag[4][2];
            const int kseg = kk * 2 + (lane >> 4);
#pragma unroll
            for (int mt = 0; mt < 4; mt++) {
                int row = wm * 64 + mt * 16 + (lane & 15);
                uint32_t b = (uint32_t)(row * 128 + kseg * 16);
                b ^= (b >> 3) & 0x70;
                ldmatrix4(afrag[mt], bufA + b);
            }
#pragma unroll
            for (int nt2 = 0; nt2 < 2; nt2++) {
                int row = wn * 32 + nt2 * 16 + (lane & 7) + ((lane >> 3) & 1) * 8;
                uint32_t b = (uint32_t)(row * 128 + kseg * 16);
                b ^= (b >> 3) & 0x70;
                uint32_t r[4];
                ldmatrix4(r, bufB + b);
                bfrag[nt2 * 2][0]     = r[0]; bfrag[nt2 * 2][1]     = r[2];
                bfrag[nt2 * 2 + 1][0] = r[1]; bfrag[nt2 * 2 + 1][1] = r[3];
            }
#pragma unroll
            for (int mt = 0; mt < 4; mt++)
#pragma unroll
                for (int nt = 0; nt < 4; nt++)
                    mma16816(acc[mt][nt], afrag[mt], bfrag[nt]);
        }
        __syncthreads();
    }

    // section is uniform per block (n0 multiple of 128 within one 256-col section)
    const int sec = n0 >> 8;
    const bool iskv = (KV != nullptr) && (sec != 0) && (sec != 3);
    const int kvbase = (sec == 1) ? 0 : (sec == 2) ? 256 : (sec == 4) ? 512 : 768;

#pragma unroll
    for (int mt = 0; mt < 4; mt++) {
        int rbase = m0 + wm * 64 + mt * 16 + (lane >> 2);
#pragma unroll
        for (int nt = 0; nt < 4; nt++) {
            int c = n0 + wn * 32 + nt * 8 + (lane & 3) * 2;
            float bx = bias[c], by = bias[c + 1];
            if (iskv) {
                int kvc = kvbase + (c & 255);
                if (rbase < M) {
                    __half2 o = __floats2half2_rn(acc[mt][nt][0] + bx, acc[mt][nt][1] + by);
                    *(__half2*)(KV + (size_t)rbase * 1024 + kvc) = o;
                }
                if (rbase + 8 < M) {
                    __half2 o = __floats2half2_rn(acc[mt][nt][2] + bx, acc[mt][nt][3] + by);
                    *(__half2*)(KV + (size_t)(rbase + 8) * 1024 + kvc) = o;
                }
            } else {
                if (rbase < M) {
                    float2 o = make_float2(acc[mt][nt][0] + bx, acc[mt][nt][1] + by);
                    *(float2*)(C + (size_t)rbase * Nc + c) = o;
                }
                if (rbase + 8 < M) {
                    float2 o = make_float2(acc[mt][nt][2] + bx, acc[mt][nt][3] + by);
                    *(float2*)(C + (size_t)(rbase + 8) * Nc + c) = o;
                }
            }
        }
    }
}

// ---------------- launch ----------------
extern "C" void kernel_launch(void* const* d_in, const int* in_sizes, int n_in,
                              void* d_out, int out_size) {
    const float* feat1  = (const float*)d_in[0];
    const float* coord1 = (const float*)d_in[1];
    const float* feat2  = (const float*)d_in[2];
    const float* coord2 = (const float*)d_in[3];
    const float* Wqkv1  = (const float*)d_in[4];
    const float* bqkv1  = (const float*)d_in[5];
    const float* Wqkv2  = (const float*)d_in[6];
    const float* bqkv2  = (const float*)d_in[7];
    const float* Wproj1 = (const float*)d_in[8];
    const float* bproj1 = (const float*)d_in[9];
    const float* Wproj2 = (const float*)d_in[10];
    const float* bproj2 = (const float*)d_in[11];
    const float* Wrpe   = (const float*)d_in[12];
    const float* brpe   = (const float*)d_in[13];
    const int* graph1   = (const int*)d_in[14];
    const int* graph2   = (const int*)d_in[15];
    const int* graph12  = (const int*)d_in[16];
    const int* graph21  = (const int*)d_in[17];
    float* out = (float*)d_out;

    float *qkv1, *qkv2;
    __half *kv1, *kv2;
    cudaGetSymbolAddress((void**)&qkv1, g_qkv1);
    cudaGetSymbolAddress((void**)&qkv2, g_qkv2);
    cudaGetSymbolAddress((void**)&kv1, g_kv1);
    cudaGetSymbolAddress((void**)&kv2, g_kv2);
    __nv_bfloat16 *f1p, *f2p, *t1p, *t2p, *w1p, *w2p, *p1p, *p2p;
    cudaGetSymbolAddress((void**)&f1p, g_f1p);
    cudaGetSymbolAddress((void**)&f2p, g_f2p);
    cudaGetSymbolAddress((void**)&t1p, g_t1p);
    cudaGetSymbolAddress((void**)&t2p, g_t2p);
    cudaGetSymbolAddress((void**)&w1p, g_w1p);
    cudaGetSymbolAddress((void**)&w2p, g_w2p);
    cudaGetSymbolAddress((void**)&p1p, g_p1p);
    cudaGetSymbolAddress((void**)&p2p, g_p2p);

    static cudaStream_t s1 = nullptr;
    static cudaEvent_t evFork = nullptr, evJoin = nullptr;
    static bool inited = false;
    if (!inited) {
        cudaStreamCreateWithFlags(&s1, cudaStreamNonBlocking);
        cudaEventCreateWithFlags(&evFork, cudaEventDisableTiming);
        cudaEventCreateWithFlags(&evJoin, cudaEventDisableTiming);
        cudaFuncSetAttribute(gemm_bf16_mma2, cudaFuncAttributeMaxDynamicSharedMemorySize, GSMEM);
        cudaFuncSetAttribute(scan_kernel, cudaFuncAttributeMaxDynamicSharedMemorySize, SCAN_SMEM);
        inited = true;
    }

    // s0: prep (zeroes counters used by s1)
    prep_all<<<128, 256>>>(Wrpe, brpe);

    // fork s1: CSR build + proj-weight transpose
    cudaEventRecord(evFork, 0);
    cudaStreamWaitEvent(s1, evFork, 0);

    const int EBLK = (EE + 255) / 256;
    dim3 gcnt(EBLK, 4);
    count4<<<gcnt, 256, 0, s1>>>(graph1, graph2, graph21, graph12);
    scan_kernel<<<4, 1024, SCAN_SMEM, s1>>>();
    permute4<<<gcnt, 256, 0, s1>>>(graph1, graph2, graph21, graph12);
    dim3 gtp((512 * 256 + 255) / 256, 2);
    transposeW2<<<gtp, 256, 0, s1>>>(Wproj1, Wproj2, p1p, p2p, 512, 256);
    cudaEventRecord(evJoin, s1);

    // s0: feat split + qkv weight transpose + QKV GEMMs
    dim3 gfs((FSV + 255) / 256, 2);
    split_feats<<<gfs, 256>>>(feat1, feat2, f1p, f2p);
    dim3 gtw((256 * 1536 + 255) / 256, 2);
    transposeW2<<<gtw, 256>>>(Wqkv1, Wqkv2, w1p, w2p, 256, 1536);

    dim3 gq(QW / 128, NP / 128, 2);
    gemm_bf16_mma2<<<gq, 256, GSMEM>>>(f1p, f2p, w1p, w2p, bqkv1, bqkv2, qkv1, qkv2,
                                       kv1, kv2, NN, 768, QW);

    // join: attn needs CSR + QKV
    cudaStreamWaitEvent(0, evJoin, 0);

    dim3 ga((NN * 32 + 255) / 256, 4);
    attn4<<<ga, 256>>>(qkv1, qkv2, kv1, kv2, coord1, coord2, t1p, t2p);

    dim3 gp(256 / 128, NP / 128, 2);
    gemm_bf16_mma2<<<gp, 256, GSMEM>>>(t1p, t2p, p1p, p2p, bproj1, bproj2,
                                       out, out + (size_t)NN * 256, nullptr, nullptr,
                                       NN, 1536, 256);
}

// round 12
// speedup vs baseline: 2.7487x; 1.0019x over previous
#include <cuda_runtime.h>
#include <cuda_bf16.h>
#include <cuda_fp16.h>
#include <math.h>
#include <stdint.h>

#define NN 20000
#define EE 320000
#define HH 4
#define QW 1536   // 6*C
#define NP 20096  // 157 * 128 (padded M)

// ---------------- scratch (static device globals) ----------------
__device__ __align__(16) float g_qkv1[NN * QW];   // only q_a / q_b sections written
__device__ __align__(16) float g_qkv2[NN * QW];
// fp16 attention operands, row = [k_a(0) | v_a(256) | k_b(512) | v_b(768)]
__device__ __align__(16) __half g_kv1[NN * 1024];
__device__ __align__(16) __half g_kv2[NN * 1024];
__device__ float g_rpe[16];

// CSR per graph
__device__ int g_deg[4][NN];
__device__ int g_off[4][NN + 1];
__device__ int g_eidx[4][EE];
__device__ int g_srcs[4][EE];

// 2-term-split bf16 A-side operands [hi | lo]; B-side stays [hi | lo | hi].
// GEMM maps B-chunk kt -> A-chunk (kt<nkA ? kt : kt-nkA), giving terms
// Ah*Bh + Ah*Bl + Al*Bh.
__device__ __align__(16) __nv_bfloat16 g_f1p[NP * 512];
__device__ __align__(16) __nv_bfloat16 g_f2p[NP * 512];
__device__ __align__(16) __nv_bfloat16 g_t1p[NP * 1024];
__device__ __align__(16) __nv_bfloat16 g_t2p[NP * 1024];
__device__ __align__(16) __nv_bfloat16 g_w1p[1536 * 768];
__device__ __align__(16) __nv_bfloat16 g_w2p[1536 * 768];
__device__ __align__(16) __nv_bfloat16 g_p1p[256 * 1536];
__device__ __align__(16) __nv_bfloat16 g_p2p[256 * 1536];

// ---------------- helpers ----------------
__device__ __forceinline__ uint32_t smem_u32(const void* p) {
    uint32_t a;
    asm("{ .reg .u64 t; cvta.to.shared.u64 t, %1; cvt.u32.u64 %0, t; }" : "=r"(a) : "l"(p));
    return a;
}
__device__ __forceinline__ void cp_async16(uint32_t dst, const void* src) {
    asm volatile("cp.async.cg.shared.global [%0], [%1], 16;" :: "r"(dst), "l"(src));
}
__device__ __forceinline__ void cp_commit() {
    asm volatile("cp.async.commit_group;" ::: "memory");
}
__device__ __forceinline__ void cp_wait0() {
    asm volatile("cp.async.wait_group 0;" ::: "memory");
}
__device__ __forceinline__ void cp_wait1() {
    asm volatile("cp.async.wait_group 1;" ::: "memory");
}
__device__ __forceinline__ void ldmatrix4(uint32_t* r, uint32_t addr) {
    asm volatile("ldmatrix.sync.aligned.m8n8.x4.shared.b16 {%0,%1,%2,%3}, [%4];"
                 : "=r"(r[0]), "=r"(r[1]), "=r"(r[2]), "=r"(r[3]) : "r"(addr));
}
__device__ __forceinline__ void mma16816(float* c, const uint32_t* a, const uint32_t* b) {
    asm volatile("mma.sync.aligned.m16n8k16.row.col.f32.bf16.bf16.f32 "
                 "{%0,%1,%2,%3}, {%4,%5,%6,%7}, {%8,%9}, {%0,%1,%2,%3};"
                 : "+f"(c[0]), "+f"(c[1]), "+f"(c[2]), "+f"(c[3])
                 : "r"(a[0]), "r"(a[1]), "r"(a[2]), "r"(a[3]), "r"(b[0]), "r"(b[1]));
}

// ---------------- prep: rpe + zero CSR counters + zero t-buffer pad rows ----------------
#define TPADV (((NP - NN) * 1024) / 8)
__global__ void prep_all(const float* __restrict__ Wrpe, const float* __restrict__ brpe) {
    int gid = blockIdx.x * blockDim.x + threadIdx.x;
    int stride = gridDim.x * blockDim.x;

    if (blockIdx.x == 0 && threadIdx.x < HH) {
        int h = threadIdx.x;
        for (int p = 0; p < 3; p++) {
            float s = 0.f;
            for (int d = 0; d < 64; d++) s += Wrpe[p * 256 + h * 64 + d];
            g_rpe[p * HH + h] = s;
        }
        float b = 0.f;
        for (int d = 0; d < 64; d++) b += brpe[h * 64 + d];
        g_rpe[12 + h] = b;
    }

    int* d = &g_deg[0][0];
    for (int j = gid; j < 4 * NN; j += stride) d[j] = 0;

    uint4 zz = make_uint4(0, 0, 0, 0);
    uint4* t1 = (uint4*)(&g_t1p[(size_t)NN * 1024]);
    uint4* t2 = (uint4*)(&g_t2p[(size_t)NN * 1024]);
    for (int j = gid; j < TPADV; j += stride) { t1[j] = zz; t2[j] = zz; }
}

// ---------------- CSR build ----------------
__global__ void count4(const int* __restrict__ g0, const int* __restrict__ g1,
                       const int* __restrict__ g2, const int* __restrict__ g3) {
    int aid = blockIdx.y;
    const int* g = (aid == 0) ? g0 : (aid == 1) ? g1 : (aid == 2) ? g2 : g3;
    int i = blockIdx.x * blockDim.x + threadIdx.x;
    if (i < EE) g_eidx[aid][i] = atomicAdd(&g_deg[aid][g[i]], 1);
}
#define SCAN_SMEM (NN * 4)
__global__ void scan_kernel() {
    extern __shared__ int sd[];
    __shared__ int ssum[1024];
    int aid = blockIdx.x;
    int t = threadIdx.x;

    for (int i = t; i < NN; i += 1024) sd[i] = g_deg[aid][i];
    __syncthreads();

    const int CH = 20;
    int base = t * CH;
    int loc[CH];
    int s = 0;
#pragma unroll
    for (int i = 0; i < CH; i++) {
        int idx = base + i;
        int v = (idx < NN) ? sd[idx] : 0;
        loc[i] = s; s += v;
    }
    ssum[t] = s;
    __syncthreads();
    for (int o = 1; o < 1024; o <<= 1) {
        int v = (t >= o) ? ssum[t - o] : 0;
        __syncthreads();
        ssum[t] += v;
        __syncthreads();
    }
    int offs = (t > 0) ? ssum[t - 1] : 0;
#pragma unroll
    for (int i = 0; i < CH; i++) {
        int idx = base + i;
        if (idx < NN) sd[idx] = offs + loc[i];
    }
    __syncthreads();
    for (int i = t; i < NN; i += 1024) g_off[aid][i] = sd[i];
    if (t == 1023) g_off[aid][NN] = ssum[1023];
}
__global__ void permute4(const int* __restrict__ g0, const int* __restrict__ g1,
                         const int* __restrict__ g2, const int* __restrict__ g3) {
    int aid = blockIdx.y;
    const int* g = (aid == 0) ? g0 : (aid == 1) ? g1 : (aid == 2) ? g2 : g3;
    int i = blockIdx.x * blockDim.x + threadIdx.x;
    if (i >= EE) return;
    int d = g[i];
    int p = g_off[aid][d] + g_eidx[aid][i];
    g_srcs[aid][p] = g[EE + i];
}

// ---------------- feat split: [NN,256] f32 -> [NP,512] bf16 [hi|lo] ----------------
#define FSV (NP * 256 / 8)
__global__ void split_feats(const float* __restrict__ feat1, const float* __restrict__ feat2,
                            __nv_bfloat16* __restrict__ d1, __nv_bfloat16* __restrict__ d2) {
    const float* src = blockIdx.y ? feat2 : feat1;
    __nv_bfloat16* dst = blockIdx.y ? d2 : d1;
    int i8 = blockIdx.x * blockDim.x + threadIdx.x;
    if (i8 >= FSV) return;
    int r = i8 >> 5;
    int kk = (i8 & 31) << 3;
    float v[8];
    if (r < NN) {
        float4 x0 = *(const float4*)(src + (size_t)r * 256 + kk);
        float4 x1 = *(const float4*)(src + (size_t)r * 256 + kk + 4);
        v[0] = x0.x; v[1] = x0.y; v[2] = x0.z; v[3] = x0.w;
        v[4] = x1.x; v[5] = x1.y; v[6] = x1.z; v[7] = x1.w;
    } else {
#pragma unroll
        for (int j = 0; j < 8; j++) v[j] = 0.f;
    }
    __align__(16) __nv_bfloat16 h8[8], l8[8];
#pragma unroll
    for (int j = 0; j < 8; j++) {
        h8[j] = __float2bfloat16(v[j]);
        l8[j] = __float2bfloat16(v[j] - __bfloat162float(h8[j]));
    }
    size_t base = (size_t)r * 512 + kk;
    *(uint4*)(dst + base)       = *(const uint4*)h8;
    *(uint4*)(dst + base + 256) = *(const uint4*)l8;
}

// ---------------- weight transpose+split: W [K,Nc] -> dst [Nc,3K] [hi|lo|hi] ----------------
__global__ void transposeW2(const float* __restrict__ Wa, const float* __restrict__ Wb,
                            __nv_bfloat16* __restrict__ oa, __nv_bfloat16* __restrict__ ob,
                            int K, int Nc) {
    const float* W = blockIdx.y ? Wb : Wa;
    __nv_bfloat16* dst = blockIdx.y ? ob : oa;
    int i = blockIdx.x * blockDim.x + threadIdx.x;
    if (i >= K * Nc) return;
    int k = i / Nc, n = i - k * Nc;
    float x = W[i];
    __nv_bfloat16 h = __float2bfloat16(x);
    __nv_bfloat16 l = __float2bfloat16(x - __bfloat162float(h));
    size_t base = (size_t)n * (3 * K) + k;
    dst[base]         = h;
    dst[base + K]     = l;
    dst[base + 2 * K] = h;
}

// ---------------- fused per-node attention (fp16 k/v operands) ----------------
// output: row w of outp [NP,1024]: hi at outoff, lo at 512+outoff
__global__ __launch_bounds__(256)
void attn4(const float* __restrict__ qkv1, const float* __restrict__ qkv2,
           const __half* __restrict__ kv1, const __half* __restrict__ kv2,
           const float* __restrict__ coord1, const float* __restrict__ coord2,
           __nv_bfloat16* __restrict__ t1p, __nv_bfloat16* __restrict__ t2p) {
    int aid = blockIdx.y;
    const float* qkvQ;
    const __half* kvSrc;
    const float *coordD, *coordS;
    __nv_bfloat16* outp;
    int qoff, koff, voff, outoff, useRpe;
    switch (aid) {
        case 0: qkvQ = qkv1; qoff = 0;   kvSrc = kv1; koff = 0;   voff = 256;
                coordD = coord1; coordS = coord1; useRpe = 1; outp = t1p; outoff = 0;   break;
        case 1: qkvQ = qkv2; qoff = 768; kvSrc = kv2; koff = 512; voff = 768;
                coordD = coord2; coordS = coord2; useRpe = 1; outp = t2p; outoff = 0;   break;
        case 2: qkvQ = qkv1; qoff = 768; kvSrc = kv2; koff = 0;   voff = 256;
                coordD = nullptr; coordS = nullptr; useRpe = 0; outp = t1p; outoff = 256; break;
        default:qkvQ = qkv2; qoff = 0;   kvSrc = kv1; koff = 512; voff = 768;
                coordD = nullptr; coordS = nullptr; useRpe = 0; outp = t2p; outoff = 256; break;
    }

    int w = (blockIdx.x * blockDim.x + threadIdx.x) >> 5;
    if (w >= NN) return;
    int lane = threadIdx.x & 31;
    int h = lane >> 3;
    int dsub = (lane & 7) << 3;

    const float* qrow = qkvQ + (size_t)w * QW + qoff + h * 64 + dsub;
    float4 q0 = *(const float4*)(qrow);
    float4 q1 = *(const float4*)(qrow + 4);

    float r0 = 0.f, r1 = 0.f, r2 = 0.f, rb = 0.f, c0 = 0.f, c1 = 0.f, c2 = 0.f;
    if (useRpe) {
        r0 = g_rpe[h]; r1 = g_rpe[4 + h]; r2 = g_rpe[8 + h]; rb = g_rpe[12 + h];
        c0 = coordD[w * 3 + 0]; c1 = coordD[w * 3 + 1]; c2 = coordD[w * 3 + 2];
    }

    int s0 = g_off[aid][w], s1 = g_off[aid][w + 1];
    float a0 = 0.f, a1 = 0.f, a2 = 0.f, a3 = 0.f, a4 = 0.f, a5 = 0.f, a6 = 0.f, a7 = 0.f;
    float den = 0.f;

#pragma unroll 2
    for (int p = s0; p < s1; p++) {
        int src = g_srcs[aid][p];
        uint4 kraw = *(const uint4*)(kvSrc + (size_t)src * 1024 + koff + h * 64 + dsub);
        uint4 vraw = *(const uint4*)(kvSrc + (size_t)src * 1024 + voff + h * 64 + dsub);
        float2 kf0 = __half22float2(*(const __half2*)&kraw.x);
        float2 kf1 = __half22float2(*(const __half2*)&kraw.y);
        float2 kf2 = __half22float2(*(const __half2*)&kraw.z);
        float2 kf3 = __half22float2(*(const __half2*)&kraw.w);
        float dot = q0.x * kf0.x + q0.y * kf0.y + q0.z * kf1.x + q0.w * kf1.y
                  + q1.x * kf2.x + q1.y * kf2.y + q1.z * kf3.x + q1.w * kf3.y;
        dot += __shfl_xor_sync(0xffffffffu, dot, 1);
        dot += __shfl_xor_sync(0xffffffffu, dot, 2);
        dot += __shfl_xor_sync(0xffffffffu, dot, 4);
        if (useRpe) {
            float d0 = c0 - coordS[src * 3 + 0];
            float d1 = c1 - coordS[src * 3 + 1];
            float d2 = c2 - coordS[src * 3 + 2];
            dot += d0 * r0 + d1 * r1 + d2 * r2 + rb;
        }
        float esc = __expf(dot);
        den += esc;
        float2 vf0 = __half22float2(*(const __half2*)&vraw.x);
        float2 vf1 = __half22float2(*(const __half2*)&vraw.y);
        float2 vf2 = __half22float2(*(const __half2*)&vraw.z);
        float2 vf3 = __half22float2(*(const __half2*)&vraw.w);
        a0 += esc * vf0.x; a1 += esc * vf0.y; a2 += esc * vf1.x; a3 += esc * vf1.y;
        a4 += esc * vf2.x; a5 += esc * vf2.y; a6 += esc * vf3.x; a7 += esc * vf3.y;
    }

    float inv = (den > 0.f) ? (1.f / den) : 0.f;
    float vals[8] = {a0 * inv, a1 * inv, a2 * inv, a3 * inv,
                     a4 * inv, a5 * inv, a6 * inv, a7 * inv};
    __align__(16) __nv_bfloat16 h8[8], l8[8];
#pragma unroll
    for (int j = 0; j < 8; j++) {
        h8[j] = __float2bfloat16(vals[j]);
        l8[j] = __float2bfloat16(vals[j] - __bfloat162float(h8[j]));
    }
    size_t rb_off = (size_t)w * 1024 + outoff + h * 64 + dsub;
    *(uint4*)(outp + rb_off)       = *(const uint4*)h8;
    *(uint4*)(outp + rb_off + 512) = *(const uint4*)l8;
}

// ---------------- bf16 mma.sync GEMM, 3-stage pipeline, A-chunk remap ----------------
// A [Mpad, KpA] = [hi|lo]; B [Nc, KpB] = [hi|lo|hi], KpB = 3*KpA/2.
// B-chunk kt maps to A-chunk (kt < nkA ? kt : kt - nkA), nkA = KpA/128... = KpA>>7.
// If KV non-null (QKV pass): sections 1,2,4,5 (of 256 cols) -> fp16 KV buffer.
#define GSMEM 98304

__global__ __launch_bounds__(256)
void gemm_bf16_mma2(const __nv_bfloat16* __restrict__ A0, const __nv_bfloat16* __restrict__ A1,
                    const __nv_bfloat16* __restrict__ B0, const __nv_bfloat16* __restrict__ B1,
                    const float* __restrict__ bias0, const float* __restrict__ bias1,
                    float* __restrict__ C0, float* __restrict__ C1,
                    __half* __restrict__ KV0, __half* __restrict__ KV1,
                    int M, int KpA, int KpB, int Nc) {
    const int z = blockIdx.z;
    const __nv_bfloat16* A = z ? A1 : A0;
    const __nv_bfloat16* B = z ? B1 : B0;
    const float* bias = z ? bias1 : bias0;
    float* C = z ? C1 : C0;
    __half* KV = z ? KV1 : KV0;

    extern __shared__ char smem[];
    const uint32_t s_u = smem_u32(smem);   // stage s: A at s*32768, B at s*32768+16384

    const int t = threadIdx.x;
    const int wid = t >> 5, lane = t & 31;
    const int wm = wid & 1, wn = wid >> 1;
    const int m0 = blockIdx.y * 128, n0 = blockIdx.x * 128;
    const int nkA = KpA >> 7;   // A-chunks in the hi section

    float acc[4][4][4];
#pragma unroll
    for (int i = 0; i < 4; i++)
#pragma unroll
        for (int j = 0; j < 4; j++)
#pragma unroll
            for (int v = 0; v < 4; v++) acc[i][j][v] = 0.f;

    auto load_tiles = [&](int stage, int kt) {
        int ka = (kt < nkA) ? kt : (kt - nkA);
        int k0A = ka << 6, k0B = kt << 6;
        uint32_t sb = s_u + stage * 32768;
#pragma unroll
        for (int i = 0; i < 4; i++) {
            int lin = i * 256 + t;
            int row = lin >> 3, ku = lin & 7;
            uint32_t b = (uint32_t)(row * 128 + ku * 16);
            b ^= (b >> 3) & 0x70;
            cp_async16(sb + b,         A + (size_t)(m0 + row) * KpA + k0A + ku * 8);
            cp_async16(sb + 16384 + b, B + (size_t)(n0 + row) * KpB + k0B + ku * 8);
        }
    };

    const int nk = KpB >> 6;  // 12 or 24
    load_tiles(0, 0); cp_commit();
    load_tiles(1, 1); cp_commit();

    int st = 0;
    for (int kt = 0; kt < nk; kt++) {
        if (kt == nk - 1) cp_wait0(); else cp_wait1();
        __syncthreads();
        if (kt + 2 < nk) {
            int lst = st + 2; if (lst >= 3) lst -= 3;
            load_tiles(lst, kt + 2);
            cp_commit();
        }

        const uint32_t bufA = s_u + st * 32768;
        const uint32_t bufB = bufA + 16384;
#pragma unroll
        for (int kk = 0; kk < 4; kk++) {
            uint32_t afrag[4][4], bfrag[4][2];
            const int kseg = kk * 2 + (lane >> 4);
#pragma unroll
            for (int mt = 0; mt < 4; mt++) {
                int row = wm * 64 + mt * 16 + (lane & 15);
                uint32_t b = (uint32_t)(row * 128 + kseg * 16);
                b ^= (b >> 3) & 0x70;
                ldmatrix4(afrag[mt], bufA + b);
            }
#pragma unroll
            for (int nt2 = 0; nt2 < 2; nt2++) {
                int row = wn * 32 + nt2 * 16 + (lane & 7) + ((lane >> 3) & 1) * 8;
                uint32_t b = (uint32_t)(row * 128 + kseg * 16);
                b ^= (b >> 3) & 0x70;
                uint32_t r[4];
                ldmatrix4(r, bufB + b);
                bfrag[nt2 * 2][0]     = r[0]; bfrag[nt2 * 2][1]     = r[2];
                bfrag[nt2 * 2 + 1][0] = r[1]; bfrag[nt2 * 2 + 1][1] = r[3];
            }
#pragma unroll
            for (int mt = 0; mt < 4; mt++)
#pragma unroll
                for (int nt = 0; nt < 4; nt++)
                    mma16816(acc[mt][nt], afrag[mt], bfrag[nt]);
        }
        if (++st == 3) st = 0;
    }

    const int sec = n0 >> 8;
    const bool iskv = (KV != nullptr) && (sec != 0) && (sec != 3);
    const int kvbase = (sec == 1) ? 0 : (sec == 2) ? 256 : (sec == 4) ? 512 : 768;

#pragma unroll
    for (int mt = 0; mt < 4; mt++) {
        int rbase = m0 + wm * 64 + mt * 16 + (lane >> 2);
#pragma unroll
        for (int nt = 0; nt < 4; nt++) {
            int c = n0 + wn * 32 + nt * 8 + (lane & 3) * 2;
            float bx = bias[c], by = bias[c + 1];
            if (iskv) {
                int kvc = kvbase + (c & 255);
                if (rbase < M) {
                    __half2 o = __floats2half2_rn(acc[mt][nt][0] + bx, acc[mt][nt][1] + by);
                    *(__half2*)(KV + (size_t)rbase * 1024 + kvc) = o;
                }
                if (rbase + 8 < M) {
                    __half2 o = __floats2half2_rn(acc[mt][nt][2] + bx, acc[mt][nt][3] + by);
                    *(__half2*)(KV + (size_t)(rbase + 8) * 1024 + kvc) = o;
                }
            } else {
                if (rbase < M) {
                    float2 o = make_float2(acc[mt][nt][0] + bx, acc[mt][nt][1] + by);
                    *(float2*)(C + (size_t)rbase * Nc + c) = o;
                }
                if (rbase + 8 < M) {
                    float2 o = make_float2(acc[mt][nt][2] + bx, acc[mt][nt][3] + by);
                    *(float2*)(C + (size_t)(rbase + 8) * Nc + c) = o;
                }
            }
        }
    }
}

// ---------------- launch ----------------
extern "C" void kernel_launch(void* const* d_in, const int* in_sizes, int n_in,
                              void* d_out, int out_size) {
    const float* feat1  = (const float*)d_in[0];
    const float* coord1 = (const float*)d_in[1];
    const float* feat2  = (const float*)d_in[2];
    const float* coord2 = (const float*)d_in[3];
    const float* Wqkv1  = (const float*)d_in[4];
    const float* bqkv1  = (const float*)d_in[5];
    const float* Wqkv2  = (const float*)d_in[6];
    const float* bqkv2  = (const float*)d_in[7];
    const float* Wproj1 = (const float*)d_in[8];
    const float* bproj1 = (const float*)d_in[9];
    const float* Wproj2 = (const float*)d_in[10];
    const float* bproj2 = (const float*)d_in[11];
    const float* Wrpe   = (const float*)d_in[12];
    const float* brpe   = (const float*)d_in[13];
    const int* graph1   = (const int*)d_in[14];
    const int* graph2   = (const int*)d_in[15];
    const int* graph12  = (const int*)d_in[16];
    const int* graph21  = (const int*)d_in[17];
    float* out = (float*)d_out;

    float *qkv1, *qkv2;
    __half *kv1, *kv2;
    cudaGetSymbolAddress((void**)&qkv1, g_qkv1);
    cudaGetSymbolAddress((void**)&qkv2, g_qkv2);
    cudaGetSymbolAddress((void**)&kv1, g_kv1);
    cudaGetSymbolAddress((void**)&kv2, g_kv2);
    __nv_bfloat16 *f1p, *f2p, *t1p, *t2p, *w1p, *w2p, *p1p, *p2p;
    cudaGetSymbolAddress((void**)&f1p, g_f1p);
    cudaGetSymbolAddress((void**)&f2p, g_f2p);
    cudaGetSymbolAddress((void**)&t1p, g_t1p);
    cudaGetSymbolAddress((void**)&t2p, g_t2p);
    cudaGetSymbolAddress((void**)&w1p, g_w1p);
    cudaGetSymbolAddress((void**)&w2p, g_w2p);
    cudaGetSymbolAddress((void**)&p1p, g_p1p);
    cudaGetSymbolAddress((void**)&p2p, g_p2p);

    static cudaStream_t s1 = nullptr;
    static cudaEvent_t evFork = nullptr, evJoin = nullptr;
    static bool inited = false;
    if (!inited) {
        cudaStreamCreateWithFlags(&s1, cudaStreamNonBlocking);
        cudaEventCreateWithFlags(&evFork, cudaEventDisableTiming);
        cudaEventCreateWithFlags(&evJoin, cudaEventDisableTiming);
        cudaFuncSetAttribute(gemm_bf16_mma2, cudaFuncAttributeMaxDynamicSharedMemorySize, GSMEM);
        cudaFuncSetAttribute(scan_kernel, cudaFuncAttributeMaxDynamicSharedMemorySize, SCAN_SMEM);
        inited = true;
    }

    // s0: prep (zeroes counters used by s1)
    prep_all<<<128, 256>>>(Wrpe, brpe);

    // fork s1: CSR build + proj-weight transpose
    cudaEventRecord(evFork, 0);
    cudaStreamWaitEvent(s1, evFork, 0);

    const int EBLK = (EE + 255) / 256;
    dim3 gcnt(EBLK, 4);
    count4<<<gcnt, 256, 0, s1>>>(graph1, graph2, graph21, graph12);
    scan_kernel<<<4, 1024, SCAN_SMEM, s1>>>();
    permute4<<<gcnt, 256, 0, s1>>>(graph1, graph2, graph21, graph12);
    dim3 gtp((512 * 256 + 255) / 256, 2);
    transposeW2<<<gtp, 256, 0, s1>>>(Wproj1, Wproj2, p1p, p2p, 512, 256);
    cudaEventRecord(evJoin, s1);

    // s0: feat split + qkv weight transpose + QKV GEMMs
    dim3 gfs((FSV + 255) / 256, 2);
    split_feats<<<gfs, 256>>>(feat1, feat2, f1p, f2p);
    dim3 gtw((256 * 1536 + 255) / 256, 2);
    transposeW2<<<gtw, 256>>>(Wqkv1, Wqkv2, w1p, w2p, 256, 1536);

    dim3 gq(QW / 128, NP / 128, 2);
    gemm_bf16_mma2<<<gq, 256, GSMEM>>>(f1p, f2p, w1p, w2p, bqkv1, bqkv2, qkv1, qkv2,
                                       kv1, kv2, NN, 512, 768, QW);

    // join: attn needs CSR + QKV
    cudaStreamWaitEvent(0, evJoin, 0);

    dim3 ga((NN * 32 + 255) / 256, 4);
    attn4<<<ga, 256>>>(qkv1, qkv2, kv1, kv2, coord1, coord2, t1p, t2p);

    dim3 gp(256 / 128, NP / 128, 2);
    gemm_bf16_mma2<<<gp, 256, GSMEM>>>(t1p, t2p, p1p, p2p, bproj1, bproj2,
                                       out, out + (size_t)NN * 256, nullptr, nullptr,
                                       NN, 1024, 1536, 256);
}

// round 13
// speedup vs baseline: 4.5421x; 1.6525x over previous
#include <cuda_runtime.h>
#include <cuda_fp16.h>
#include <math.h>
#include <stdint.h>

#define NN 20000
#define EE 320000
#define HH 4
#define QW 1536   // 6*C
#define NP 20096  // 157 * 128 (padded M)

// ---------------- scratch (static device globals) ----------------
__device__ __align__(16) float g_qkv1[NN * QW];   // only q_a / q_b sections written
__device__ __align__(16) float g_qkv2[NN * QW];
// fp16 attention operands, row = [k_a(0) | v_a(256) | k_b(512) | v_b(768)]
__device__ __align__(16) __half g_kv1[NN * 1024];
__device__ __align__(16) __half g_kv2[NN * 1024];
__device__ float g_rpe[16];

// CSR per graph
__device__ int g_deg[4][NN];
__device__ int g_off[4][NN + 1];
__device__ int g_eidx[4][EE];
__device__ int g_srcs[4][EE];

// fp16 GEMM operands (single-pass, no splitting)
__device__ __align__(16) __half g_f1p[NP * 256];    // feat1 fp16, padded
__device__ __align__(16) __half g_f2p[NP * 256];
__device__ __align__(16) __half g_t1p[NP * 512];    // attention out fp16 [att_aa|att_ab]
__device__ __align__(16) __half g_t2p[NP * 512];
__device__ __align__(16) __half g_w1p[1536 * 256];  // Wqkv^T fp16
__device__ __align__(16) __half g_w2p[1536 * 256];
__device__ __align__(16) __half g_p1p[256 * 512];   // Wproj^T fp16
__device__ __align__(16) __half g_p2p[256 * 512];

// ---------------- helpers ----------------
__device__ __forceinline__ uint32_t smem_u32(const void* p) {
    uint32_t a;
    asm("{ .reg .u64 t; cvta.to.shared.u64 t, %1; cvt.u32.u64 %0, t; }" : "=r"(a) : "l"(p));
    return a;
}
__device__ __forceinline__ void cp_async16(uint32_t dst, const void* src) {
    asm volatile("cp.async.cg.shared.global [%0], [%1], 16;" :: "r"(dst), "l"(src));
}
__device__ __forceinline__ void cp_commit() {
    asm volatile("cp.async.commit_group;" ::: "memory");
}
__device__ __forceinline__ void cp_wait0() {
    asm volatile("cp.async.wait_group 0;" ::: "memory");
}
__device__ __forceinline__ void cp_wait1() {
    asm volatile("cp.async.wait_group 1;" ::: "memory");
}
__device__ __forceinline__ void ldmatrix4(uint32_t* r, uint32_t addr) {
    asm volatile("ldmatrix.sync.aligned.m8n8.x4.shared.b16 {%0,%1,%2,%3}, [%4];"
                 : "=r"(r[0]), "=r"(r[1]), "=r"(r[2]), "=r"(r[3]) : "r"(addr));
}
__device__ __forceinline__ void mma16816(float* c, const uint32_t* a, const uint32_t* b) {
    asm volatile("mma.sync.aligned.m16n8k16.row.col.f32.f16.f16.f32 "
                 "{%0,%1,%2,%3}, {%4,%5,%6,%7}, {%8,%9}, {%0,%1,%2,%3};"
                 : "+f"(c[0]), "+f"(c[1]), "+f"(c[2]), "+f"(c[3])
                 : "r"(a[0]), "r"(a[1]), "r"(a[2]), "r"(a[3]), "r"(b[0]), "r"(b[1]));
}

// ---------------- prep: rpe + zero CSR counters + zero t-buffer pad rows ----------------
#define TPADV (((NP - NN) * 512) / 8)
__global__ void prep_all(const float* __restrict__ Wrpe, const float* __restrict__ brpe) {
    int gid = blockIdx.x * blockDim.x + threadIdx.x;
    int stride = gridDim.x * blockDim.x;

    if (blockIdx.x == 0 && threadIdx.x < HH) {
        int h = threadIdx.x;
        for (int p = 0; p < 3; p++) {
            float s = 0.f;
            for (int d = 0; d < 64; d++) s += Wrpe[p * 256 + h * 64 + d];
            g_rpe[p * HH + h] = s;
        }
        float b = 0.f;
        for (int d = 0; d < 64; d++) b += brpe[h * 64 + d];
        g_rpe[12 + h] = b;
    }

    int* d = &g_deg[0][0];
    for (int j = gid; j < 4 * NN; j += stride) d[j] = 0;

    uint4 zz = make_uint4(0, 0, 0, 0);
    uint4* t1 = (uint4*)(&g_t1p[(size_t)NN * 512]);
    uint4* t2 = (uint4*)(&g_t2p[(size_t)NN * 512]);
    for (int j = gid; j < TPADV; j += stride) { t1[j] = zz; t2[j] = zz; }
}

// ---------------- CSR build ----------------
__global__ void count4(const int* __restrict__ g0, const int* __restrict__ g1,
                       const int* __restrict__ g2, const int* __restrict__ g3) {
    int aid = blockIdx.y;
    const int* g = (aid == 0) ? g0 : (aid == 1) ? g1 : (aid == 2) ? g2 : g3;
    int i = blockIdx.x * blockDim.x + threadIdx.x;
    if (i < EE) g_eidx[aid][i] = atomicAdd(&g_deg[aid][g[i]], 1);
}
#define SCAN_SMEM (NN * 4)
__global__ void scan_kernel() {
    extern __shared__ int sd[];
    __shared__ int ssum[1024];
    int aid = blockIdx.x;
    int t = threadIdx.x;

    for (int i = t; i < NN; i += 1024) sd[i] = g_deg[aid][i];
    __syncthreads();

    const int CH = 20;
    int base = t * CH;
    int loc[CH];
    int s = 0;
#pragma unroll
    for (int i = 0; i < CH; i++) {
        int idx = base + i;
        int v = (idx < NN) ? sd[idx] : 0;
        loc[i] = s; s += v;
    }
    ssum[t] = s;
    __syncthreads();
    for (int o = 1; o < 1024; o <<= 1) {
        int v = (t >= o) ? ssum[t - o] : 0;
        __syncthreads();
        ssum[t] += v;
        __syncthreads();
    }
    int offs = (t > 0) ? ssum[t - 1] : 0;
#pragma unroll
    for (int i = 0; i < CH; i++) {
        int idx = base + i;
        if (idx < NN) sd[idx] = offs + loc[i];
    }
    __syncthreads();
    for (int i = t; i < NN; i += 1024) g_off[aid][i] = sd[i];
    if (t == 1023) g_off[aid][NN] = ssum[1023];
}
__global__ void permute4(const int* __restrict__ g0, const int* __restrict__ g1,
                         const int* __restrict__ g2, const int* __restrict__ g3) {
    int aid = blockIdx.y;
    const int* g = (aid == 0) ? g0 : (aid == 1) ? g1 : (aid == 2) ? g2 : g3;
    int i = blockIdx.x * blockDim.x + threadIdx.x;
    if (i >= EE) return;
    int d = g[i];
    int p = g_off[aid][d] + g_eidx[aid][i];
    g_srcs[aid][p] = g[EE + i];
}

// ---------------- feat convert: [NN,256] f32 -> [NP,256] fp16 ----------------
#define FSV (NP * 256 / 8)
__global__ void split_feats(const float* __restrict__ feat1, const float* __restrict__ feat2,
                            __half* __restrict__ d1, __half* __restrict__ d2) {
    const float* src = blockIdx.y ? feat2 : feat1;
    __half* dst = blockIdx.y ? d2 : d1;
    int i8 = blockIdx.x * blockDim.x + threadIdx.x;
    if (i8 >= FSV) return;
    int r = i8 >> 5;
    int kk = (i8 & 31) << 3;
    __align__(16) __half h8[8];
    if (r < NN) {
        float4 x0 = *(const float4*)(src + (size_t)r * 256 + kk);
        float4 x1 = *(const float4*)(src + (size_t)r * 256 + kk + 4);
        h8[0] = __float2half_rn(x0.x); h8[1] = __float2half_rn(x0.y);
        h8[2] = __float2half_rn(x0.z); h8[3] = __float2half_rn(x0.w);
        h8[4] = __float2half_rn(x1.x); h8[5] = __float2half_rn(x1.y);
        h8[6] = __float2half_rn(x1.z); h8[7] = __float2half_rn(x1.w);
    } else {
#pragma unroll
        for (int j = 0; j < 8; j++) h8[j] = __float2half_rn(0.f);
    }
    *(uint4*)(dst + (size_t)r * 256 + kk) = *(const uint4*)h8;
}

// ---------------- weight transpose: W [K,Nc] f32 -> dst [Nc,K] fp16 ----------------
__global__ void transposeW2(const float* __restrict__ Wa, const float* __restrict__ Wb,
                            __half* __restrict__ oa, __half* __restrict__ ob,
                            int K, int Nc) {
    const float* W = blockIdx.y ? Wb : Wa;
    __half* dst = blockIdx.y ? ob : oa;
    int i = blockIdx.x * blockDim.x + threadIdx.x;
    if (i >= K * Nc) return;
    int k = i / Nc, n = i - k * Nc;
    dst[(size_t)n * K + k] = __float2half_rn(W[i]);
}

// ---------------- fused per-node attention (fp16 k/v, fp16 out) ----------------
__global__ __launch_bounds__(256)
void attn4(const float* __restrict__ qkv1, const float* __restrict__ qkv2,
           const __half* __restrict__ kv1, const __half* __restrict__ kv2,
           const float* __restrict__ coord1, const float* __restrict__ coord2,
           __half* __restrict__ t1p, __half* __restrict__ t2p) {
    int aid = blockIdx.y;
    const float* qkvQ;
    const __half* kvSrc;
    const float *coordD, *coordS;
    __half* outp;
    int qoff, koff, voff, outoff, useRpe;
    switch (aid) {
        case 0: qkvQ = qkv1; qoff = 0;   kvSrc = kv1; koff = 0;   voff = 256;
                coordD = coord1; coordS = coord1; useRpe = 1; outp = t1p; outoff = 0;   break;
        case 1: qkvQ = qkv2; qoff = 768; kvSrc = kv2; koff = 512; voff = 768;
                coordD = coord2; coordS = coord2; useRpe = 1; outp = t2p; outoff = 0;   break;
        case 2: qkvQ = qkv1; qoff = 768; kvSrc = kv2; koff = 0;   voff = 256;
                coordD = nullptr; coordS = nullptr; useRpe = 0; outp = t1p; outoff = 256; break;
        default:qkvQ = qkv2; qoff = 0;   kvSrc = kv1; koff = 512; voff = 768;
                coordD = nullptr; coordS = nullptr; useRpe = 0; outp = t2p; outoff = 256; break;
    }

    int w = (blockIdx.x * blockDim.x + threadIdx.x) >> 5;
    if (w >= NN) return;
    int lane = threadIdx.x & 31;
    int h = lane >> 3;
    int dsub = (lane & 7) << 3;

    const float* qrow = qkvQ + (size_t)w * QW + qoff + h * 64 + dsub;
    float4 q0 = *(const float4*)(qrow);
    float4 q1 = *(const float4*)(qrow + 4);

    float r0 = 0.f, r1 = 0.f, r2 = 0.f, rb = 0.f, c0 = 0.f, c1 = 0.f, c2 = 0.f;
    if (useRpe) {
        r0 = g_rpe[h]; r1 = g_rpe[4 + h]; r2 = g_rpe[8 + h]; rb = g_rpe[12 + h];
        c0 = coordD[w * 3 + 0]; c1 = coordD[w * 3 + 1]; c2 = coordD[w * 3 + 2];
    }

    int s0 = g_off[aid][w], s1 = g_off[aid][w + 1];
    float a0 = 0.f, a1 = 0.f, a2 = 0.f, a3 = 0.f, a4 = 0.f, a5 = 0.f, a6 = 0.f, a7 = 0.f;
    float den = 0.f;

#pragma unroll 2
    for (int p = s0; p < s1; p++) {
        int src = g_srcs[aid][p];
        uint4 kraw = *(const uint4*)(kvSrc + (size_t)src * 1024 + koff + h * 64 + dsub);
        uint4 vraw = *(const uint4*)(kvSrc + (size_t)src * 1024 + voff + h * 64 + dsub);
        float2 kf0 = __half22float2(*(const __half2*)&kraw.x);
        float2 kf1 = __half22float2(*(const __half2*)&kraw.y);
        float2 kf2 = __half22float2(*(const __half2*)&kraw.z);
        float2 kf3 = __half22float2(*(const __half2*)&kraw.w);
        float dot = q0.x * kf0.x + q0.y * kf0.y + q0.z * kf1.x + q0.w * kf1.y
                  + q1.x * kf2.x + q1.y * kf2.y + q1.z * kf3.x + q1.w * kf3.y;
        dot += __shfl_xor_sync(0xffffffffu, dot, 1);
        dot += __shfl_xor_sync(0xffffffffu, dot, 2);
        dot += __shfl_xor_sync(0xffffffffu, dot, 4);
        if (useRpe) {
            float d0 = c0 - coordS[src * 3 + 0];
            float d1 = c1 - coordS[src * 3 + 1];
            float d2 = c2 - coordS[src * 3 + 2];
            dot += d0 * r0 + d1 * r1 + d2 * r2 + rb;
        }
        float esc = __expf(dot);
        den += esc;
        float2 vf0 = __half22float2(*(const __half2*)&vraw.x);
        float2 vf1 = __half22float2(*(const __half2*)&vraw.y);
        float2 vf2 = __half22float2(*(const __half2*)&vraw.z);
        float2 vf3 = __half22float2(*(const __half2*)&vraw.w);
        a0 += esc * vf0.x; a1 += esc * vf0.y; a2 += esc * vf1.x; a3 += esc * vf1.y;
        a4 += esc * vf2.x; a5 += esc * vf2.y; a6 += esc * vf3.x; a7 += esc * vf3.y;
    }

    float inv = (den > 0.f) ? (1.f / den) : 0.f;
    __align__(16) __half h8[8];
    h8[0] = __float2half_rn(a0 * inv); h8[1] = __float2half_rn(a1 * inv);
    h8[2] = __float2half_rn(a2 * inv); h8[3] = __float2half_rn(a3 * inv);
    h8[4] = __float2half_rn(a4 * inv); h8[5] = __float2half_rn(a5 * inv);
    h8[6] = __float2half_rn(a6 * inv); h8[7] = __float2half_rn(a7 * inv);
    *(uint4*)(outp + (size_t)w * 512 + outoff + h * 64 + dsub) = *(const uint4*)h8;
}

// ---------------- fp16 mma.sync GEMM, 3-stage pipeline (both sets via blockIdx.z) ----------------
// C[M,Nc] = A[Mpad,K] @ B[Nc,K]^T + bias.  K % 64 == 0.
// If KV non-null (QKV pass): 256-col sections 1,2,4,5 -> fp16 KV buffer.
#define GSMEM 98304

__global__ __launch_bounds__(256)
void gemm_f16_mma2(const __half* __restrict__ A0, const __half* __restrict__ A1,
                   const __half* __restrict__ B0, const __half* __restrict__ B1,
                   const float* __restrict__ bias0, const float* __restrict__ bias1,
                   float* __restrict__ C0, float* __restrict__ C1,
                   __half* __restrict__ KV0, __half* __restrict__ KV1,
                   int M, int K, int Nc) {
    const int z = blockIdx.z;
    const __half* A = z ? A1 : A0;
    const __half* B = z ? B1 : B0;
    const float* bias = z ? bias1 : bias0;
    float* C = z ? C1 : C0;
    __half* KV = z ? KV1 : KV0;

    extern __shared__ char smem[];
    const uint32_t s_u = smem_u32(smem);   // stage s: A at s*32768, B at +16384

    const int t = threadIdx.x;
    const int wid = t >> 5, lane = t & 31;
    const int wm = wid & 1, wn = wid >> 1;
    const int m0 = blockIdx.y * 128, n0 = blockIdx.x * 128;

    float acc[4][4][4];
#pragma unroll
    for (int i = 0; i < 4; i++)
#pragma unroll
        for (int j = 0; j < 4; j++)
#pragma unroll
            for (int v = 0; v < 4; v++) acc[i][j][v] = 0.f;

    auto load_tiles = [&](int stage, int kt) {
        int k0 = kt << 6;
        uint32_t sb = s_u + stage * 32768;
#pragma unroll
        for (int i = 0; i < 4; i++) {
            int lin = i * 256 + t;
            int row = lin >> 3, ku = lin & 7;
            uint32_t b = (uint32_t)(row * 128 + ku * 16);
            b ^= (b >> 3) & 0x70;
            cp_async16(sb + b,         A + (size_t)(m0 + row) * K + k0 + ku * 8);
            cp_async16(sb + 16384 + b, B + (size_t)(n0 + row) * K + k0 + ku * 8);
        }
    };

    const int nk = K >> 6;   // 4 (QKV) or 8 (proj)
    load_tiles(0, 0); cp_commit();
    load_tiles(1, 1); cp_commit();

    int st = 0;
    for (int kt = 0; kt < nk; kt++) {
        if (kt == nk - 1) cp_wait0(); else cp_wait1();
        __syncthreads();
        if (kt + 2 < nk) {
            int lst = st + 2; if (lst >= 3) lst -= 3;
            load_tiles(lst, kt + 2);
            cp_commit();
        }

        const uint32_t bufA = s_u + st * 32768;
        const uint32_t bufB = bufA + 16384;
#pragma unroll
        for (int kk = 0; kk < 4; kk++) {
            uint32_t afrag[4][4], bfrag[4][2];
            const int kseg = kk * 2 + (lane >> 4);
#pragma unroll
            for (int mt = 0; mt < 4; mt++) {
                int row = wm * 64 + mt * 16 + (lane & 15);
                uint32_t b = (uint32_t)(row * 128 + kseg * 16);
                b ^= (b >> 3) & 0x70;
                ldmatrix4(afrag[mt], bufA + b);
            }
#pragma unroll
            for (int nt2 = 0; nt2 < 2; nt2++) {
                int row = wn * 32 + nt2 * 16 + (lane & 7) + ((lane >> 3) & 1) * 8;
                uint32_t b = (uint32_t)(row * 128 + kseg * 16);
                b ^= (b >> 3) & 0x70;
                uint32_t r[4];
                ldmatrix4(r, bufB + b);
                bfrag[nt2 * 2][0]     = r[0]; bfrag[nt2 * 2][1]     = r[2];
                bfrag[nt2 * 2 + 1][0] = r[1]; bfrag[nt2 * 2 + 1][1] = r[3];
            }
#pragma unroll
            for (int mt = 0; mt < 4; mt++)
#pragma unroll
                for (int nt = 0; nt < 4; nt++)
                    mma16816(acc[mt][nt], afrag[mt], bfrag[nt]);
        }
        if (++st == 3) st = 0;
    }

    const int sec = n0 >> 8;
    const bool iskv = (KV != nullptr) && (sec != 0) && (sec != 3);
    const int kvbase = (sec == 1) ? 0 : (sec == 2) ? 256 : (sec == 4) ? 512 : 768;

#pragma unroll
    for (int mt = 0; mt < 4; mt++) {
        int rbase = m0 + wm * 64 + mt * 16 + (lane >> 2);
#pragma unroll
        for (int nt = 0; nt < 4; nt++) {
            int c = n0 + wn * 32 + nt * 8 + (lane & 3) * 2;
            float bx = bias[c], by = bias[c + 1];
            if (iskv) {
                int kvc = kvbase + (c & 255);
                if (rbase < M) {
                    __half2 o = __floats2half2_rn(acc[mt][nt][0] + bx, acc[mt][nt][1] + by);
                    *(__half2*)(KV + (size_t)rbase * 1024 + kvc) = o;
                }
                if (rbase + 8 < M) {
                    __half2 o = __floats2half2_rn(acc[mt][nt][2] + bx, acc[mt][nt][3] + by);
                    *(__half2*)(KV + (size_t)(rbase + 8) * 1024 + kvc) = o;
                }
            } else {
                if (rbase < M) {
                    float2 o = make_float2(acc[mt][nt][0] + bx, acc[mt][nt][1] + by);
                    *(float2*)(C + (size_t)rbase * Nc + c) = o;
                }
                if (rbase + 8 < M) {
                    float2 o = make_float2(acc[mt][nt][2] + bx, acc[mt][nt][3] + by);
                    *(float2*)(C + (size_t)(rbase + 8) * Nc + c) = o;
                }
            }
        }
    }
}

// ---------------- launch ----------------
extern "C" void kernel_launch(void* const* d_in, const int* in_sizes, int n_in,
                              void* d_out, int out_size) {
    const float* feat1  = (const float*)d_in[0];
    const float* coord1 = (const float*)d_in[1];
    const float* feat2  = (const float*)d_in[2];
    const float* coord2 = (const float*)d_in[3];
    const float* Wqkv1  = (const float*)d_in[4];
    const float* bqkv1  = (const float*)d_in[5];
    const float* Wqkv2  = (const float*)d_in[6];
    const float* bqkv2  = (const float*)d_in[7];
    const float* Wproj1 = (const float*)d_in[8];
    const float* bproj1 = (const float*)d_in[9];
    const float* Wproj2 = (const float*)d_in[10];
    const float* bproj2 = (const float*)d_in[11];
    const float* Wrpe   = (const float*)d_in[12];
    const float* brpe   = (const float*)d_in[13];
    const int* graph1   = (const int*)d_in[14];
    const int* graph2   = (const int*)d_in[15];
    const int* graph12  = (const int*)d_in[16];
    const int* graph21  = (const int*)d_in[17];
    float* out = (float*)d_out;

    float *qkv1, *qkv2;
    __half *kv1, *kv2;
    cudaGetSymbolAddress((void**)&qkv1, g_qkv1);
    cudaGetSymbolAddress((void**)&qkv2, g_qkv2);
    cudaGetSymbolAddress((void**)&kv1, g_kv1);
    cudaGetSymbolAddress((void**)&kv2, g_kv2);
    __half *f1p, *f2p, *t1p, *t2p, *w1p, *w2p, *p1p, *p2p;
    cudaGetSymbolAddress((void**)&f1p, g_f1p);
    cudaGetSymbolAddress((void**)&f2p, g_f2p);
    cudaGetSymbolAddress((void**)&t1p, g_t1p);
    cudaGetSymbolAddress((void**)&t2p, g_t2p);
    cudaGetSymbolAddress((void**)&w1p, g_w1p);
    cudaGetSymbolAddress((void**)&w2p, g_w2p);
    cudaGetSymbolAddress((void**)&p1p, g_p1p);
    cudaGetSymbolAddress((void**)&p2p, g_p2p);

    static cudaStream_t s1 = nullptr;
    static cudaEvent_t evFork = nullptr, evJoin = nullptr;
    static bool inited = false;
    if (!inited) {
        cudaStreamCreateWithFlags(&s1, cudaStreamNonBlocking);
        cudaEventCreateWithFlags(&evFork, cudaEventDisableTiming);
        cudaEventCreateWithFlags(&evJoin, cudaEventDisableTiming);
        cudaFuncSetAttribute(gemm_f16_mma2, cudaFuncAttributeMaxDynamicSharedMemorySize, GSMEM);
        cudaFuncSetAttribute(scan_kernel, cudaFuncAttributeMaxDynamicSharedMemorySize, SCAN_SMEM);
        inited = true;
    }

    // s0: prep (zeroes counters used by s1)
    prep_all<<<128, 256>>>(Wrpe, brpe);

    // fork s1: CSR build + proj-weight transpose
    cudaEventRecord(evFork, 0);
    cudaStreamWaitEvent(s1, evFork, 0);

    const int EBLK = (EE + 255) / 256;
    dim3 gcnt(EBLK, 4);
    count4<<<gcnt, 256, 0, s1>>>(graph1, graph2, graph21, graph12);
    scan_kernel<<<4, 1024, SCAN_SMEM, s1>>>();
    permute4<<<gcnt, 256, 0, s1>>>(graph1, graph2, graph21, graph12);
    dim3 gtp((512 * 256 + 255) / 256, 2);
    transposeW2<<<gtp, 256, 0, s1>>>(Wproj1, Wproj2, p1p, p2p, 512, 256);
    cudaEventRecord(evJoin, s1);

    // s0: feat convert + qkv weight transpose + QKV GEMMs
    dim3 gfs((FSV + 255) / 256, 2);
    split_feats<<<gfs, 256>>>(feat1, feat2, f1p, f2p);
    dim3 gtw((256 * 1536 + 255) / 256, 2);
    transposeW2<<<gtw, 256>>>(Wqkv1, Wqkv2, w1p, w2p, 256, 1536);

    dim3 gq(QW / 128, NP / 128, 2);
    gemm_f16_mma2<<<gq, 256, GSMEM>>>(f1p, f2p, w1p, w2p, bqkv1, bqkv2, qkv1, qkv2,
                                      kv1, kv2, NN, 256, QW);

    // join: attn needs CSR + QKV
    cudaStreamWaitEvent(0, evJoin, 0);

    dim3 ga((NN * 32 + 255) / 256, 4);
    attn4<<<ga, 256>>>(qkv1, qkv2, kv1, kv2, coord1, coord2, t1p, t2p);

    dim3 gp(256 / 128, NP / 128, 2);
    gemm_f16_mma2<<<gp, 256, GSMEM>>>(t1p, t2p, p1p, p2p, bproj1, bproj2,
                                      out, out + (size_t)NN * 256, nullptr, nullptr,
                                      NN, 512, 256);
}

// round 14
// speedup vs baseline: 4.6663x; 1.0273x over previous
#include <cuda_runtime.h>
#include <cuda_fp16.h>
#include <math.h>
#include <stdint.h>

#define NN 20000
#define EE 320000
#define HH 4
#define QW 1536   // 6*C
#define NP 20096  // 157 * 128 (padded M)

// ---------------- scratch (static device globals) ----------------
__device__ __align__(16) float g_qkv1[NN * QW];   // only q_a / q_b sections written
__device__ __align__(16) float g_qkv2[NN * QW];
// fp16 attention operands, row = [k_a(0) | v_a(256) | k_b(512) | v_b(768)]
__device__ __align__(16) __half g_kv1[NN * 1024];
__device__ __align__(16) __half g_kv2[NN * 1024];
__device__ float g_rpe[16];

// CSR per graph
__device__ int g_deg[4][NN];
__device__ int g_off[4][NN + 1];
__device__ int g_eidx[4][EE];
__device__ int g_srcs[4][EE];

// fp16 GEMM operands
__device__ __align__(16) __half g_f1p[NP * 256];
__device__ __align__(16) __half g_f2p[NP * 256];
__device__ __align__(16) __half g_t1p[NP * 512];
__device__ __align__(16) __half g_t2p[NP * 512];
__device__ __align__(16) __half g_w1p[1536 * 256];
__device__ __align__(16) __half g_w2p[1536 * 256];
__device__ __align__(16) __half g_p1p[256 * 512];
__device__ __align__(16) __half g_p2p[256 * 512];

// ---------------- helpers ----------------
__device__ __forceinline__ uint32_t smem_u32(const void* p) {
    uint32_t a;
    asm("{ .reg .u64 t; cvta.to.shared.u64 t, %1; cvt.u32.u64 %0, t; }" : "=r"(a) : "l"(p));
    return a;
}
__device__ __forceinline__ void cp_async16(uint32_t dst, const void* src) {
    asm volatile("cp.async.cg.shared.global [%0], [%1], 16;" :: "r"(dst), "l"(src));
}
__device__ __forceinline__ void cp_commit() {
    asm volatile("cp.async.commit_group;" ::: "memory");
}
__device__ __forceinline__ void cp_wait0() {
    asm volatile("cp.async.wait_group 0;" ::: "memory");
}
__device__ __forceinline__ void cp_wait1() {
    asm volatile("cp.async.wait_group 1;" ::: "memory");
}
__device__ __forceinline__ void ldmatrix4(uint32_t* r, uint32_t addr) {
    asm volatile("ldmatrix.sync.aligned.m8n8.x4.shared.b16 {%0,%1,%2,%3}, [%4];"
                 : "=r"(r[0]), "=r"(r[1]), "=r"(r[2]), "=r"(r[3]) : "r"(addr));
}
__device__ __forceinline__ void mma16816(float* c, const uint32_t* a, const uint32_t* b) {
    asm volatile("mma.sync.aligned.m16n8k16.row.col.f32.f16.f16.f32 "
                 "{%0,%1,%2,%3}, {%4,%5,%6,%7}, {%8,%9}, {%0,%1,%2,%3};"
                 : "+f"(c[0]), "+f"(c[1]), "+f"(c[2]), "+f"(c[3])
                 : "r"(a[0]), "r"(a[1]), "r"(a[2]), "r"(a[3]), "r"(b[0]), "r"(b[1]));
}

// ---------------- prep: rpe + zero CSR counters + zero t-buffer pad rows ----------------
#define TPADV (((NP - NN) * 512) / 8)
__global__ void prep_all(const float* __restrict__ Wrpe, const float* __restrict__ brpe) {
    int gid = blockIdx.x * blockDim.x + threadIdx.x;
    int stride = gridDim.x * blockDim.x;

    if (blockIdx.x == 0 && threadIdx.x < HH) {
        int h = threadIdx.x;
        for (int p = 0; p < 3; p++) {
            float s = 0.f;
            for (int d = 0; d < 64; d++) s += Wrpe[p * 256 + h * 64 + d];
            g_rpe[p * HH + h] = s;
        }
        float b = 0.f;
        for (int d = 0; d < 64; d++) b += brpe[h * 64 + d];
        g_rpe[12 + h] = b;
    }

    int* d = &g_deg[0][0];
    for (int j = gid; j < 4 * NN; j += stride) d[j] = 0;

    uint4 zz = make_uint4(0, 0, 0, 0);
    uint4* t1 = (uint4*)(&g_t1p[(size_t)NN * 512]);
    uint4* t2 = (uint4*)(&g_t2p[(size_t)NN * 512]);
    for (int j = gid; j < TPADV; j += stride) { t1[j] = zz; t2[j] = zz; }
}

// ---------------- CSR build ----------------
__global__ void count4(const int* __restrict__ g0, const int* __restrict__ g1,
                       const int* __restrict__ g2, const int* __restrict__ g3) {
    int aid = blockIdx.y;
    const int* g = (aid == 0) ? g0 : (aid == 1) ? g1 : (aid == 2) ? g2 : g3;
    int i = blockIdx.x * blockDim.x + threadIdx.x;
    if (i < EE) g_eidx[aid][i] = atomicAdd(&g_deg[aid][g[i]], 1);
}
#define SCAN_SMEM (NN * 4)
__global__ void scan_kernel() {
    extern __shared__ int sd[];
    __shared__ int ssum[1024];
    int aid = blockIdx.x;
    int t = threadIdx.x;

    for (int i = t; i < NN; i += 1024) sd[i] = g_deg[aid][i];
    __syncthreads();

    const int CH = 20;
    int base = t * CH;
    int loc[CH];
    int s = 0;
#pragma unroll
    for (int i = 0; i < CH; i++) {
        int idx = base + i;
        int v = (idx < NN) ? sd[idx] : 0;
        loc[i] = s; s += v;
    }
    ssum[t] = s;
    __syncthreads();
    for (int o = 1; o < 1024; o <<= 1) {
        int v = (t >= o) ? ssum[t - o] : 0;
        __syncthreads();
        ssum[t] += v;
        __syncthreads();
    }
    int offs = (t > 0) ? ssum[t - 1] : 0;
#pragma unroll
    for (int i = 0; i < CH; i++) {
        int idx = base + i;
        if (idx < NN) sd[idx] = offs + loc[i];
    }
    __syncthreads();
    for (int i = t; i < NN; i += 1024) g_off[aid][i] = sd[i];
    if (t == 1023) g_off[aid][NN] = ssum[1023];
}
__global__ void permute4(const int* __restrict__ g0, const int* __restrict__ g1,
                         const int* __restrict__ g2, const int* __restrict__ g3) {
    int aid = blockIdx.y;
    const int* g = (aid == 0) ? g0 : (aid == 1) ? g1 : (aid == 2) ? g2 : g3;
    int i = blockIdx.x * blockDim.x + threadIdx.x;
    if (i >= EE) return;
    int d = g[i];
    int p = g_off[aid][d] + g_eidx[aid][i];
    g_srcs[aid][p] = g[EE + i];
}

// ---------------- feat convert: [NN,256] f32 -> [NP,256] fp16 ----------------
#define FSV (NP * 256 / 8)
__global__ void split_feats(const float* __restrict__ feat1, const float* __restrict__ feat2,
                            __half* __restrict__ d1, __half* __restrict__ d2) {
    const float* src = blockIdx.y ? feat2 : feat1;
    __half* dst = blockIdx.y ? d2 : d1;
    int i8 = blockIdx.x * blockDim.x + threadIdx.x;
    if (i8 >= FSV) return;
    int r = i8 >> 5;
    int kk = (i8 & 31) << 3;
    __align__(16) __half h8[8];
    if (r < NN) {
        float4 x0 = *(const float4*)(src + (size_t)r * 256 + kk);
        float4 x1 = *(const float4*)(src + (size_t)r * 256 + kk + 4);
        h8[0] = __float2half_rn(x0.x); h8[1] = __float2half_rn(x0.y);
        h8[2] = __float2half_rn(x0.z); h8[3] = __float2half_rn(x0.w);
        h8[4] = __float2half_rn(x1.x); h8[5] = __float2half_rn(x1.y);
        h8[6] = __float2half_rn(x1.z); h8[7] = __float2half_rn(x1.w);
    } else {
#pragma unroll
        for (int j = 0; j < 8; j++) h8[j] = __float2half_rn(0.f);
    }
    *(uint4*)(dst + (size_t)r * 256 + kk) = *(const uint4*)h8;
}

// ---------------- coalesced weight transpose: W [K,Nc] f32 -> dst [Nc,K] fp16 ----------------
// 32x32 tile via smem; grid (Nc/32, K/32, 2)
__global__ void transposeW2c(const float* __restrict__ Wa, const float* __restrict__ Wb,
                             __half* __restrict__ oa, __half* __restrict__ ob,
                             int K, int Nc) {
    const float* W = blockIdx.z ? Wb : Wa;
    __half* dst = blockIdx.z ? ob : oa;
    __shared__ __half tile[32][33];
    int n0 = blockIdx.x * 32, k0 = blockIdx.y * 32;
    int tx = threadIdx.x, ty = threadIdx.y;   // 32 x 8
#pragma unroll
    for (int i = ty; i < 32; i += 8)
        tile[i][tx] = __float2half_rn(W[(size_t)(k0 + i) * Nc + n0 + tx]);
    __syncthreads();
#pragma unroll
    for (int i = ty; i < 32; i += 8)
        dst[(size_t)(n0 + i) * K + k0 + tx] = tile[tx][i];
}

// ---------------- fused per-node attention (fp16 k/v, fp16 out) ----------------
// aid = aidbase + 2*blockIdx.y  (chain A: aids 0,2 -> t1p; chain B: aids 1,3 -> t2p)
__global__ __launch_bounds__(256)
void attn4(const float* __restrict__ qkv1, const float* __restrict__ qkv2,
           const __half* __restrict__ kv1, const __half* __restrict__ kv2,
           const float* __restrict__ coord1, const float* __restrict__ coord2,
           __half* __restrict__ t1p, __half* __restrict__ t2p, int aidbase) {
    int aid = aidbase + 2 * blockIdx.y;
    const float* qkvQ;
    const __half* kvSrc;
    const float *coordD, *coordS;
    __half* outp;
    int qoff, koff, voff, outoff, useRpe;
    switch (aid) {
        case 0: qkvQ = qkv1; qoff = 0;   kvSrc = kv1; koff = 0;   voff = 256;
                coordD = coord1; coordS = coord1; useRpe = 1; outp = t1p; outoff = 0;   break;
        case 1: qkvQ = qkv2; qoff = 768; kvSrc = kv2; koff = 512; voff = 768;
                coordD = coord2; coordS = coord2; useRpe = 1; outp = t2p; outoff = 0;   break;
        case 2: qkvQ = qkv1; qoff = 768; kvSrc = kv2; koff = 0;   voff = 256;
                coordD = nullptr; coordS = nullptr; useRpe = 0; outp = t1p; outoff = 256; break;
        default:qkvQ = qkv2; qoff = 0;   kvSrc = kv1; koff = 512; voff = 768;
                coordD = nullptr; coordS = nullptr; useRpe = 0; outp = t2p; outoff = 256; break;
    }

    int w = (blockIdx.x * blockDim.x + threadIdx.x) >> 5;
    if (w >= NN) return;
    int lane = threadIdx.x & 31;
    int h = lane >> 3;
    int dsub = (lane & 7) << 3;

    const float* qrow = qkvQ + (size_t)w * QW + qoff + h * 64 + dsub;
    float4 q0 = *(const float4*)(qrow);
    float4 q1 = *(const float4*)(qrow + 4);

    float r0 = 0.f, r1 = 0.f, r2 = 0.f, rb = 0.f, c0 = 0.f, c1 = 0.f, c2 = 0.f;
    if (useRpe) {
        r0 = g_rpe[h]; r1 = g_rpe[4 + h]; r2 = g_rpe[8 + h]; rb = g_rpe[12 + h];
        c0 = coordD[w * 3 + 0]; c1 = coordD[w * 3 + 1]; c2 = coordD[w * 3 + 2];
    }

    int s0 = g_off[aid][w], s1 = g_off[aid][w + 1];
    float a0 = 0.f, a1 = 0.f, a2 = 0.f, a3 = 0.f, a4 = 0.f, a5 = 0.f, a6 = 0.f, a7 = 0.f;
    float den = 0.f;

#pragma unroll 2
    for (int p = s0; p < s1; p++) {
        int src = g_srcs[aid][p];
        uint4 kraw = *(const uint4*)(kvSrc + (size_t)src * 1024 + koff + h * 64 + dsub);
        uint4 vraw = *(const uint4*)(kvSrc + (size_t)src * 1024 + voff + h * 64 + dsub);
        float2 kf0 = __half22float2(*(const __half2*)&kraw.x);
        float2 kf1 = __half22float2(*(const __half2*)&kraw.y);
        float2 kf2 = __half22float2(*(const __half2*)&kraw.z);
        float2 kf3 = __half22float2(*(const __half2*)&kraw.w);
        float dot = q0.x * kf0.x + q0.y * kf0.y + q0.z * kf1.x + q0.w * kf1.y
                  + q1.x * kf2.x + q1.y * kf2.y + q1.z * kf3.x + q1.w * kf3.y;
        dot += __shfl_xor_sync(0xffffffffu, dot, 1);
        dot += __shfl_xor_sync(0xffffffffu, dot, 2);
        dot += __shfl_xor_sync(0xffffffffu, dot, 4);
        if (useRpe) {
            float d0 = c0 - coordS[src * 3 + 0];
            float d1 = c1 - coordS[src * 3 + 1];
            float d2 = c2 - coordS[src * 3 + 2];
            dot += d0 * r0 + d1 * r1 + d2 * r2 + rb;
        }
        float esc = __expf(dot);
        den += esc;
        float2 vf0 = __half22float2(*(const __half2*)&vraw.x);
        float2 vf1 = __half22float2(*(const __half2*)&vraw.y);
        float2 vf2 = __half22float2(*(const __half2*)&vraw.z);
        float2 vf3 = __half22float2(*(const __half2*)&vraw.w);
        a0 += esc * vf0.x; a1 += esc * vf0.y; a2 += esc * vf1.x; a3 += esc * vf1.y;
        a4 += esc * vf2.x; a5 += esc * vf2.y; a6 += esc * vf3.x; a7 += esc * vf3.y;
    }

    float inv = (den > 0.f) ? (1.f / den) : 0.f;
    __align__(16) __half h8[8];
    h8[0] = __float2half_rn(a0 * inv); h8[1] = __float2half_rn(a1 * inv);
    h8[2] = __float2half_rn(a2 * inv); h8[3] = __float2half_rn(a3 * inv);
    h8[4] = __float2half_rn(a4 * inv); h8[5] = __float2half_rn(a5 * inv);
    h8[6] = __float2half_rn(a6 * inv); h8[7] = __float2half_rn(a7 * inv);
    *(uint4*)(outp + (size_t)w * 512 + outoff + h * 64 + dsub) = *(const uint4*)h8;
}

// ---------------- fp16 mma.sync GEMM, 3-stage pipeline ----------------
// C[M,Nc] = A[Mpad,K] @ B[Nc,K]^T + bias.  K % 64 == 0.
// blockIdx.z selects set (use gridDim.z=1 + identical pointers for single-set).
// If KV non-null (QKV pass): 256-col sections 1,2,4,5 -> fp16 KV buffer.
#define GSMEM 98304

__global__ __launch_bounds__(256)
void gemm_f16_mma2(const __half* __restrict__ A0, const __half* __restrict__ A1,
                   const __half* __restrict__ B0, const __half* __restrict__ B1,
                   const float* __restrict__ bias0, const float* __restrict__ bias1,
                   float* __restrict__ C0, float* __restrict__ C1,
                   __half* __restrict__ KV0, __half* __restrict__ KV1,
                   int M, int K, int Nc) {
    const int z = blockIdx.z;
    const __half* A = z ? A1 : A0;
    const __half* B = z ? B1 : B0;
    const float* bias = z ? bias1 : bias0;
    float* C = z ? C1 : C0;
    __half* KV = z ? KV1 : KV0;

    extern __shared__ char smem[];
    const uint32_t s_u = smem_u32(smem);

    const int t = threadIdx.x;
    const int wid = t >> 5, lane = t & 31;
    const int wm = wid & 1, wn = wid >> 1;
    const int m0 = blockIdx.y * 128, n0 = blockIdx.x * 128;

    float acc[4][4][4];
#pragma unroll
    for (int i = 0; i < 4; i++)
#pragma unroll
        for (int j = 0; j < 4; j++)
#pragma unroll
            for (int v = 0; v < 4; v++) acc[i][j][v] = 0.f;

    auto load_tiles = [&](int stage, int kt) {
        int k0 = kt << 6;
        uint32_t sb = s_u + stage * 32768;
#pragma unroll
        for (int i = 0; i < 4; i++) {
            int lin = i * 256 + t;
            int row = lin >> 3, ku = lin & 7;
            uint32_t b = (uint32_t)(row * 128 + ku * 16);
            b ^= (b >> 3) & 0x70;
            cp_async16(sb + b,         A + (size_t)(m0 + row) * K + k0 + ku * 8);
            cp_async16(sb + 16384 + b, B + (size_t)(n0 + row) * K + k0 + ku * 8);
        }
    };

    const int nk = K >> 6;
    load_tiles(0, 0); cp_commit();
    load_tiles(1, 1); cp_commit();

    int st = 0;
    for (int kt = 0; kt < nk; kt++) {
        if (kt == nk - 1) cp_wait0(); else cp_wait1();
        __syncthreads();
        if (kt + 2 < nk) {
            int lst = st + 2; if (lst >= 3) lst -= 3;
            load_tiles(lst, kt + 2);
            cp_commit();
        }

        const uint32_t bufA = s_u + st * 32768;
        const uint32_t bufB = bufA + 16384;
#pragma unroll
        for (int kk = 0; kk < 4; kk++) {
            uint32_t afrag[4][4], bfrag[4][2];
            const int kseg = kk * 2 + (lane >> 4);
#pragma unroll
            for (int mt = 0; mt < 4; mt++) {
                int row = wm * 64 + mt * 16 + (lane & 15);
                uint32_t b = (uint32_t)(row * 128 + kseg * 16);
                b ^= (b >> 3) & 0x70;
                ldmatrix4(afrag[mt], bufA + b);
            }
#pragma unroll
            for (int nt2 = 0; nt2 < 2; nt2++) {
                int row = wn * 32 + nt2 * 16 + (lane & 7) + ((lane >> 3) & 1) * 8;
                uint32_t b = (uint32_t)(row * 128 + kseg * 16);
                b ^= (b >> 3) & 0x70;
                uint32_t r[4];
                ldmatrix4(r, bufB + b);
                bfrag[nt2 * 2][0]     = r[0]; bfrag[nt2 * 2][1]     = r[2];
                bfrag[nt2 * 2 + 1][0] = r[1]; bfrag[nt2 * 2 + 1][1] = r[3];
            }
#pragma unroll
            for (int mt = 0; mt < 4; mt++)
#pragma unroll
                for (int nt = 0; nt < 4; nt++)
                    mma16816(acc[mt][nt], afrag[mt], bfrag[nt]);
        }
        if (++st == 3) st = 0;
    }

    const int sec = n0 >> 8;
    const bool iskv = (KV != nullptr) && (sec != 0) && (sec != 3);
    const int kvbase = (sec == 1) ? 0 : (sec == 2) ? 256 : (sec == 4) ? 512 : 768;

#pragma unroll
    for (int mt = 0; mt < 4; mt++) {
        int rbase = m0 + wm * 64 + mt * 16 + (lane >> 2);
#pragma unroll
        for (int nt = 0; nt < 4; nt++) {
            int c = n0 + wn * 32 + nt * 8 + (lane & 3) * 2;
            float bx = bias[c], by = bias[c + 1];
            if (iskv) {
                int kvc = kvbase + (c & 255);
                if (rbase < M) {
                    __half2 o = __floats2half2_rn(acc[mt][nt][0] + bx, acc[mt][nt][1] + by);
                    *(__half2*)(KV + (size_t)rbase * 1024 + kvc) = o;
                }
                if (rbase + 8 < M) {
                    __half2 o = __floats2half2_rn(acc[mt][nt][2] + bx, acc[mt][nt][3] + by);
                    *(__half2*)(KV + (size_t)(rbase + 8) * 1024 + kvc) = o;
                }
            } else {
                if (rbase < M) {
                    float2 o = make_float2(acc[mt][nt][0] + bx, acc[mt][nt][1] + by);
                    *(float2*)(C + (size_t)rbase * Nc + c) = o;
                }
                if (rbase + 8 < M) {
                    float2 o = make_float2(acc[mt][nt][2] + bx, acc[mt][nt][3] + by);
                    *(float2*)(C + (size_t)(rbase + 8) * Nc + c) = o;
                }
            }
        }
    }
}

// ---------------- launch ----------------
extern "C" void kernel_launch(void* const* d_in, const int* in_sizes, int n_in,
                              void* d_out, int out_size) {
    const float* feat1  = (const float*)d_in[0];
    const float* coord1 = (const float*)d_in[1];
    const float* feat2  = (const float*)d_in[2];
    const float* coord2 = (const float*)d_in[3];
    const float* Wqkv1  = (const float*)d_in[4];
    const float* bqkv1  = (const float*)d_in[5];
    const float* Wqkv2  = (const float*)d_in[6];
    const float* bqkv2  = (const float*)d_in[7];
    const float* Wproj1 = (const float*)d_in[8];
    const float* bproj1 = (const float*)d_in[9];
    const float* Wproj2 = (const float*)d_in[10];
    const float* bproj2 = (const float*)d_in[11];
    const float* Wrpe   = (const float*)d_in[12];
    const float* brpe   = (const float*)d_in[13];
    const int* graph1   = (const int*)d_in[14];
    const int* graph2   = (const int*)d_in[15];
    const int* graph12  = (const int*)d_in[16];
    const int* graph21  = (const int*)d_in[17];
    float* out = (float*)d_out;

    float *qkv1, *qkv2;
    __half *kv1, *kv2;
    cudaGetSymbolAddress((void**)&qkv1, g_qkv1);
    cudaGetSymbolAddress((void**)&qkv2, g_qkv2);
    cudaGetSymbolAddress((void**)&kv1, g_kv1);
    cudaGetSymbolAddress((void**)&kv2, g_kv2);
    __half *f1p, *f2p, *t1p, *t2p, *w1p, *w2p, *p1p, *p2p;
    cudaGetSymbolAddress((void**)&f1p, g_f1p);
    cudaGetSymbolAddress((void**)&f2p, g_f2p);
    cudaGetSymbolAddress((void**)&t1p, g_t1p);
    cudaGetSymbolAddress((void**)&t2p, g_t2p);
    cudaGetSymbolAddress((void**)&w1p, g_w1p);
    cudaGetSymbolAddress((void**)&w2p, g_w2p);
    cudaGetSymbolAddress((void**)&p1p, g_p1p);
    cudaGetSymbolAddress((void**)&p2p, g_p2p);

    static cudaStream_t s1 = nullptr;
    static cudaEvent_t evFork = nullptr, evCSR = nullptr, evQKV = nullptr, evDone = nullptr;
    static bool inited = false;
    if (!inited) {
        cudaStreamCreateWithFlags(&s1, cudaStreamNonBlocking);
        cudaEventCreateWithFlags(&evFork, cudaEventDisableTiming);
        cudaEventCreateWithFlags(&evCSR, cudaEventDisableTiming);
        cudaEventCreateWithFlags(&evQKV, cudaEventDisableTiming);
        cudaEventCreateWithFlags(&evDone, cudaEventDisableTiming);
        cudaFuncSetAttribute(gemm_f16_mma2, cudaFuncAttributeMaxDynamicSharedMemorySize, GSMEM);
        cudaFuncSetAttribute(scan_kernel, cudaFuncAttributeMaxDynamicSharedMemorySize, SCAN_SMEM);
        inited = true;
    }

    // s0: prep (zeroes counters used by s1's count4)
    prep_all<<<128, 256>>>(Wrpe, brpe);

    // fork s1: CSR build + proj-weight transpose
    cudaEventRecord(evFork, 0);
    cudaStreamWaitEvent(s1, evFork, 0);

    const int EBLK = (EE + 255) / 256;
    dim3 gcnt(EBLK, 4);
    count4<<<gcnt, 256, 0, s1>>>(graph1, graph2, graph21, graph12);
    scan_kernel<<<4, 1024, SCAN_SMEM, s1>>>();
    permute4<<<gcnt, 256, 0, s1>>>(graph1, graph2, graph21, graph12);
    dim3 gtp(256 / 32, 512 / 32, 2);
    transposeW2c<<<gtp, dim3(32, 8), 0, s1>>>(Wproj1, Wproj2, p1p, p2p, 512, 256);
    cudaEventRecord(evCSR, s1);   // CSR + proj weights ready

    // s0: feat convert + qkv weight transpose + QKV GEMMs (both sets)
    dim3 gfs((FSV + 255) / 256, 2);
    split_feats<<<gfs, 256>>>(feat1, feat2, f1p, f2p);
    dim3 gtw(1536 / 32, 256 / 32, 2);
    transposeW2c<<<gtw, dim3(32, 8)>>>(Wqkv1, Wqkv2, w1p, w2p, 256, 1536);

    dim3 gq(QW / 128, NP / 128, 2);
    gemm_f16_mma2<<<gq, 256, GSMEM>>>(f1p, f2p, w1p, w2p, bqkv1, bqkv2, qkv1, qkv2,
                                      kv1, kv2, NN, 256, QW);
    cudaEventRecord(evQKV, 0);

    // chain A on s0: attn aids {0,2} -> t1p, then proj set1
    cudaStreamWaitEvent(0, evCSR, 0);
    dim3 ga((NN * 32 + 255) / 256, 2);
    attn4<<<ga, 256>>>(qkv1, qkv2, kv1, kv2, coord1, coord2, t1p, t2p, 0);
    dim3 gp(256 / 128, NP / 128, 1);
    gemm_f16_mma2<<<gp, 256, GSMEM>>>(t1p, t1p, p1p, p1p, bproj1, bproj1,
                                      out, out, nullptr, nullptr, NN, 512, 256);

    // chain B on s1: attn aids {1,3} -> t2p, then proj set2
    cudaStreamWaitEvent(s1, evQKV, 0);
    attn4<<<ga, 256, 0, s1>>>(qkv1, qkv2, kv1, kv2, coord1, coord2, t1p, t2p, 1);
    gemm_f16_mma2<<<gp, 256, GSMEM, s1>>>(t2p, t2p, p2p, p2p, bproj2, bproj2,
                                          out + (size_t)NN * 256, out + (size_t)NN * 256,
                                          nullptr, nullptr, NN, 512, 256);
    cudaEventRecord(evDone, s1);

    // join all forks back into s0 before capture end
    cudaStreamWaitEvent(0, evDone, 0);
}